// round 11
// baseline (speedup 1.0000x reference)
#include <cuda_runtime.h>
#include <cuda_bf16.h>
#include <math.h>

// ---------------------------------------------------------------------------
// Problem constants
// ---------------------------------------------------------------------------
#define BATCH   16
#define NH      8
#define HID     128
#define VD      16
#define RIN     64
#define RLAT    32
#define NIN     (RIN*RIN)   // 4096
#define NLAT    (RLAT*RLAT) // 1024
#define PI_F    3.14159265358979323846f

#define NWMAT   15
#define GEMM_SMEM   (4*128*136*2)                 // BM=128: 139264 bytes
#define GEMM64_SMEM ((2*64*136 + 2*128*136)*2)    // BM=64 : 104448 bytes

// procatt tiled smem budget
#define KMAX  40
#define PROC_SMEM (256*128*4 + 64*KMAX*8*4 + 64*KMAX*4 + 64*4 + 64*8*4)  // 225536

typedef __nv_bfloat16 bf16;
typedef __nv_bfloat162 bf162;

// ---------------------------------------------------------------------------
// Scratch buffers
// ---------------------------------------------------------------------------
__device__ float g_val[BATCH*NIN*HID];                       // f32 value proj
__device__ float g_T  [BATCH*2048*HID];                      // sep-attention T
__device__ __align__(16) bf16 g_hA_h[BATCH*NLAT*HID];
__device__ __align__(16) bf16 g_hA_l[BATCH*NLAT*HID];
__device__ __align__(16) bf16 g_hB_h[BATCH*NLAT*HID];
__device__ __align__(16) bf16 g_hB_l[BATCH*NLAT*HID];
__device__ __align__(16) bf16 g_pa_h[BATCH*NLAT*HID];
__device__ __align__(16) bf16 g_pa_l[BATCH*NLAT*HID];
__device__ __align__(16) bf16 g_t1_h[BATCH*NLAT*HID];
__device__ __align__(16) bf16 g_t1_l[BATCH*NLAT*HID];
__device__ __align__(16) bf16 g_hup_h[BATCH*NIN*HID];
__device__ __align__(16) bf16 g_hup_l[BATCH*NIN*HID];
__device__ float g_wdn[NH*RLAT*RIN];
__device__ float g_wup[NH*RIN*RLAT];
__device__ int   g_kidx[NLAT*64];
__device__ int   g_kcnt[NLAT];
__device__ __align__(16) bf16 g_bwh[NWMAT*HID*HID];
__device__ __align__(16) bf16 g_bwl[NWMAT*HID*HID];

// ---------------------------------------------------------------------------
// Helpers
// ---------------------------------------------------------------------------
__device__ __forceinline__ float gelu_f(float x) {
    const float c = 0.7978845608028654f;
    float y = c * fmaf(0.044715f * x, x * x, x);
    return x / (1.0f + __expf(-2.0f * y));
}

__device__ __forceinline__ float head_scale(float r) {
    return tanf(0.25f * PI_F * (1.0f - 1e-7f) * (1.0f + sinf(r)));
}

__device__ __forceinline__ void split_bf(float v, bf16& h, bf16& l) {
    h = __float2bfloat16(v);
    l = __float2bfloat16(v - __bfloat162float(h));
}

__device__ __forceinline__ void mma_bf16(float* d,
        unsigned a0, unsigned a1, unsigned a2, unsigned a3,
        unsigned b0, unsigned b1) {
    asm volatile(
        "mma.sync.aligned.m16n8k16.row.col.f32.bf16.bf16.f32 "
        "{%0,%1,%2,%3}, {%4,%5,%6,%7}, {%8,%9}, {%0,%1,%2,%3};"
        : "+f"(d[0]), "+f"(d[1]), "+f"(d[2]), "+f"(d[3])
        : "r"(a0), "r"(a1), "r"(a2), "r"(a3), "r"(b0), "r"(b1));
}

__device__ __forceinline__ void ldsm4(unsigned& r0, unsigned& r1, unsigned& r2,
                                      unsigned& r3, unsigned addr) {
    asm volatile("ldmatrix.sync.aligned.m8n8.x4.shared.b16 {%0,%1,%2,%3}, [%4];"
        : "=r"(r0), "=r"(r1), "=r"(r2), "=r"(r3) : "r"(addr));
}

// ---------------------------------------------------------------------------
// Merged precompute kernel:
//   blocks [0,960)    : weight prep (15 mats x 64 blocks)
//   blocks [960,1984) : kNN neighbor lists (1024 queries)
//   blocks [1984,2000): separable factors (8 down heads, 8 up heads)
// ---------------------------------------------------------------------------
struct BWList { const float* w[NWMAT]; unsigned bre_mask; };

__device__ void factor_body(int h, const float* rv, float* w, int RQ, int RK) {
    int tid = threadIdx.x, lane = tid & 31, wp = tid >> 5;
    int KP = RK >> 5;
    float s = head_scale(rv[h]);
    for (int q = wp; q < RQ; q += 8) {
        float qp = (float)q / (float)RQ;
        float d[2];
        float mind = 1e30f;
        for (int i = 0; i < KP; i++) {
            int k = lane + i * 32;
            float dd = qp - (float)k / (float)RK;
            d[i] = 0.5f * dd * dd;
            mind = fminf(mind, d[i]);
        }
        for (int o = 16; o > 0; o >>= 1)
            mind = fminf(mind, __shfl_xor_sync(0xffffffffu, mind, o));
        float p[2], sum = 0.f;
        for (int i = 0; i < KP; i++) { p[i] = __expf(s * (mind - d[i])); sum += p[i]; }
        for (int o = 16; o > 0; o >>= 1)
            sum += __shfl_xor_sync(0xffffffffu, sum, o);
        float inv = 1.0f / sum;
        for (int i = 0; i < KP; i++)
            w[(h * RQ + q) * RK + lane + i * 32] = p[i] * inv;
    }
}

__global__ void k_pre(BWList L, bf16* __restrict__ outh, bf16* __restrict__ outl,
                      int* __restrict__ kidx, int* __restrict__ kcnt,
                      const float* __restrict__ down_r, const float* __restrict__ up_r,
                      float* __restrict__ wdn, float* __restrict__ wup) {
    int bid = blockIdx.x;
    int tid = threadIdx.x;
    if (bid < 960) {
        int mat = bid >> 6;
        const float* w = L.w[mat];
        int bre = (L.bre_mask >> mat) & 1;
        int idx = (bid & 63) * 256 + tid;
        int k = idx >> 7, n = idx & 127;
        float v;
        if (bre) {
            int h = n >> 4, vd = n & 15;
            v = w[((size_t)h * HID + k) * VD + vd];
        } else {
            v = w[k * HID + n];
        }
        bf16 hi, lo;
        split_bf(v, hi, lo);
        size_t o = (size_t)mat * HID * HID + n * HID + k;
        outh[o] = hi;
        outl[o] = lo;
        return;
    }
    if (bid < 1984) {
        int q = bid - 960;
        int lane = tid & 31, w = tid >> 5;
        int qx = q & (RLAT - 1), qy = q >> 5;
        int dv[4];
#pragma unroll
        for (int i = 0; i < 4; i++) {
            int k = tid * 4 + i;
            int kx = k & (RLAT - 1), ky = k >> 5;
            int dx = qx - kx, dy = qy - ky;
            dv[i] = dx * dx + dy * dy;
        }
        __shared__ int scount;
        int lo = 0, hi = 2 * 31 * 31;
        while (lo < hi) {
            int mid = (lo + hi) >> 1;
            if (tid == 0) scount = 0;
            __syncthreads();
            int c = 0;
#pragma unroll
            for (int i = 0; i < 4; i++) c += (dv[i] <= mid);
#pragma unroll
            for (int o = 16; o > 0; o >>= 1) c += __shfl_down_sync(0xffffffffu, c, o);
            if (lane == 0) atomicAdd(&scount, c);
            __syncthreads();
            if (scount >= 21) hi = mid; else lo = mid + 1;
            __syncthreads();
        }
        int sel[4], cnt_t = 0;
#pragma unroll
        for (int i = 0; i < 4; i++) { sel[i] = (dv[i] <= lo); cnt_t += sel[i]; }
        int incl = cnt_t;
#pragma unroll
        for (int o = 1; o < 32; o <<= 1) {
            int v = __shfl_up_sync(0xffffffffu, incl, o);
            if (lane >= o) incl += v;
        }
        __shared__ int wsum[8], wbase[8];
        if (lane == 31) wsum[w] = incl;
        __syncthreads();
        if (tid == 0) {
            int b = 0;
            for (int i = 0; i < 8; i++) { wbase[i] = b; b += wsum[i]; }
            kcnt[q] = b;
        }
        __syncthreads();
        int pos = wbase[w] + incl - cnt_t;
#pragma unroll
        for (int i = 0; i < 4; i++) {
            if (sel[i] && pos < 64) kidx[q * 64 + pos] = tid * 4 + i;
            pos += sel[i];
        }
        return;
    }
    int j = bid - 1984;
    if (j < 8) factor_body(j, down_r, wdn, RLAT, RIN);
    else       factor_body(j - 8, up_r, wup, RIN, RLAT);
}

// ---------------------------------------------------------------------------
// Tensor-core GEMM BM=128 (bf16x3 split), ldmatrix fragment loads.
// Used for the two M=65536 GEMMs (encoder-fused value GEMM + decoder).
// ---------------------------------------------------------------------------
template <int AENC, int DUAL, int DOGELU, int DEC, int OBF>
__global__ void __launch_bounds__(256, 1)
k_gemm(const bf16* __restrict__ Ah, const bf16* __restrict__ Al,
       const bf16* __restrict__ Bh, const bf16* __restrict__ Bl,
       const bf16* __restrict__ A2h, const bf16* __restrict__ A2l,
       const bf16* __restrict__ B2h, const bf16* __restrict__ B2l,
       const float* __restrict__ bias, const float* __restrict__ bias2,
       const float* __restrict__ x, const float* __restrict__ enw,
       const float* __restrict__ enb,
       const float* __restrict__ d2w, const float* __restrict__ d2b,
       float* __restrict__ Cf, bf16* __restrict__ Ch, bf16* __restrict__ Cl) {
    extern __shared__ __align__(16) char smem_raw[];
    bf16* sAh = (bf16*)smem_raw;
    bf16* sAl = sAh + 128 * 136;
    bf16* sBh = sAl + 128 * 136;
    bf16* sBl = sBh + 128 * 136;

    int tid = threadIdx.x;
    int wid = tid >> 5, lane = tid & 31;
    int g = lane >> 2, s = lane & 3;
    size_t rbase = (size_t)blockIdx.x * 128;

    unsigned sAh_b = (unsigned)__cvta_generic_to_shared(sAh);
    unsigned sAl_b = (unsigned)__cvta_generic_to_shared(sAl);
    unsigned sBh_b = (unsigned)__cvta_generic_to_shared(sBh);
    unsigned sBl_b = (unsigned)__cvta_generic_to_shared(sBl);
    int arowf = wid * 16 + (lane & 15);
    unsigned aoff = (unsigned)((arowf * 136 + ((lane >> 4) << 3)) * 2);
    int brow = (lane & 7) + ((lane >> 4) << 3);
    unsigned boff = (unsigned)((brow * 136 + (((lane >> 3) & 1) << 3)) * 2);

    float acc[16][4];
#pragma unroll
    for (int j = 0; j < 16; j++)
#pragma unroll
        for (int e = 0; e < 4; e++) acc[j][e] = 0.f;

    const int NPASS = DUAL ? 2 : 1;
#pragma unroll
    for (int pass = 0; pass < NPASS; pass++) {
        const bf16* Aph = (DUAL && pass) ? A2h : Ah;
        const bf16* Apl = (DUAL && pass) ? A2l : Al;
        const bf16* Bph = (DUAL && pass) ? B2h : Bh;
        const bf16* Bpl = (DUAL && pass) ? B2l : Bl;

        if (AENC && pass == 0) {
            int row = tid >> 1, half = tid & 1;
            size_t grow = rbase + row;
            float x0 = x[grow * 3 + 0], x1 = x[grow * 3 + 1], x2 = x[grow * 3 + 2];
#pragma unroll 8
            for (int c = 0; c < 64; c++) {
                int cc = half * 64 + c;
                float a = fmaf(x0, enw[cc],
                          fmaf(x1, enw[HID + cc],
                          fmaf(x2, enw[2 * HID + cc], enb[cc])));
                a = gelu_f(a);
                bf16 h, l;
                split_bf(a, h, l);
                sAh[row * 136 + cc] = h;
                sAl[row * 136 + cc] = l;
            }
        } else {
            const uint4* Ah4 = (const uint4*)(Aph + rbase * 128);
            const uint4* Al4 = (const uint4*)(Apl + rbase * 128);
#pragma unroll
            for (int i = 0; i < 8; i++) {
                int idx8 = tid + i * 256;
                int row = idx8 >> 4, k8 = (idx8 & 15) << 3;
                *(uint4*)&sAh[row * 136 + k8] = Ah4[idx8];
                *(uint4*)&sAl[row * 136 + k8] = Al4[idx8];
            }
        }
        {
            const uint4* Bh4 = (const uint4*)Bph;
            const uint4* Bl4 = (const uint4*)Bpl;
#pragma unroll
            for (int i = 0; i < 8; i++) {
                int idx8 = tid + i * 256;
                int n = idx8 >> 4, k8 = (idx8 & 15) << 3;
                *(uint4*)&sBh[n * 136 + k8] = Bh4[idx8];
                *(uint4*)&sBl[n * 136 + k8] = Bl4[idx8];
            }
        }
        __syncthreads();

#pragma unroll
        for (int ks = 0; ks < 8; ks++) {
            unsigned kb = (unsigned)(ks * 16 * 2);
            unsigned ah0, ah1, ah2, ah3, al0, al1, al2, al3;
            ldsm4(ah0, ah1, ah2, ah3, sAh_b + aoff + kb);
            ldsm4(al0, al1, al2, al3, sAl_b + aoff + kb);
#pragma unroll
            for (int j2 = 0; j2 < 8; j2++) {
                unsigned bofs = boff + (unsigned)(j2 * 16 * 136 * 2) + kb;
                unsigned bh0, bh1, bh2, bh3, bl0, bl1, bl2, bl3;
                ldsm4(bh0, bh1, bh2, bh3, sBh_b + bofs);
                ldsm4(bl0, bl1, bl2, bl3, sBl_b + bofs);
                mma_bf16(acc[2 * j2],     ah0, ah1, ah2, ah3, bh0, bh1);
                mma_bf16(acc[2 * j2],     ah0, ah1, ah2, ah3, bl0, bl1);
                mma_bf16(acc[2 * j2],     al0, al1, al2, al3, bh0, bh1);
                mma_bf16(acc[2 * j2 + 1], ah0, ah1, ah2, ah3, bh2, bh3);
                mma_bf16(acc[2 * j2 + 1], ah0, ah1, ah2, ah3, bl2, bl3);
                mma_bf16(acc[2 * j2 + 1], al0, al1, al2, al3, bh2, bh3);
            }
        }
        __syncthreads();
    }

    int r0 = wid * 16 + g;
    if (DEC) {
        float p0 = 0.f, p1 = 0.f;
#pragma unroll
        for (int j = 0; j < 16; j++) {
            int c = j * 8 + 2 * s;
            float b0 = bias ? bias[c] : 0.f;
            float b1 = bias ? bias[c + 1] : 0.f;
            float w0 = d2w[c], w1 = d2w[c + 1];
            float v0 = gelu_f(acc[j][0] + b0), v1 = gelu_f(acc[j][1] + b1);
            float v2 = gelu_f(acc[j][2] + b0), v3 = gelu_f(acc[j][3] + b1);
            p0 = fmaf(v0, w0, fmaf(v1, w1, p0));
            p1 = fmaf(v2, w0, fmaf(v3, w1, p1));
        }
        p0 += __shfl_xor_sync(0xffffffffu, p0, 1);
        p0 += __shfl_xor_sync(0xffffffffu, p0, 2);
        p1 += __shfl_xor_sync(0xffffffffu, p1, 1);
        p1 += __shfl_xor_sync(0xffffffffu, p1, 2);
        if (s == 0) {
            float db = d2b[0];
            Cf[rbase + r0] = p0 + db;
            Cf[rbase + r0 + 8] = p1 + db;
        }
    } else {
#pragma unroll
        for (int j = 0; j < 16; j++) {
            int c = j * 8 + 2 * s;
            float b0 = 0.f, b1 = 0.f;
            if (bias) {
                float2 bb = *(const float2*)&bias[c];
                b0 += bb.x; b1 += bb.y;
            }
            if (DUAL && bias2) {
                float2 bb = *(const float2*)&bias2[c];
                b0 += bb.x; b1 += bb.y;
            }
            float v0 = acc[j][0] + b0, v1 = acc[j][1] + b1;
            float v2 = acc[j][2] + b0, v3 = acc[j][3] + b1;
            if (DOGELU) {
                v0 = gelu_f(v0); v1 = gelu_f(v1);
                v2 = gelu_f(v2); v3 = gelu_f(v3);
            }
            if (OBF) {
                bf16 h0, l0, h1, l1, h2, l2, h3, l3;
                split_bf(v0, h0, l0); split_bf(v1, h1, l1);
                split_bf(v2, h2, l2); split_bf(v3, h3, l3);
                bf162 ph0 = {h0, h1}, ph1 = {h2, h3};
                bf162 pl0 = {l0, l1}, pl1 = {l2, l3};
                *(bf162*)&Ch[(rbase + r0) * 128 + c] = ph0;
                *(bf162*)&Cl[(rbase + r0) * 128 + c] = pl0;
                *(bf162*)&Ch[(rbase + r0 + 8) * 128 + c] = ph1;
                *(bf162*)&Cl[(rbase + r0 + 8) * 128 + c] = pl1;
            } else {
                float2 u0 = {v0, v1}, u1 = {v2, v3};
                *(float2*)&Cf[(rbase + r0) * 128 + c] = u0;
                *(float2*)&Cf[(rbase + r0 + 8) * 128 + c] = u1;
            }
        }
    }
}

// ---------------------------------------------------------------------------
// Tensor-core GEMM BM=64 (bf16x3 split) for latent (M=16384) GEMMs.
// grid = M/64 = 256 blocks, 2 CTAs/SM (104 KB smem, 32-reg accumulators).
// ---------------------------------------------------------------------------
template <int DUAL, int DOGELU, int OBF>
__global__ void __launch_bounds__(256, 2)
k_gemm64(const bf16* __restrict__ Ah, const bf16* __restrict__ Al,
         const bf16* __restrict__ Bh, const bf16* __restrict__ Bl,
         const bf16* __restrict__ A2h, const bf16* __restrict__ A2l,
         const bf16* __restrict__ B2h, const bf16* __restrict__ B2l,
         const float* __restrict__ bias, const float* __restrict__ bias2,
         float* __restrict__ Cf, bf16* __restrict__ Ch, bf16* __restrict__ Cl) {
    extern __shared__ __align__(16) char smem_raw[];
    bf16* sAh = (bf16*)smem_raw;            // [64][136]
    bf16* sAl = sAh + 64 * 136;
    bf16* sBh = sAl + 64 * 136;             // [128][136]
    bf16* sBl = sBh + 128 * 136;

    int tid = threadIdx.x;
    int wid = tid >> 5, lane = tid & 31;
    int wm = wid & 3, wn = wid >> 2;
    int g = lane >> 2, s = lane & 3;
    size_t rbase = (size_t)blockIdx.x * 64;

    unsigned sAh_b = (unsigned)__cvta_generic_to_shared(sAh);
    unsigned sAl_b = (unsigned)__cvta_generic_to_shared(sAl);
    unsigned sBh_b = (unsigned)__cvta_generic_to_shared(sBh);
    unsigned sBl_b = (unsigned)__cvta_generic_to_shared(sBl);
    int arowf = wm * 16 + (lane & 15);
    unsigned aoff = (unsigned)((arowf * 136 + ((lane >> 4) << 3)) * 2);
    int brow = (lane & 7) + ((lane >> 4) << 3);
    unsigned boff = (unsigned)(((wn * 64 + brow) * 136 + (((lane >> 3) & 1) << 3)) * 2);

    float acc[8][4];
#pragma unroll
    for (int j = 0; j < 8; j++)
#pragma unroll
        for (int e = 0; e < 4; e++) acc[j][e] = 0.f;

    const int NPASS = DUAL ? 2 : 1;
#pragma unroll
    for (int pass = 0; pass < NPASS; pass++) {
        const bf16* Aph = (DUAL && pass) ? A2h : Ah;
        const bf16* Apl = (DUAL && pass) ? A2l : Al;
        const bf16* Bph = (DUAL && pass) ? B2h : Bh;
        const bf16* Bpl = (DUAL && pass) ? B2l : Bl;
        {
            const uint4* Ah4 = (const uint4*)(Aph + rbase * 128);
            const uint4* Al4 = (const uint4*)(Apl + rbase * 128);
#pragma unroll
            for (int i = 0; i < 4; i++) {
                int idx8 = tid + i * 256;
                int row = idx8 >> 4, k8 = (idx8 & 15) << 3;
                *(uint4*)&sAh[row * 136 + k8] = Ah4[idx8];
                *(uint4*)&sAl[row * 136 + k8] = Al4[idx8];
            }
            const uint4* Bh4 = (const uint4*)Bph;
            const uint4* Bl4 = (const uint4*)Bpl;
#pragma unroll
            for (int i = 0; i < 8; i++) {
                int idx8 = tid + i * 256;
                int n = idx8 >> 4, k8 = (idx8 & 15) << 3;
                *(uint4*)&sBh[n * 136 + k8] = Bh4[idx8];
                *(uint4*)&sBl[n * 136 + k8] = Bl4[idx8];
            }
        }
        __syncthreads();

#pragma unroll
        for (int ks = 0; ks < 8; ks++) {
            unsigned kb = (unsigned)(ks * 16 * 2);
            unsigned ah0, ah1, ah2, ah3, al0, al1, al2, al3;
            ldsm4(ah0, ah1, ah2, ah3, sAh_b + aoff + kb);
            ldsm4(al0, al1, al2, al3, sAl_b + aoff + kb);
#pragma unroll
            for (int j2 = 0; j2 < 4; j2++) {
                unsigned bofs = boff + (unsigned)(j2 * 16 * 136 * 2) + kb;
                unsigned bh0, bh1, bh2, bh3, bl0, bl1, bl2, bl3;
                ldsm4(bh0, bh1, bh2, bh3, sBh_b + bofs);
                ldsm4(bl0, bl1, bl2, bl3, sBl_b + bofs);
                mma_bf16(acc[2 * j2],     ah0, ah1, ah2, ah3, bh0, bh1);
                mma_bf16(acc[2 * j2],     ah0, ah1, ah2, ah3, bl0, bl1);
                mma_bf16(acc[2 * j2],     al0, al1, al2, al3, bh0, bh1);
                mma_bf16(acc[2 * j2 + 1], ah0, ah1, ah2, ah3, bh2, bh3);
                mma_bf16(acc[2 * j2 + 1], ah0, ah1, ah2, ah3, bl2, bl3);
                mma_bf16(acc[2 * j2 + 1], al0, al1, al2, al3, bh2, bh3);
            }
        }
        __syncthreads();
    }

    int r0 = wm * 16 + g;
#pragma unroll
    for (int j = 0; j < 8; j++) {
        int c = wn * 64 + j * 8 + 2 * s;
        float b0 = 0.f, b1 = 0.f;
        if (bias) {
            float2 bb = *(const float2*)&bias[c];
            b0 += bb.x; b1 += bb.y;
        }
        if (DUAL && bias2) {
            float2 bb = *(const float2*)&bias2[c];
            b0 += bb.x; b1 += bb.y;
        }
        float v0 = acc[j][0] + b0, v1 = acc[j][1] + b1;
        float v2 = acc[j][2] + b0, v3 = acc[j][3] + b1;
        if (DOGELU) {
            v0 = gelu_f(v0); v1 = gelu_f(v1);
            v2 = gelu_f(v2); v3 = gelu_f(v3);
        }
        if (OBF) {
            bf16 h0, l0, h1, l1, h2, l2, h3, l3;
            split_bf(v0, h0, l0); split_bf(v1, h1, l1);
            split_bf(v2, h2, l2); split_bf(v3, h3, l3);
            bf162 ph0 = {h0, h1}, ph1 = {h2, h3};
            bf162 pl0 = {l0, l1}, pl1 = {l2, l3};
            *(bf162*)&Ch[(rbase + r0) * 128 + c] = ph0;
            *(bf162*)&Cl[(rbase + r0) * 128 + c] = pl0;
            *(bf162*)&Ch[(rbase + r0 + 8) * 128 + c] = ph1;
            *(bf162*)&Cl[(rbase + r0 + 8) * 128 + c] = pl1;
        } else {
            float2 u0 = {v0, v1}, u1 = {v2, v3};
            *(float2*)&Cf[(rbase + r0) * 128 + c] = u0;
            *(float2*)&Cf[(rbase + r0 + 8) * 128 + c] = u1;
        }
    }
}

// ---------------------------------------------------------------------------
// Separable attention step 1 (contract ky):
//   T[b][qy][kx][c] = sum_ky w[h][qy][ky] * V[b][ky*RK+kx][c]
// grid (RK/8, BATCH, NH), block 256.
// ---------------------------------------------------------------------------
template <int RQ, int RK>
__global__ void k_sepY(const float* __restrict__ V, const float* __restrict__ w,
                       float* __restrict__ T) {
    constexpr int QPT = RQ / 8;
    __shared__ float sW[RQ * RK];
    __shared__ float sV[RK * 128];
    int tid = threadIdx.x;
    int kxc = blockIdx.x;
    int b = blockIdx.y, h = blockIdx.z;
    const float* wh = w + h * RQ * RK;
    for (int i = tid; i < RQ * RK; i += 256) sW[i] = wh[i];
    for (int i = tid; i < RK * 128; i += 256) {
        int ky = i >> 7, col = i & 127;
        int kx = kxc * 8 + (col >> 4), vd = col & 15;
        sV[i] = V[(((size_t)b * RK + ky) * RK + kx) * 128 + h * 16 + vd];
    }
    __syncthreads();
    int qy0 = (tid >> 5) * QPT, col0 = (tid & 31) * 4;
    float acc[QPT][4];
#pragma unroll
    for (int i = 0; i < QPT; i++)
#pragma unroll
        for (int j = 0; j < 4; j++) acc[i][j] = 0.f;
#pragma unroll 4
    for (int ky = 0; ky < RK; ky++) {
        float4 v = *reinterpret_cast<const float4*>(&sV[ky * 128 + col0]);
#pragma unroll
        for (int i = 0; i < QPT; i++) {
            float a = sW[(qy0 + i) * RK + ky];
            acc[i][0] = fmaf(a, v.x, acc[i][0]);
            acc[i][1] = fmaf(a, v.y, acc[i][1]);
            acc[i][2] = fmaf(a, v.z, acc[i][2]);
            acc[i][3] = fmaf(a, v.w, acc[i][3]);
        }
    }
    int kx = kxc * 8 + (col0 >> 4), vd0 = col0 & 15;
#pragma unroll
    for (int i = 0; i < QPT; i++) {
        float4 r = make_float4(acc[i][0], acc[i][1], acc[i][2], acc[i][3]);
        *reinterpret_cast<float4*>(
            &T[(((size_t)b * RQ + qy0 + i) * RK + kx) * 128 + h * 16 + vd0]) = r;
    }
}

// ---------------------------------------------------------------------------
// Separable attention step 2 (contract kx), fused gelu, bf16 hi/lo output.
// Block = (QB qy rows, b, h); single-pass (one stage + one sync); thread =
// (qp, qx, 4-channel group). sW stored transposed [kx][RQ] (conflict-free);
// sT read via LDS128 (broadcast within 8-thread groups).
// QB = 256/(RQ*4): down 2, up 1. Grid: down 16x16x8=2048, up 64x16x8=8192.
// ---------------------------------------------------------------------------
template <int RQ, int RK>
__global__ void __launch_bounds__(256, 1)
k_sepX(const float* __restrict__ T, const float* __restrict__ w,
       bf16* __restrict__ Oh, bf16* __restrict__ Ol) {
    constexpr int QB = 256 / (RQ * 4);
    static_assert(RQ * 4 * QB == 256, "layout");
    __shared__ float sWt[RK * RQ];                    // transposed [kx][qx]
    __shared__ __align__(16) float sT[QB * RK * 16];
    int tid = threadIdx.x;
    int b = blockIdx.y, h = blockIdx.z;
    int qy0 = blockIdx.x * QB;
    const float* wh = w + h * RQ * RK;
    // stage sW transposed: sWt[kx*RQ + qx] = wh[qx*RK + kx]
    for (int i = tid; i < RQ * RK; i += 256) {
        int kx = i / RQ, qx = i - kx * RQ;
        sWt[i] = wh[qx * RK + kx];
    }
    // stage sT for QB qy rows
    for (int i = tid; i < QB * RK * 16; i += 256) {
        int qp = i / (RK * 16);
        int rem = i - qp * (RK * 16);
        int kx = rem >> 4, vd = rem & 15;
        sT[i] = T[(((size_t)b * RQ + qy0 + qp) * RK + kx) * 128 + h * 16 + vd];
    }
    __syncthreads();

    int sub = tid & (RQ * 4 - 1);
    int qx = sub >> 2;
    int c4 = (sub & 3) * 4;
    int qp = tid / (RQ * 4);
    const float* tr = &sT[qp * RK * 16];
    float a0 = 0.f, a1 = 0.f, a2 = 0.f, a3 = 0.f;
#pragma unroll 8
    for (int kx = 0; kx < RK; kx++) {
        float wv = sWt[kx * RQ + qx];
        float4 v = *(const float4*)&tr[kx * 16 + c4];
        a0 = fmaf(wv, v.x, a0);
        a1 = fmaf(wv, v.y, a1);
        a2 = fmaf(wv, v.z, a2);
        a3 = fmaf(wv, v.w, a3);
    }
    int qy = qy0 + qp;
    size_t oi = ((size_t)b * RQ * RQ + qy * RQ + qx) * 128 + h * 16 + c4;
    float g0 = gelu_f(a0), g1 = gelu_f(a1), g2 = gelu_f(a2), g3 = gelu_f(a3);
    bf16 h0, l0, h1, l1, h2, l2, h3, l3;
    split_bf(g0, h0, l0); split_bf(g1, h1, l1);
    split_bf(g2, h2, l2); split_bf(g3, h3, l3);
    bf162 ph0 = {h0, h1}, ph1 = {h2, h3};
    bf162 pl0 = {l0, l1}, pl1 = {l2, l3};
    *(bf162*)&Oh[oi] = ph0;
    *(bf162*)&Oh[oi + 2] = ph1;
    *(bf162*)&Ol[oi] = pl0;
    *(bf162*)&Ol[oi + 2] = pl1;
}

// ---------------------------------------------------------------------------
// Tiled sparse proc attention -> bf16 plane output
// ---------------------------------------------------------------------------
__global__ void __launch_bounds__(256, 1)
k_procatt(const float* __restrict__ V, const float* __restrict__ rv,
          const int* __restrict__ kidx, const int* __restrict__ kcnt,
          bf16* __restrict__ Oh, bf16* __restrict__ Ol) {
    extern __shared__ float psm[];
    float* sV   = psm;
    float* sp   = sV + 256 * 128;
    int*   skl  = (int*)(sp + 64 * KMAX * 8);
    int*   scnt = skl + 64 * KMAX;
    float* sinv = (float*)(scnt + 64);
    __shared__ float sscale[NH];

    int tile = blockIdx.x;
    int b = blockIdx.y;
    int tx = tile & 3, ty = tile >> 2;
    int x0 = tx * 8 - 4, y0 = ty * 8 - 4;
    int tid = threadIdx.x, lane = tid & 31, w = tid >> 5;

    if (tid < NH) sscale[tid] = head_scale(rv[tid]);

    const float4* V4 = (const float4*)V;
    for (int r = w; r < 256; r += 8) {
        int ix = r & 15, iy = r >> 4;
        int kx = x0 + ix, ky = y0 + iy;
        if ((unsigned)kx < 32u && (unsigned)ky < 32u) {
            int k = ky * 32 + kx;
            *(float4*)&sV[r * 128 + lane * 4] = V4[((size_t)b * NLAT + k) * 32 + lane];
        }
    }
    if (tid < 64) {
        int qx = tx * 8 + (tid & 7), qy = ty * 8 + (tid >> 3);
        scnt[tid] = kcnt[qy * 32 + qx];
    }
    for (int i = tid; i < 64 * KMAX; i += 256) {
        int ql = i / KMAX, j = i - ql * KMAX;
        if (j < 64) {
            int qx = tx * 8 + (ql & 7), qy = ty * 8 + (ql >> 3);
            int gk = kidx[(qy * 32 + qx) * 64 + j];
            int kx = gk & 31, ky = gk >> 5;
            skl[i] = (ky - y0) * 16 + (kx - x0);
        }
    }
    __syncthreads();
    for (int i = tid; i < 64 * KMAX; i += 256) {
        int ql = i / KMAX, j = i - ql * KMAX;
        if (j < scnt[ql]) {
            int kl = skl[i];
            int ix = kl & 15, iy = kl >> 4;
            float dx = (float)(ix - 4 - (ql & 7)) * (1.0f / RLAT);
            float dy = (float)(iy - 4 - (ql >> 3)) * (1.0f / RLAT);
            float dist = 0.5f * (dx * dx + dy * dy);
#pragma unroll
            for (int h = 0; h < NH; h++)
                sp[i * 8 + h] = __expf(-sscale[h] * dist);
        }
    }
    __syncthreads();
    for (int hq = tid; hq < 512; hq += 256) {
        int ql = hq >> 3, h = hq & 7;
        int cnt = scnt[ql];
        float sum = 0.f;
        for (int j = 0; j < cnt; j++) sum += sp[(ql * KMAX + j) * 8 + h];
        sinv[ql * 8 + h] = 1.0f / sum;
    }
    __syncthreads();

    int qy_l = w;
    int cg = lane;
    int h = cg >> 2;
    const float4* sV4 = (const float4*)sV;
#pragma unroll
    for (int qx_l = 0; qx_l < 8; qx_l++) {
        int ql = qy_l * 8 + qx_l;
        int cnt = scnt[ql];
        int base = ql * KMAX;
        float4 acc = make_float4(0.f, 0.f, 0.f, 0.f);
        for (int j = 0; j < cnt; j++) {
            float p = sp[(base + j) * 8 + h];
            float4 v = sV4[skl[base + j] * 32 + cg];
            acc.x = fmaf(p, v.x, acc.x);
            acc.y = fmaf(p, v.y, acc.y);
            acc.z = fmaf(p, v.z, acc.z);
            acc.w = fmaf(p, v.w, acc.w);
        }
        float inv = sinv[ql * 8 + h];
        float r0 = gelu_f(acc.x * inv), r1 = gelu_f(acc.y * inv);
        float r2 = gelu_f(acc.z * inv), r3 = gelu_f(acc.w * inv);
        int qglob = (ty * 8 + qy_l) * 32 + tx * 8 + qx_l;
        size_t oi = ((size_t)b * NLAT + qglob) * 128 + cg * 4;
        bf16 h0, l0, h1, l1, h2, l2, h3, l3;
        split_bf(r0, h0, l0); split_bf(r1, h1, l1);
        split_bf(r2, h2, l2); split_bf(r3, h3, l3);
        bf162 ph0 = {h0, h1}, ph1 = {h2, h3};
        bf162 pl0 = {l0, l1}, pl1 = {l2, l3};
        *(bf162*)&Oh[oi] = ph0;
        *(bf162*)&Oh[oi + 2] = ph1;
        *(bf162*)&Ol[oi] = pl0;
        *(bf162*)&Ol[oi + 2] = pl1;
    }
}

// ---------------------------------------------------------------------------
// Launcher
// ---------------------------------------------------------------------------
extern "C" void kernel_launch(void* const* d_in, const int* in_sizes, int n_in,
                              void* d_out, int out_size) {
    const float* x        = (const float*)d_in[0];
    const float* en_w     = (const float*)d_in[1];
    const float* en_b     = (const float*)d_in[2];
    const float* down_r   = (const float*)d_in[3];
    const float* down_w   = (const float*)d_in[4];
    const float* pa_r     = (const float*)d_in[5];
    const float* pa_w     = (const float*)d_in[6];
    const float* mlp1_w   = (const float*)d_in[7];
    const float* mlp1_b   = (const float*)d_in[8];
    const float* mlp2_w   = (const float*)d_in[9];
    const float* mlp2_b   = (const float*)d_in[10];
    const float* res_w    = (const float*)d_in[11];
    const float* res_b    = (const float*)d_in[12];
    const float* up_r     = (const float*)d_in[13];
    const float* up_w     = (const float*)d_in[14];
    const float* de1_w    = (const float*)d_in[15];
    const float* de1_b    = (const float*)d_in[16];
    const float* de2_w    = (const float*)d_in[17];
    const float* de2_b    = (const float*)d_in[18];
    float* out = (float*)d_out;

    float *val, *T, *wdn, *wup;
    int *kidx, *kcnt;
    bf16 *bwh, *bwl;
    bf16 *hAh, *hAl, *hBh, *hBl, *pah, *pal, *t1h, *t1l, *huph, *hupl;
    cudaGetSymbolAddress((void**)&val,  g_val);
    cudaGetSymbolAddress((void**)&T,    g_T);
    cudaGetSymbolAddress((void**)&wdn,  g_wdn);
    cudaGetSymbolAddress((void**)&wup,  g_wup);
    cudaGetSymbolAddress((void**)&kidx, g_kidx);
    cudaGetSymbolAddress((void**)&kcnt, g_kcnt);
    cudaGetSymbolAddress((void**)&bwh,  g_bwh);
    cudaGetSymbolAddress((void**)&bwl,  g_bwl);
    cudaGetSymbolAddress((void**)&hAh,  g_hA_h);
    cudaGetSymbolAddress((void**)&hAl,  g_hA_l);
    cudaGetSymbolAddress((void**)&hBh,  g_hB_h);
    cudaGetSymbolAddress((void**)&hBl,  g_hB_l);
    cudaGetSymbolAddress((void**)&pah,  g_pa_h);
    cudaGetSymbolAddress((void**)&pal,  g_pa_l);
    cudaGetSymbolAddress((void**)&t1h,  g_t1_h);
    cudaGetSymbolAddress((void**)&t1l,  g_t1_l);
    cudaGetSymbolAddress((void**)&huph, g_hup_h);
    cudaGetSymbolAddress((void**)&hupl, g_hup_l);

    cudaFuncSetAttribute(k_gemm<1,0,0,0,0>, cudaFuncAttributeMaxDynamicSharedMemorySize, GEMM_SMEM);
    cudaFuncSetAttribute(k_gemm<0,0,1,1,0>, cudaFuncAttributeMaxDynamicSharedMemorySize, GEMM_SMEM);
    cudaFuncSetAttribute(k_gemm64<0,0,0>, cudaFuncAttributeMaxDynamicSharedMemorySize, GEMM64_SMEM);
    cudaFuncSetAttribute(k_gemm64<0,1,1>, cudaFuncAttributeMaxDynamicSharedMemorySize, GEMM64_SMEM);
    cudaFuncSetAttribute(k_gemm64<1,1,1>, cudaFuncAttributeMaxDynamicSharedMemorySize, GEMM64_SMEM);
    cudaFuncSetAttribute(k_procatt, cudaFuncAttributeMaxDynamicSharedMemorySize, PROC_SMEM);

    const int M_IN  = BATCH * NIN;   // 65536
    const int M_LAT = BATCH * NLAT;  // 16384
    const size_t MS = (size_t)HID * HID;

    BWList L;
    L.w[0] = down_w;
    L.w[1] = pa_w;          L.w[2] = pa_w + 16384;  L.w[3] = pa_w + 32768;
    L.w[4] = up_w;
    L.w[5] = mlp1_w;        L.w[6] = mlp1_w + MS;   L.w[7] = mlp1_w + 2 * MS;
    L.w[8] = mlp2_w;        L.w[9] = mlp2_w + MS;   L.w[10] = mlp2_w + 2 * MS;
    L.w[11] = res_w;        L.w[12] = res_w + MS;   L.w[13] = res_w + 2 * MS;
    L.w[14] = de1_w;
    L.bre_mask = 0x1F;

    // merged precompute: weights + knn + factors
    k_pre<<<2000, 256>>>(L, bwh, bwl, kidx, kcnt, down_r, up_r, wdn, wup);

#define BW(i) (bwh + (size_t)(i) * MS), (bwl + (size_t)(i) * MS)
#define NUL4 nullptr, nullptr, nullptr, nullptr

    // ---- down: fused encoder + value GEMM, then separable attention ----
    k_gemm<1,0,0,0,0><<<M_IN / 128, 256, GEMM_SMEM>>>(
        nullptr, nullptr, BW(0), NUL4,
        nullptr, nullptr, x, en_w, en_b, nullptr, nullptr,
        val, nullptr, nullptr);
    {
        dim3 g1(RIN / 8, BATCH, NH);
        k_sepY<RLAT, RIN><<<g1, 256>>>(val, wdn, T);
        dim3 g2(RLAT / 2, BATCH, NH);      // QB=2 for RQ=32
        k_sepX<RLAT, RIN><<<g2, 256>>>(T, wdn, hAh, hAl);
    }

    // ---- processor blocks ----
    bf16 *hinh = hAh, *hinl = hAl, *houth = hBh, *houtl = hBl;
    for (int i = 0; i < 3; i++) {
        k_gemm64<0,0,0><<<M_LAT / 64, 256, GEMM64_SMEM>>>(
            hinh, hinl, BW(1 + i), NUL4,
            nullptr, nullptr, val, nullptr, nullptr);
        {
            dim3 g(16, BATCH);
            k_procatt<<<g, 256, PROC_SMEM>>>(val, pa_r + i * NH, kidx, kcnt, pah, pal);
        }
        k_gemm64<0,1,1><<<M_LAT / 64, 256, GEMM64_SMEM>>>(
            pah, pal, BW(5 + i), NUL4,
            mlp1_b + i * HID, nullptr, nullptr, t1h, t1l);
        k_gemm64<1,1,1><<<M_LAT / 64, 256, GEMM64_SMEM>>>(
            t1h, t1l, BW(8 + i), hinh, hinl, BW(11 + i),
            mlp2_b + i * HID, res_b + i * HID,
            nullptr, houth, houtl);
        bf16* t;
        t = hinh; hinh = houth; houth = t;
        t = hinl; hinl = houtl; houtl = t;
    }

    // ---- up: value GEMM + separable attention ----
    k_gemm64<0,0,0><<<M_LAT / 64, 256, GEMM64_SMEM>>>(
        hinh, hinl, BW(4), NUL4,
        nullptr, nullptr, val, nullptr, nullptr);
    {
        dim3 g1(RLAT / 8, BATCH, NH);
        k_sepY<RIN, RLAT><<<g1, 256>>>(val, wup, T);
        dim3 g2(RIN, BATCH, NH);           // QB=1 for RQ=64
        k_sepX<RIN, RLAT><<<g2, 256>>>(T, wup, huph, hupl);
    }

    // ---- fused decoder ----
    k_gemm<0,0,1,1,0><<<M_IN / 128, 256, GEMM_SMEM>>>(
        huph, hupl, BW(14), NUL4,
        de1_b, nullptr, nullptr, nullptr, nullptr, de2_w, de2_b,
        out, nullptr, nullptr);
#undef BW
#undef NUL4
}

// round 12
// speedup vs baseline: 1.0840x; 1.0840x over previous
#include <cuda_runtime.h>
#include <cuda_bf16.h>
#include <math.h>

// ---------------------------------------------------------------------------
// Problem constants
// ---------------------------------------------------------------------------
#define BATCH   16
#define NH      8
#define HID     128
#define VD      16
#define RIN     64
#define RLAT    32
#define NIN     (RIN*RIN)   // 4096
#define NLAT    (RLAT*RLAT) // 1024
#define PI_F    3.14159265358979323846f

#define NWMAT   15
#define GEMM_SMEM (4*128*136*2)   // BM=128: 139264 bytes

// procatt tiled smem budget
#define KMAX  40
#define PROC_SMEM (256*128*4 + 64*KMAX*8*4 + 64*KMAX*4 + 64*4 + 64*8*4)  // 225536

typedef __nv_bfloat16 bf16;
typedef __nv_bfloat162 bf162;

// ---------------------------------------------------------------------------
// Scratch buffers
// ---------------------------------------------------------------------------
__device__ float g_val[BATCH*NIN*HID];                       // f32 value proj
__device__ float g_T  [BATCH*2048*HID];                      // sep-attention T
__device__ __align__(16) bf16 g_hA_h[BATCH*NLAT*HID];
__device__ __align__(16) bf16 g_hA_l[BATCH*NLAT*HID];
__device__ __align__(16) bf16 g_hB_h[BATCH*NLAT*HID];
__device__ __align__(16) bf16 g_hB_l[BATCH*NLAT*HID];
__device__ __align__(16) bf16 g_pa_h[BATCH*NLAT*HID];
__device__ __align__(16) bf16 g_pa_l[BATCH*NLAT*HID];
__device__ __align__(16) bf16 g_t1_h[BATCH*NLAT*HID];
__device__ __align__(16) bf16 g_t1_l[BATCH*NLAT*HID];
__device__ __align__(16) bf16 g_hup_h[BATCH*NIN*HID];
__device__ __align__(16) bf16 g_hup_l[BATCH*NIN*HID];
__device__ float g_wdn [NH*RLAT*RIN];    // [h][qy][ky]
__device__ float g_wdnT[NH*RIN*RLAT];    // [h][kx][qx]  (transposed)
__device__ float g_wup [NH*RIN*RLAT];
__device__ float g_wupT[NH*RLAT*RIN];
__device__ int   g_kidx[NLAT*64];
__device__ int   g_kcnt[NLAT];
__device__ __align__(16) bf16 g_bwh[NWMAT*HID*HID];
__device__ __align__(16) bf16 g_bwl[NWMAT*HID*HID];

// ---------------------------------------------------------------------------
// Helpers
// ---------------------------------------------------------------------------
__device__ __forceinline__ float gelu_f(float x) {
    const float c = 0.7978845608028654f;
    float y = c * fmaf(0.044715f * x, x * x, x);
    return x / (1.0f + __expf(-2.0f * y));
}

__device__ __forceinline__ float head_scale(float r) {
    return tanf(0.25f * PI_F * (1.0f - 1e-7f) * (1.0f + sinf(r)));
}

__device__ __forceinline__ void split_bf(float v, bf16& h, bf16& l) {
    h = __float2bfloat16(v);
    l = __float2bfloat16(v - __bfloat162float(h));
}

__device__ __forceinline__ void mma_bf16(float* d,
        unsigned a0, unsigned a1, unsigned a2, unsigned a3,
        unsigned b0, unsigned b1) {
    asm volatile(
        "mma.sync.aligned.m16n8k16.row.col.f32.bf16.bf16.f32 "
        "{%0,%1,%2,%3}, {%4,%5,%6,%7}, {%8,%9}, {%0,%1,%2,%3};"
        : "+f"(d[0]), "+f"(d[1]), "+f"(d[2]), "+f"(d[3])
        : "r"(a0), "r"(a1), "r"(a2), "r"(a3), "r"(b0), "r"(b1));
}

__device__ __forceinline__ void ldsm4(unsigned& r0, unsigned& r1, unsigned& r2,
                                      unsigned& r3, unsigned addr) {
    asm volatile("ldmatrix.sync.aligned.m8n8.x4.shared.b16 {%0,%1,%2,%3}, [%4];"
        : "=r"(r0), "=r"(r1), "=r"(r2), "=r"(r3) : "r"(addr));
}

// ---------------------------------------------------------------------------
// Merged precompute kernel:
//   blocks [0,960)    : weight prep (15 mats x 64 blocks)
//   blocks [960,1984) : kNN neighbor lists (1024 queries)
//   blocks [1984,2000): separable factors + transposed copies
// ---------------------------------------------------------------------------
struct BWList { const float* w[NWMAT]; unsigned bre_mask; };

__device__ void factor_body(int h, const float* rv, float* w, float* wt,
                            int RQ, int RK) {
    int tid = threadIdx.x, lane = tid & 31, wp = tid >> 5;
    int KP = RK >> 5;
    float s = head_scale(rv[h]);
    for (int q = wp; q < RQ; q += 8) {
        float qp = (float)q / (float)RQ;
        float d[2];
        float mind = 1e30f;
        for (int i = 0; i < KP; i++) {
            int k = lane + i * 32;
            float dd = qp - (float)k / (float)RK;
            d[i] = 0.5f * dd * dd;
            mind = fminf(mind, d[i]);
        }
        for (int o = 16; o > 0; o >>= 1)
            mind = fminf(mind, __shfl_xor_sync(0xffffffffu, mind, o));
        float p[2], sum = 0.f;
        for (int i = 0; i < KP; i++) { p[i] = __expf(s * (mind - d[i])); sum += p[i]; }
        for (int o = 16; o > 0; o >>= 1)
            sum += __shfl_xor_sync(0xffffffffu, sum, o);
        float inv = 1.0f / sum;
        for (int i = 0; i < KP; i++) {
            int k = lane + i * 32;
            float val = p[i] * inv;
            w [(h * RQ + q) * RK + k] = val;
            wt[(h * RK + k) * RQ + q] = val;
        }
    }
}

__global__ void k_pre(BWList L, bf16* __restrict__ outh, bf16* __restrict__ outl,
                      int* __restrict__ kidx, int* __restrict__ kcnt,
                      const float* __restrict__ down_r, const float* __restrict__ up_r,
                      float* __restrict__ wdn, float* __restrict__ wdnT,
                      float* __restrict__ wup, float* __restrict__ wupT) {
    int bid = blockIdx.x;
    int tid = threadIdx.x;
    if (bid < 960) {
        int mat = bid >> 6;
        const float* w = L.w[mat];
        int bre = (L.bre_mask >> mat) & 1;
        int idx = (bid & 63) * 256 + tid;
        int k = idx >> 7, n = idx & 127;
        float v;
        if (bre) {
            int h = n >> 4, vd = n & 15;
            v = w[((size_t)h * HID + k) * VD + vd];
        } else {
            v = w[k * HID + n];
        }
        bf16 hi, lo;
        split_bf(v, hi, lo);
        size_t o = (size_t)mat * HID * HID + n * HID + k;
        outh[o] = hi;
        outl[o] = lo;
        return;
    }
    if (bid < 1984) {
        int q = bid - 960;
        int lane = tid & 31, w = tid >> 5;
        int qx = q & (RLAT - 1), qy = q >> 5;
        int dv[4];
#pragma unroll
        for (int i = 0; i < 4; i++) {
            int k = tid * 4 + i;
            int kx = k & (RLAT - 1), ky = k >> 5;
            int dx = qx - kx, dy = qy - ky;
            dv[i] = dx * dx + dy * dy;
        }
        __shared__ int scount;
        int lo = 0, hi = 2 * 31 * 31;
        while (lo < hi) {
            int mid = (lo + hi) >> 1;
            if (tid == 0) scount = 0;
            __syncthreads();
            int c = 0;
#pragma unroll
            for (int i = 0; i < 4; i++) c += (dv[i] <= mid);
#pragma unroll
            for (int o = 16; o > 0; o >>= 1) c += __shfl_down_sync(0xffffffffu, c, o);
            if (lane == 0) atomicAdd(&scount, c);
            __syncthreads();
            if (scount >= 21) hi = mid; else lo = mid + 1;
            __syncthreads();
        }
        int sel[4], cnt_t = 0;
#pragma unroll
        for (int i = 0; i < 4; i++) { sel[i] = (dv[i] <= lo); cnt_t += sel[i]; }
        int incl = cnt_t;
#pragma unroll
        for (int o = 1; o < 32; o <<= 1) {
            int v = __shfl_up_sync(0xffffffffu, incl, o);
            if (lane >= o) incl += v;
        }
        __shared__ int wsum[8], wbase[8];
        if (lane == 31) wsum[w] = incl;
        __syncthreads();
        if (tid == 0) {
            int b = 0;
            for (int i = 0; i < 8; i++) { wbase[i] = b; b += wsum[i]; }
            kcnt[q] = b;
        }
        __syncthreads();
        int pos = wbase[w] + incl - cnt_t;
#pragma unroll
        for (int i = 0; i < 4; i++) {
            if (sel[i] && pos < 64) kidx[q * 64 + pos] = tid * 4 + i;
            pos += sel[i];
        }
        return;
    }
    int j = bid - 1984;
    if (j < 8) factor_body(j, down_r, wdn, wdnT, RLAT, RIN);
    else       factor_body(j - 8, up_r, wup, wupT, RIN, RLAT);
}

// ---------------------------------------------------------------------------
// Tensor-core GEMM BM=128 (bf16x3 split), ldmatrix fragment loads.
// ---------------------------------------------------------------------------
template <int AENC, int DUAL, int DOGELU, int DEC, int OBF>
__global__ void __launch_bounds__(256, 1)
k_gemm(const bf16* __restrict__ Ah, const bf16* __restrict__ Al,
       const bf16* __restrict__ Bh, const bf16* __restrict__ Bl,
       const bf16* __restrict__ A2h, const bf16* __restrict__ A2l,
       const bf16* __restrict__ B2h, const bf16* __restrict__ B2l,
       const float* __restrict__ bias, const float* __restrict__ bias2,
       const float* __restrict__ x, const float* __restrict__ enw,
       const float* __restrict__ enb,
       const float* __restrict__ d2w, const float* __restrict__ d2b,
       float* __restrict__ Cf, bf16* __restrict__ Ch, bf16* __restrict__ Cl) {
    extern __shared__ __align__(16) char smem_raw[];
    bf16* sAh = (bf16*)smem_raw;
    bf16* sAl = sAh + 128 * 136;
    bf16* sBh = sAl + 128 * 136;
    bf16* sBl = sBh + 128 * 136;

    int tid = threadIdx.x;
    int wid = tid >> 5, lane = tid & 31;
    int g = lane >> 2, s = lane & 3;
    size_t rbase = (size_t)blockIdx.x * 128;

    unsigned sAh_b = (unsigned)__cvta_generic_to_shared(sAh);
    unsigned sAl_b = (unsigned)__cvta_generic_to_shared(sAl);
    unsigned sBh_b = (unsigned)__cvta_generic_to_shared(sBh);
    unsigned sBl_b = (unsigned)__cvta_generic_to_shared(sBl);
    int arowf = wid * 16 + (lane & 15);
    unsigned aoff = (unsigned)((arowf * 136 + ((lane >> 4) << 3)) * 2);
    int brow = (lane & 7) + ((lane >> 4) << 3);
    unsigned boff = (unsigned)((brow * 136 + (((lane >> 3) & 1) << 3)) * 2);

    float acc[16][4];
#pragma unroll
    for (int j = 0; j < 16; j++)
#pragma unroll
        for (int e = 0; e < 4; e++) acc[j][e] = 0.f;

    const int NPASS = DUAL ? 2 : 1;
#pragma unroll
    for (int pass = 0; pass < NPASS; pass++) {
        const bf16* Aph = (DUAL && pass) ? A2h : Ah;
        const bf16* Apl = (DUAL && pass) ? A2l : Al;
        const bf16* Bph = (DUAL && pass) ? B2h : Bh;
        const bf16* Bpl = (DUAL && pass) ? B2l : Bl;

        if (AENC && pass == 0) {
            int row = tid >> 1, half = tid & 1;
            size_t grow = rbase + row;
            float x0 = x[grow * 3 + 0], x1 = x[grow * 3 + 1], x2 = x[grow * 3 + 2];
#pragma unroll 8
            for (int c = 0; c < 64; c++) {
                int cc = half * 64 + c;
                float a = fmaf(x0, enw[cc],
                          fmaf(x1, enw[HID + cc],
                          fmaf(x2, enw[2 * HID + cc], enb[cc])));
                a = gelu_f(a);
                bf16 h, l;
                split_bf(a, h, l);
                sAh[row * 136 + cc] = h;
                sAl[row * 136 + cc] = l;
            }
        } else {
            const uint4* Ah4 = (const uint4*)(Aph + rbase * 128);
            const uint4* Al4 = (const uint4*)(Apl + rbase * 128);
#pragma unroll
            for (int i = 0; i < 8; i++) {
                int idx8 = tid + i * 256;
                int row = idx8 >> 4, k8 = (idx8 & 15) << 3;
                *(uint4*)&sAh[row * 136 + k8] = Ah4[idx8];
                *(uint4*)&sAl[row * 136 + k8] = Al4[idx8];
            }
        }
        {
            const uint4* Bh4 = (const uint4*)Bph;
            const uint4* Bl4 = (const uint4*)Bpl;
#pragma unroll
            for (int i = 0; i < 8; i++) {
                int idx8 = tid + i * 256;
                int n = idx8 >> 4, k8 = (idx8 & 15) << 3;
                *(uint4*)&sBh[n * 136 + k8] = Bh4[idx8];
                *(uint4*)&sBl[n * 136 + k8] = Bl4[idx8];
            }
        }
        __syncthreads();

#pragma unroll
        for (int ks = 0; ks < 8; ks++) {
            unsigned kb = (unsigned)(ks * 16 * 2);
            unsigned ah0, ah1, ah2, ah3, al0, al1, al2, al3;
            ldsm4(ah0, ah1, ah2, ah3, sAh_b + aoff + kb);
            ldsm4(al0, al1, al2, al3, sAl_b + aoff + kb);
#pragma unroll
            for (int j2 = 0; j2 < 8; j2++) {
                unsigned bofs = boff + (unsigned)(j2 * 16 * 136 * 2) + kb;
                unsigned bh0, bh1, bh2, bh3, bl0, bl1, bl2, bl3;
                ldsm4(bh0, bh1, bh2, bh3, sBh_b + bofs);
                ldsm4(bl0, bl1, bl2, bl3, sBl_b + bofs);
                mma_bf16(acc[2 * j2],     ah0, ah1, ah2, ah3, bh0, bh1);
                mma_bf16(acc[2 * j2],     ah0, ah1, ah2, ah3, bl0, bl1);
                mma_bf16(acc[2 * j2],     al0, al1, al2, al3, bh0, bh1);
                mma_bf16(acc[2 * j2 + 1], ah0, ah1, ah2, ah3, bh2, bh3);
                mma_bf16(acc[2 * j2 + 1], ah0, ah1, ah2, ah3, bl2, bl3);
                mma_bf16(acc[2 * j2 + 1], al0, al1, al2, al3, bh2, bh3);
            }
        }
        __syncthreads();
    }

    int r0 = wid * 16 + g;
    if (DEC) {
        float p0 = 0.f, p1 = 0.f;
#pragma unroll
        for (int j = 0; j < 16; j++) {
            int c = j * 8 + 2 * s;
            float b0 = bias ? bias[c] : 0.f;
            float b1 = bias ? bias[c + 1] : 0.f;
            float w0 = d2w[c], w1 = d2w[c + 1];
            float v0 = gelu_f(acc[j][0] + b0), v1 = gelu_f(acc[j][1] + b1);
            float v2 = gelu_f(acc[j][2] + b0), v3 = gelu_f(acc[j][3] + b1);
            p0 = fmaf(v0, w0, fmaf(v1, w1, p0));
            p1 = fmaf(v2, w0, fmaf(v3, w1, p1));
        }
        p0 += __shfl_xor_sync(0xffffffffu, p0, 1);
        p0 += __shfl_xor_sync(0xffffffffu, p0, 2);
        p1 += __shfl_xor_sync(0xffffffffu, p1, 1);
        p1 += __shfl_xor_sync(0xffffffffu, p1, 2);
        if (s == 0) {
            float db = d2b[0];
            Cf[rbase + r0] = p0 + db;
            Cf[rbase + r0 + 8] = p1 + db;
        }
    } else {
#pragma unroll
        for (int j = 0; j < 16; j++) {
            int c = j * 8 + 2 * s;
            float b0 = 0.f, b1 = 0.f;
            if (bias) {
                float2 bb = *(const float2*)&bias[c];
                b0 += bb.x; b1 += bb.y;
            }
            if (DUAL && bias2) {
                float2 bb = *(const float2*)&bias2[c];
                b0 += bb.x; b1 += bb.y;
            }
            float v0 = acc[j][0] + b0, v1 = acc[j][1] + b1;
            float v2 = acc[j][2] + b0, v3 = acc[j][3] + b1;
            if (DOGELU) {
                v0 = gelu_f(v0); v1 = gelu_f(v1);
                v2 = gelu_f(v2); v3 = gelu_f(v3);
            }
            if (OBF) {
                bf16 h0, l0, h1, l1, h2, l2, h3, l3;
                split_bf(v0, h0, l0); split_bf(v1, h1, l1);
                split_bf(v2, h2, l2); split_bf(v3, h3, l3);
                bf162 ph0 = {h0, h1}, ph1 = {h2, h3};
                bf162 pl0 = {l0, l1}, pl1 = {l2, l3};
                *(bf162*)&Ch[(rbase + r0) * 128 + c] = ph0;
                *(bf162*)&Cl[(rbase + r0) * 128 + c] = pl0;
                *(bf162*)&Ch[(rbase + r0 + 8) * 128 + c] = ph1;
                *(bf162*)&Cl[(rbase + r0 + 8) * 128 + c] = pl1;
            } else {
                float2 u0 = {v0, v1}, u1 = {v2, v3};
                *(float2*)&Cf[(rbase + r0) * 128 + c] = u0;
                *(float2*)&Cf[(rbase + r0 + 8) * 128 + c] = u1;
            }
        }
    }
}

// ---------------------------------------------------------------------------
// Separable attention step 1 (contract ky):
//   T[b][qy][kx][c] = sum_ky w[h][qy][ky] * V[b][ky*RK+kx][c]
// grid (RK/8, BATCH, NH), block 256.
// ---------------------------------------------------------------------------
template <int RQ, int RK>
__global__ void k_sepY(const float* __restrict__ V, const float* __restrict__ w,
                       float* __restrict__ T) {
    constexpr int QPT = RQ / 8;
    __shared__ float sW[RQ * RK];
    __shared__ float sV[RK * 128];
    int tid = threadIdx.x;
    int kxc = blockIdx.x;
    int b = blockIdx.y, h = blockIdx.z;
    const float* wh = w + h * RQ * RK;
    for (int i = tid; i < RQ * RK; i += 256) sW[i] = wh[i];
    for (int i = tid; i < RK * 128; i += 256) {
        int ky = i >> 7, col = i & 127;
        int kx = kxc * 8 + (col >> 4), vd = col & 15;
        sV[i] = V[(((size_t)b * RK + ky) * RK + kx) * 128 + h * 16 + vd];
    }
    __syncthreads();
    int qy0 = (tid >> 5) * QPT, col0 = (tid & 31) * 4;
    float acc[QPT][4];
#pragma unroll
    for (int i = 0; i < QPT; i++)
#pragma unroll
        for (int j = 0; j < 4; j++) acc[i][j] = 0.f;
#pragma unroll 4
    for (int ky = 0; ky < RK; ky++) {
        float4 v = *reinterpret_cast<const float4*>(&sV[ky * 128 + col0]);
#pragma unroll
        for (int i = 0; i < QPT; i++) {
            float a = sW[(qy0 + i) * RK + ky];
            acc[i][0] = fmaf(a, v.x, acc[i][0]);
            acc[i][1] = fmaf(a, v.y, acc[i][1]);
            acc[i][2] = fmaf(a, v.z, acc[i][2]);
            acc[i][3] = fmaf(a, v.w, acc[i][3]);
        }
    }
    int kx = kxc * 8 + (col0 >> 4), vd0 = col0 & 15;
#pragma unroll
    for (int i = 0; i < QPT; i++) {
        float4 r = make_float4(acc[i][0], acc[i][1], acc[i][2], acc[i][3]);
        *reinterpret_cast<float4*>(
            &T[(((size_t)b * RQ + qy0 + i) * RK + kx) * 128 + h * 16 + vd0]) = r;
    }
}

// ---------------------------------------------------------------------------
// Separable attention step 2 (contract kx), fused gelu, bf16 hi/lo output.
// Block = (QB qy rows, b, h); single stage + single sync. Thread = (qp, qx,
// 4-channel group). Weights read from PRE-TRANSPOSED global array (coalesced
// staging); sT read via LDS128 broadcast. QB: down 2, up 1.
// ---------------------------------------------------------------------------
template <int RQ, int RK>
__global__ void __launch_bounds__(256, 1)
k_sepX(const float* __restrict__ T, const float* __restrict__ wT,
       bf16* __restrict__ Oh, bf16* __restrict__ Ol) {
    constexpr int QB = 256 / (RQ * 4);
    static_assert(RQ * 4 * QB == 256, "layout");
    __shared__ float sWt[RK * RQ];                    // [kx][qx]
    __shared__ __align__(16) float sT[QB * RK * 16];
    int tid = threadIdx.x;
    int b = blockIdx.y, h = blockIdx.z;
    int qy0 = blockIdx.x * QB;
    const float* wth = wT + h * RQ * RK;
    // coalesced straight copy of pre-transposed weights
    for (int i = tid; i < RQ * RK; i += 256) sWt[i] = wth[i];
    // stage sT for QB qy rows (coalesced 64B segments)
    for (int i = tid; i < QB * RK * 16; i += 256) {
        int qp = i / (RK * 16);
        int rem = i - qp * (RK * 16);
        int kx = rem >> 4, vd = rem & 15;
        sT[i] = T[(((size_t)b * RQ + qy0 + qp) * RK + kx) * 128 + h * 16 + vd];
    }
    __syncthreads();

    int sub = tid & (RQ * 4 - 1);
    int qx = sub >> 2;
    int c4 = (sub & 3) * 4;
    int qp = tid / (RQ * 4);
    const float* tr = &sT[qp * RK * 16];
    float a0 = 0.f, a1 = 0.f, a2 = 0.f, a3 = 0.f;
#pragma unroll 8
    for (int kx = 0; kx < RK; kx++) {
        float wv = sWt[kx * RQ + qx];
        float4 v = *(const float4*)&tr[kx * 16 + c4];
        a0 = fmaf(wv, v.x, a0);
        a1 = fmaf(wv, v.y, a1);
        a2 = fmaf(wv, v.z, a2);
        a3 = fmaf(wv, v.w, a3);
    }
    int qy = qy0 + qp;
    size_t oi = ((size_t)b * RQ * RQ + qy * RQ + qx) * 128 + h * 16 + c4;
    float g0 = gelu_f(a0), g1 = gelu_f(a1), g2 = gelu_f(a2), g3 = gelu_f(a3);
    bf16 h0, l0, h1, l1, h2, l2, h3, l3;
    split_bf(g0, h0, l0); split_bf(g1, h1, l1);
    split_bf(g2, h2, l2); split_bf(g3, h3, l3);
    bf162 ph0 = {h0, h1}, ph1 = {h2, h3};
    bf162 pl0 = {l0, l1}, pl1 = {l2, l3};
    *(bf162*)&Oh[oi] = ph0;
    *(bf162*)&Oh[oi + 2] = ph1;
    *(bf162*)&Ol[oi] = pl0;
    *(bf162*)&Ol[oi + 2] = pl1;
}

// ---------------------------------------------------------------------------
// Tiled sparse proc attention -> bf16 plane output
// ---------------------------------------------------------------------------
__global__ void __launch_bounds__(256, 1)
k_procatt(const float* __restrict__ V, const float* __restrict__ rv,
          const int* __restrict__ kidx, const int* __restrict__ kcnt,
          bf16* __restrict__ Oh, bf16* __restrict__ Ol) {
    extern __shared__ float psm[];
    float* sV   = psm;
    float* sp   = sV + 256 * 128;
    int*   skl  = (int*)(sp + 64 * KMAX * 8);
    int*   scnt = skl + 64 * KMAX;
    float* sinv = (float*)(scnt + 64);
    __shared__ float sscale[NH];

    int tile = blockIdx.x;
    int b = blockIdx.y;
    int tx = tile & 3, ty = tile >> 2;
    int x0 = tx * 8 - 4, y0 = ty * 8 - 4;
    int tid = threadIdx.x, lane = tid & 31, w = tid >> 5;

    if (tid < NH) sscale[tid] = head_scale(rv[tid]);

    const float4* V4 = (const float4*)V;
    for (int r = w; r < 256; r += 8) {
        int ix = r & 15, iy = r >> 4;
        int kx = x0 + ix, ky = y0 + iy;
        if ((unsigned)kx < 32u && (unsigned)ky < 32u) {
            int k = ky * 32 + kx;
            *(float4*)&sV[r * 128 + lane * 4] = V4[((size_t)b * NLAT + k) * 32 + lane];
        }
    }
    if (tid < 64) {
        int qx = tx * 8 + (tid & 7), qy = ty * 8 + (tid >> 3);
        scnt[tid] = kcnt[qy * 32 + qx];
    }
    for (int i = tid; i < 64 * KMAX; i += 256) {
        int ql = i / KMAX, j = i - ql * KMAX;
        if (j < 64) {
            int qx = tx * 8 + (ql & 7), qy = ty * 8 + (ql >> 3);
            int gk = kidx[(qy * 32 + qx) * 64 + j];
            int kx = gk & 31, ky = gk >> 5;
            skl[i] = (ky - y0) * 16 + (kx - x0);
        }
    }
    __syncthreads();
    for (int i = tid; i < 64 * KMAX; i += 256) {
        int ql = i / KMAX, j = i - ql * KMAX;
        if (j < scnt[ql]) {
            int kl = skl[i];
            int ix = kl & 15, iy = kl >> 4;
            float dx = (float)(ix - 4 - (ql & 7)) * (1.0f / RLAT);
            float dy = (float)(iy - 4 - (ql >> 3)) * (1.0f / RLAT);
            float dist = 0.5f * (dx * dx + dy * dy);
#pragma unroll
            for (int h = 0; h < NH; h++)
                sp[i * 8 + h] = __expf(-sscale[h] * dist);
        }
    }
    __syncthreads();
    for (int hq = tid; hq < 512; hq += 256) {
        int ql = hq >> 3, h = hq & 7;
        int cnt = scnt[ql];
        float sum = 0.f;
        for (int j = 0; j < cnt; j++) sum += sp[(ql * KMAX + j) * 8 + h];
        sinv[ql * 8 + h] = 1.0f / sum;
    }
    __syncthreads();

    int qy_l = w;
    int cg = lane;
    int h = cg >> 2;
    const float4* sV4 = (const float4*)sV;
#pragma unroll
    for (int qx_l = 0; qx_l < 8; qx_l++) {
        int ql = qy_l * 8 + qx_l;
        int cnt = scnt[ql];
        int base = ql * KMAX;
        float4 acc = make_float4(0.f, 0.f, 0.f, 0.f);
        for (int j = 0; j < cnt; j++) {
            float p = sp[(base + j) * 8 + h];
            float4 v = sV4[skl[base + j] * 32 + cg];
            acc.x = fmaf(p, v.x, acc.x);
            acc.y = fmaf(p, v.y, acc.y);
            acc.z = fmaf(p, v.z, acc.z);
            acc.w = fmaf(p, v.w, acc.w);
        }
        float inv = sinv[ql * 8 + h];
        float r0 = gelu_f(acc.x * inv), r1 = gelu_f(acc.y * inv);
        float r2 = gelu_f(acc.z * inv), r3 = gelu_f(acc.w * inv);
        int qglob = (ty * 8 + qy_l) * 32 + tx * 8 + qx_l;
        size_t oi = ((size_t)b * NLAT + qglob) * 128 + cg * 4;
        bf16 h0, l0, h1, l1, h2, l2, h3, l3;
        split_bf(r0, h0, l0); split_bf(r1, h1, l1);
        split_bf(r2, h2, l2); split_bf(r3, h3, l3);
        bf162 ph0 = {h0, h1}, ph1 = {h2, h3};
        bf162 pl0 = {l0, l1}, pl1 = {l2, l3};
        *(bf162*)&Oh[oi] = ph0;
        *(bf162*)&Oh[oi + 2] = ph1;
        *(bf162*)&Ol[oi] = pl0;
        *(bf162*)&Ol[oi + 2] = pl1;
    }
}

// ---------------------------------------------------------------------------
// Launcher
// ---------------------------------------------------------------------------
extern "C" void kernel_launch(void* const* d_in, const int* in_sizes, int n_in,
                              void* d_out, int out_size) {
    const float* x        = (const float*)d_in[0];
    const float* en_w     = (const float*)d_in[1];
    const float* en_b     = (const float*)d_in[2];
    const float* down_r   = (const float*)d_in[3];
    const float* down_w   = (const float*)d_in[4];
    const float* pa_r     = (const float*)d_in[5];
    const float* pa_w     = (const float*)d_in[6];
    const float* mlp1_w   = (const float*)d_in[7];
    const float* mlp1_b   = (const float*)d_in[8];
    const float* mlp2_w   = (const float*)d_in[9];
    const float* mlp2_b   = (const float*)d_in[10];
    const float* res_w    = (const float*)d_in[11];
    const float* res_b    = (const float*)d_in[12];
    const float* up_r     = (const float*)d_in[13];
    const float* up_w     = (const float*)d_in[14];
    const float* de1_w    = (const float*)d_in[15];
    const float* de1_b    = (const float*)d_in[16];
    const float* de2_w    = (const float*)d_in[17];
    const float* de2_b    = (const float*)d_in[18];
    float* out = (float*)d_out;

    float *val, *T, *wdn, *wdnT, *wup, *wupT;
    int *kidx, *kcnt;
    bf16 *bwh, *bwl;
    bf16 *hAh, *hAl, *hBh, *hBl, *pah, *pal, *t1h, *t1l, *huph, *hupl;
    cudaGetSymbolAddress((void**)&val,  g_val);
    cudaGetSymbolAddress((void**)&T,    g_T);
    cudaGetSymbolAddress((void**)&wdn,  g_wdn);
    cudaGetSymbolAddress((void**)&wdnT, g_wdnT);
    cudaGetSymbolAddress((void**)&wup,  g_wup);
    cudaGetSymbolAddress((void**)&wupT, g_wupT);
    cudaGetSymbolAddress((void**)&kidx, g_kidx);
    cudaGetSymbolAddress((void**)&kcnt, g_kcnt);
    cudaGetSymbolAddress((void**)&bwh,  g_bwh);
    cudaGetSymbolAddress((void**)&bwl,  g_bwl);
    cudaGetSymbolAddress((void**)&hAh,  g_hA_h);
    cudaGetSymbolAddress((void**)&hAl,  g_hA_l);
    cudaGetSymbolAddress((void**)&hBh,  g_hB_h);
    cudaGetSymbolAddress((void**)&hBl,  g_hB_l);
    cudaGetSymbolAddress((void**)&pah,  g_pa_h);
    cudaGetSymbolAddress((void**)&pal,  g_pa_l);
    cudaGetSymbolAddress((void**)&t1h,  g_t1_h);
    cudaGetSymbolAddress((void**)&t1l,  g_t1_l);
    cudaGetSymbolAddress((void**)&huph, g_hup_h);
    cudaGetSymbolAddress((void**)&hupl, g_hup_l);

    cudaFuncSetAttribute(k_gemm<1,0,0,0,0>, cudaFuncAttributeMaxDynamicSharedMemorySize, GEMM_SMEM);
    cudaFuncSetAttribute(k_gemm<0,0,0,0,0>, cudaFuncAttributeMaxDynamicSharedMemorySize, GEMM_SMEM);
    cudaFuncSetAttribute(k_gemm<0,0,1,0,1>, cudaFuncAttributeMaxDynamicSharedMemorySize, GEMM_SMEM);
    cudaFuncSetAttribute(k_gemm<0,1,1,0,1>, cudaFuncAttributeMaxDynamicSharedMemorySize, GEMM_SMEM);
    cudaFuncSetAttribute(k_gemm<0,0,1,1,0>, cudaFuncAttributeMaxDynamicSharedMemorySize, GEMM_SMEM);
    cudaFuncSetAttribute(k_procatt, cudaFuncAttributeMaxDynamicSharedMemorySize, PROC_SMEM);

    const int M_IN  = BATCH * NIN;   // 65536
    const int M_LAT = BATCH * NLAT;  // 16384
    const size_t MS = (size_t)HID * HID;

    BWList L;
    L.w[0] = down_w;
    L.w[1] = pa_w;          L.w[2] = pa_w + 16384;  L.w[3] = pa_w + 32768;
    L.w[4] = up_w;
    L.w[5] = mlp1_w;        L.w[6] = mlp1_w + MS;   L.w[7] = mlp1_w + 2 * MS;
    L.w[8] = mlp2_w;        L.w[9] = mlp2_w + MS;   L.w[10] = mlp2_w + 2 * MS;
    L.w[11] = res_w;        L.w[12] = res_w + MS;   L.w[13] = res_w + 2 * MS;
    L.w[14] = de1_w;
    L.bre_mask = 0x1F;

    // merged precompute: weights + knn + factors (+ transposed factors)
    k_pre<<<2000, 256>>>(L, bwh, bwl, kidx, kcnt, down_r, up_r,
                         wdn, wdnT, wup, wupT);

#define BW(i) (bwh + (size_t)(i) * MS), (bwl + (size_t)(i) * MS)
#define NUL4 nullptr, nullptr, nullptr, nullptr

    // ---- down: fused encoder + value GEMM, then separable attention ----
    k_gemm<1,0,0,0,0><<<M_IN / 128, 256, GEMM_SMEM>>>(
        nullptr, nullptr, BW(0), NUL4,
        nullptr, nullptr, x, en_w, en_b, nullptr, nullptr,
        val, nullptr, nullptr);
    {
        dim3 g1(RIN / 8, BATCH, NH);
        k_sepY<RLAT, RIN><<<g1, 256>>>(val, wdn, T);
        dim3 g2(RLAT / 2, BATCH, NH);      // QB=2 for RQ=32
        k_sepX<RLAT, RIN><<<g2, 256>>>(T, wdnT, hAh, hAl);
    }

    // ---- processor blocks ----
    bf16 *hinh = hAh, *hinl = hAl, *houth = hBh, *houtl = hBl;
    for (int i = 0; i < 3; i++) {
        k_gemm<0,0,0,0,0><<<M_LAT / 128, 256, GEMM_SMEM>>>(
            hinh, hinl, BW(1 + i), NUL4,
            nullptr, nullptr, nullptr, nullptr, nullptr, nullptr, nullptr,
            val, nullptr, nullptr);
        {
            dim3 g(16, BATCH);
            k_procatt<<<g, 256, PROC_SMEM>>>(val, pa_r + i * NH, kidx, kcnt, pah, pal);
        }
        k_gemm<0,0,1,0,1><<<M_LAT / 128, 256, GEMM_SMEM>>>(
            pah, pal, BW(5 + i), NUL4,
            mlp1_b + i * HID, nullptr, nullptr, nullptr, nullptr, nullptr, nullptr,
            nullptr, t1h, t1l);
        k_gemm<0,1,1,0,1><<<M_LAT / 128, 256, GEMM_SMEM>>>(
            t1h, t1l, BW(8 + i), hinh, hinl, BW(11 + i),
            mlp2_b + i * HID, res_b + i * HID,
            nullptr, nullptr, nullptr, nullptr, nullptr,
            nullptr, houth, houtl);
        bf16* t;
        t = hinh; hinh = houth; houth = t;
        t = hinl; hinl = houtl; houtl = t;
    }

    // ---- up: value GEMM + separable attention ----
    k_gemm<0,0,0,0,0><<<M_LAT / 128, 256, GEMM_SMEM>>>(
        hinh, hinl, BW(4), NUL4,
        nullptr, nullptr, nullptr, nullptr, nullptr, nullptr, nullptr,
        val, nullptr, nullptr);
    {
        dim3 g1(RLAT / 8, BATCH, NH);
        k_sepY<RIN, RLAT><<<g1, 256>>>(val, wup, T);
        dim3 g2(RIN, BATCH, NH);           // QB=1 for RQ=64
        k_sepX<RIN, RLAT><<<g2, 256>>>(T, wupT, huph, hupl);
    }

    // ---- fused decoder ----
    k_gemm<0,0,1,1,0><<<M_IN / 128, 256, GEMM_SMEM>>>(
        huph, hupl, BW(14), NUL4,
        de1_b, nullptr, nullptr, nullptr, nullptr, de2_w, de2_b,
        out, nullptr, nullptr);
#undef BW
#undef NUL4
}

// round 13
// speedup vs baseline: 1.1629x; 1.0727x over previous
#include <cuda_runtime.h>
#include <cuda_bf16.h>
#include <math.h>

// ---------------------------------------------------------------------------
// Problem constants
// ---------------------------------------------------------------------------
#define BATCH   16
#define NH      8
#define HID     128
#define VD      16
#define RIN     64
#define RLAT    32
#define NIN     (RIN*RIN)   // 4096
#define NLAT    (RLAT*RLAT) // 1024
#define PI_F    3.14159265358979323846f

#define NWMAT   15
#define GEMM_SMEM (4*128*136*2)   // BM=128: 139264 bytes

// procatt tiled smem budget
#define KMAX  40
#define PROC_SMEM (256*128*4 + 64*KMAX*8*4 + 64*KMAX*4 + 64*4 + 64*8*4)  // 225536

typedef __nv_bfloat16 bf16;
typedef __nv_bfloat162 bf162;

// ---------------------------------------------------------------------------
// Scratch buffers
// ---------------------------------------------------------------------------
__device__ float g_val[BATCH*NIN*HID];                       // f32 value proj
__device__ float g_T  [BATCH*2048*HID];                      // sep-attention T
__device__ __align__(16) bf16 g_hA_h[BATCH*NLAT*HID];
__device__ __align__(16) bf16 g_hA_l[BATCH*NLAT*HID];
__device__ __align__(16) bf16 g_hB_h[BATCH*NLAT*HID];
__device__ __align__(16) bf16 g_hB_l[BATCH*NLAT*HID];
__device__ __align__(16) bf16 g_pa_h[BATCH*NLAT*HID];
__device__ __align__(16) bf16 g_pa_l[BATCH*NLAT*HID];
__device__ __align__(16) bf16 g_t1_h[BATCH*NLAT*HID];
__device__ __align__(16) bf16 g_t1_l[BATCH*NLAT*HID];
__device__ __align__(16) bf16 g_hup_h[BATCH*NIN*HID];
__device__ __align__(16) bf16 g_hup_l[BATCH*NIN*HID];
__device__ float g_wdn [NH*RLAT*RIN];    // [h][qy][ky]
__device__ float g_wdnT[NH*RIN*RLAT];    // [h][kx][qx]  (transposed)
__device__ float g_wup [NH*RIN*RLAT];
__device__ float g_wupT[NH*RLAT*RIN];
__device__ int   g_kidx[NLAT*64];
__device__ int   g_kcnt[NLAT];
__device__ __align__(16) bf16 g_bwh[NWMAT*HID*HID];
__device__ __align__(16) bf16 g_bwl[NWMAT*HID*HID];

// ---------------------------------------------------------------------------
// Helpers
// ---------------------------------------------------------------------------
__device__ __forceinline__ float gelu_f(float x) {
    const float c = 0.7978845608028654f;
    float y = c * fmaf(0.044715f * x, x * x, x);
    return x / (1.0f + __expf(-2.0f * y));
}

__device__ __forceinline__ float head_scale(float r) {
    return tanf(0.25f * PI_F * (1.0f - 1e-7f) * (1.0f + sinf(r)));
}

__device__ __forceinline__ void split_bf(float v, bf16& h, bf16& l) {
    h = __float2bfloat16(v);
    l = __float2bfloat16(v - __bfloat162float(h));
}

__device__ __forceinline__ void mma_bf16(float* d,
        unsigned a0, unsigned a1, unsigned a2, unsigned a3,
        unsigned b0, unsigned b1) {
    asm volatile(
        "mma.sync.aligned.m16n8k16.row.col.f32.bf16.bf16.f32 "
        "{%0,%1,%2,%3}, {%4,%5,%6,%7}, {%8,%9}, {%0,%1,%2,%3};"
        : "+f"(d[0]), "+f"(d[1]), "+f"(d[2]), "+f"(d[3])
        : "r"(a0), "r"(a1), "r"(a2), "r"(a3), "r"(b0), "r"(b1));
}

__device__ __forceinline__ void ldsm4(unsigned& r0, unsigned& r1, unsigned& r2,
                                      unsigned& r3, unsigned addr) {
    asm volatile("ldmatrix.sync.aligned.m8n8.x4.shared.b16 {%0,%1,%2,%3}, [%4];"
        : "=r"(r0), "=r"(r1), "=r"(r2), "=r"(r3) : "r"(addr));
}

// ---------------------------------------------------------------------------
// Merged precompute kernel:
//   blocks [0,960)    : weight prep (15 mats x 64 blocks)
//   blocks [960,1984) : kNN neighbor lists (1024 queries)
//   blocks [1984,2000): separable factors + transposed copies
// ---------------------------------------------------------------------------
struct BWList { const float* w[NWMAT]; unsigned bre_mask; };

__device__ void factor_body(int h, const float* rv, float* w, float* wt,
                            int RQ, int RK) {
    int tid = threadIdx.x, lane = tid & 31, wp = tid >> 5;
    int KP = RK >> 5;
    float s = head_scale(rv[h]);
    for (int q = wp; q < RQ; q += 8) {
        float qp = (float)q / (float)RQ;
        float d[2];
        float mind = 1e30f;
        for (int i = 0; i < KP; i++) {
            int k = lane + i * 32;
            float dd = qp - (float)k / (float)RK;
            d[i] = 0.5f * dd * dd;
            mind = fminf(mind, d[i]);
        }
        for (int o = 16; o > 0; o >>= 1)
            mind = fminf(mind, __shfl_xor_sync(0xffffffffu, mind, o));
        float p[2], sum = 0.f;
        for (int i = 0; i < KP; i++) { p[i] = __expf(s * (mind - d[i])); sum += p[i]; }
        for (int o = 16; o > 0; o >>= 1)
            sum += __shfl_xor_sync(0xffffffffu, sum, o);
        float inv = 1.0f / sum;
        for (int i = 0; i < KP; i++) {
            int k = lane + i * 32;
            float val = p[i] * inv;
            w [(h * RQ + q) * RK + k] = val;
            wt[(h * RK + k) * RQ + q] = val;
        }
    }
}

__global__ void k_pre(BWList L, bf16* __restrict__ outh, bf16* __restrict__ outl,
                      int* __restrict__ kidx, int* __restrict__ kcnt,
                      const float* __restrict__ down_r, const float* __restrict__ up_r,
                      float* __restrict__ wdn, float* __restrict__ wdnT,
                      float* __restrict__ wup, float* __restrict__ wupT) {
    int bid = blockIdx.x;
    int tid = threadIdx.x;
    if (bid < 960) {
        int mat = bid >> 6;
        const float* w = L.w[mat];
        int bre = (L.bre_mask >> mat) & 1;
        int idx = (bid & 63) * 256 + tid;
        int k = idx >> 7, n = idx & 127;
        float v;
        if (bre) {
            int h = n >> 4, vd = n & 15;
            v = w[((size_t)h * HID + k) * VD + vd];
        } else {
            v = w[k * HID + n];
        }
        bf16 hi, lo;
        split_bf(v, hi, lo);
        size_t o = (size_t)mat * HID * HID + n * HID + k;
        outh[o] = hi;
        outl[o] = lo;
        return;
    }
    if (bid < 1984) {
        int q = bid - 960;
        int lane = tid & 31, w = tid >> 5;
        int qx = q & (RLAT - 1), qy = q >> 5;
        int dv[4];
#pragma unroll
        for (int i = 0; i < 4; i++) {
            int k = tid * 4 + i;
            int kx = k & (RLAT - 1), ky = k >> 5;
            int dx = qx - kx, dy = qy - ky;
            dv[i] = dx * dx + dy * dy;
        }
        __shared__ int scount;
        int lo = 0, hi = 2 * 31 * 31;
        while (lo < hi) {
            int mid = (lo + hi) >> 1;
            if (tid == 0) scount = 0;
            __syncthreads();
            int c = 0;
#pragma unroll
            for (int i = 0; i < 4; i++) c += (dv[i] <= mid);
#pragma unroll
            for (int o = 16; o > 0; o >>= 1) c += __shfl_down_sync(0xffffffffu, c, o);
            if (lane == 0) atomicAdd(&scount, c);
            __syncthreads();
            if (scount >= 21) hi = mid; else lo = mid + 1;
            __syncthreads();
        }
        int sel[4], cnt_t = 0;
#pragma unroll
        for (int i = 0; i < 4; i++) { sel[i] = (dv[i] <= lo); cnt_t += sel[i]; }
        int incl = cnt_t;
#pragma unroll
        for (int o = 1; o < 32; o <<= 1) {
            int v = __shfl_up_sync(0xffffffffu, incl, o);
            if (lane >= o) incl += v;
        }
        __shared__ int wsum[8], wbase[8];
        if (lane == 31) wsum[w] = incl;
        __syncthreads();
        if (tid == 0) {
            int b = 0;
            for (int i = 0; i < 8; i++) { wbase[i] = b; b += wsum[i]; }
            kcnt[q] = b;
        }
        __syncthreads();
        int pos = wbase[w] + incl - cnt_t;
#pragma unroll
        for (int i = 0; i < 4; i++) {
            if (sel[i] && pos < 64) kidx[q * 64 + pos] = tid * 4 + i;
            pos += sel[i];
        }
        return;
    }
    int j = bid - 1984;
    if (j < 8) factor_body(j, down_r, wdn, wdnT, RLAT, RIN);
    else       factor_body(j - 8, up_r, wup, wupT, RIN, RLAT);
}

// ---------------------------------------------------------------------------
// Tensor-core GEMM BM=128 (bf16x3 split), ldmatrix fragment loads.
// ---------------------------------------------------------------------------
template <int AENC, int DUAL, int DOGELU, int DEC, int OBF>
__global__ void __launch_bounds__(256, 1)
k_gemm(const bf16* __restrict__ Ah, const bf16* __restrict__ Al,
       const bf16* __restrict__ Bh, const bf16* __restrict__ Bl,
       const bf16* __restrict__ A2h, const bf16* __restrict__ A2l,
       const bf16* __restrict__ B2h, const bf16* __restrict__ B2l,
       const float* __restrict__ bias, const float* __restrict__ bias2,
       const float* __restrict__ x, const float* __restrict__ enw,
       const float* __restrict__ enb,
       const float* __restrict__ d2w, const float* __restrict__ d2b,
       float* __restrict__ Cf, bf16* __restrict__ Ch, bf16* __restrict__ Cl) {
    extern __shared__ __align__(16) char smem_raw[];
    bf16* sAh = (bf16*)smem_raw;
    bf16* sAl = sAh + 128 * 136;
    bf16* sBh = sAl + 128 * 136;
    bf16* sBl = sBh + 128 * 136;

    int tid = threadIdx.x;
    int wid = tid >> 5, lane = tid & 31;
    int g = lane >> 2, s = lane & 3;
    size_t rbase = (size_t)blockIdx.x * 128;

    unsigned sAh_b = (unsigned)__cvta_generic_to_shared(sAh);
    unsigned sAl_b = (unsigned)__cvta_generic_to_shared(sAl);
    unsigned sBh_b = (unsigned)__cvta_generic_to_shared(sBh);
    unsigned sBl_b = (unsigned)__cvta_generic_to_shared(sBl);
    int arowf = wid * 16 + (lane & 15);
    unsigned aoff = (unsigned)((arowf * 136 + ((lane >> 4) << 3)) * 2);
    int brow = (lane & 7) + ((lane >> 4) << 3);
    unsigned boff = (unsigned)((brow * 136 + (((lane >> 3) & 1) << 3)) * 2);

    float acc[16][4];
#pragma unroll
    for (int j = 0; j < 16; j++)
#pragma unroll
        for (int e = 0; e < 4; e++) acc[j][e] = 0.f;

    const int NPASS = DUAL ? 2 : 1;
#pragma unroll
    for (int pass = 0; pass < NPASS; pass++) {
        const bf16* Aph = (DUAL && pass) ? A2h : Ah;
        const bf16* Apl = (DUAL && pass) ? A2l : Al;
        const bf16* Bph = (DUAL && pass) ? B2h : Bh;
        const bf16* Bpl = (DUAL && pass) ? B2l : Bl;

        if (AENC && pass == 0) {
            int row = tid >> 1, half = tid & 1;
            size_t grow = rbase + row;
            float x0 = x[grow * 3 + 0], x1 = x[grow * 3 + 1], x2 = x[grow * 3 + 2];
#pragma unroll 8
            for (int c = 0; c < 64; c++) {
                int cc = half * 64 + c;
                float a = fmaf(x0, enw[cc],
                          fmaf(x1, enw[HID + cc],
                          fmaf(x2, enw[2 * HID + cc], enb[cc])));
                a = gelu_f(a);
                bf16 h, l;
                split_bf(a, h, l);
                sAh[row * 136 + cc] = h;
                sAl[row * 136 + cc] = l;
            }
        } else {
            const uint4* Ah4 = (const uint4*)(Aph + rbase * 128);
            const uint4* Al4 = (const uint4*)(Apl + rbase * 128);
#pragma unroll
            for (int i = 0; i < 8; i++) {
                int idx8 = tid + i * 256;
                int row = idx8 >> 4, k8 = (idx8 & 15) << 3;
                *(uint4*)&sAh[row * 136 + k8] = Ah4[idx8];
                *(uint4*)&sAl[row * 136 + k8] = Al4[idx8];
            }
        }
        {
            const uint4* Bh4 = (const uint4*)Bph;
            const uint4* Bl4 = (const uint4*)Bpl;
#pragma unroll
            for (int i = 0; i < 8; i++) {
                int idx8 = tid + i * 256;
                int n = idx8 >> 4, k8 = (idx8 & 15) << 3;
                *(uint4*)&sBh[n * 136 + k8] = Bh4[idx8];
                *(uint4*)&sBl[n * 136 + k8] = Bl4[idx8];
            }
        }
        __syncthreads();

#pragma unroll
        for (int ks = 0; ks < 8; ks++) {
            unsigned kb = (unsigned)(ks * 16 * 2);
            unsigned ah0, ah1, ah2, ah3, al0, al1, al2, al3;
            ldsm4(ah0, ah1, ah2, ah3, sAh_b + aoff + kb);
            ldsm4(al0, al1, al2, al3, sAl_b + aoff + kb);
#pragma unroll
            for (int j2 = 0; j2 < 8; j2++) {
                unsigned bofs = boff + (unsigned)(j2 * 16 * 136 * 2) + kb;
                unsigned bh0, bh1, bh2, bh3, bl0, bl1, bl2, bl3;
                ldsm4(bh0, bh1, bh2, bh3, sBh_b + bofs);
                ldsm4(bl0, bl1, bl2, bl3, sBl_b + bofs);
                mma_bf16(acc[2 * j2],     ah0, ah1, ah2, ah3, bh0, bh1);
                mma_bf16(acc[2 * j2],     ah0, ah1, ah2, ah3, bl0, bl1);
                mma_bf16(acc[2 * j2],     al0, al1, al2, al3, bh0, bh1);
                mma_bf16(acc[2 * j2 + 1], ah0, ah1, ah2, ah3, bh2, bh3);
                mma_bf16(acc[2 * j2 + 1], ah0, ah1, ah2, ah3, bl2, bl3);
                mma_bf16(acc[2 * j2 + 1], al0, al1, al2, al3, bh2, bh3);
            }
        }
        __syncthreads();
    }

    int r0 = wid * 16 + g;
    if (DEC) {
        float p0 = 0.f, p1 = 0.f;
#pragma unroll
        for (int j = 0; j < 16; j++) {
            int c = j * 8 + 2 * s;
            float b0 = bias ? bias[c] : 0.f;
            float b1 = bias ? bias[c + 1] : 0.f;
            float w0 = d2w[c], w1 = d2w[c + 1];
            float v0 = gelu_f(acc[j][0] + b0), v1 = gelu_f(acc[j][1] + b1);
            float v2 = gelu_f(acc[j][2] + b0), v3 = gelu_f(acc[j][3] + b1);
            p0 = fmaf(v0, w0, fmaf(v1, w1, p0));
            p1 = fmaf(v2, w0, fmaf(v3, w1, p1));
        }
        p0 += __shfl_xor_sync(0xffffffffu, p0, 1);
        p0 += __shfl_xor_sync(0xffffffffu, p0, 2);
        p1 += __shfl_xor_sync(0xffffffffu, p1, 1);
        p1 += __shfl_xor_sync(0xffffffffu, p1, 2);
        if (s == 0) {
            float db = d2b[0];
            Cf[rbase + r0] = p0 + db;
            Cf[rbase + r0 + 8] = p1 + db;
        }
    } else {
#pragma unroll
        for (int j = 0; j < 16; j++) {
            int c = j * 8 + 2 * s;
            float b0 = 0.f, b1 = 0.f;
            if (bias) {
                float2 bb = *(const float2*)&bias[c];
                b0 += bb.x; b1 += bb.y;
            }
            if (DUAL && bias2) {
                float2 bb = *(const float2*)&bias2[c];
                b0 += bb.x; b1 += bb.y;
            }
            float v0 = acc[j][0] + b0, v1 = acc[j][1] + b1;
            float v2 = acc[j][2] + b0, v3 = acc[j][3] + b1;
            if (DOGELU) {
                v0 = gelu_f(v0); v1 = gelu_f(v1);
                v2 = gelu_f(v2); v3 = gelu_f(v3);
            }
            if (OBF) {
                bf16 h0, l0, h1, l1, h2, l2, h3, l3;
                split_bf(v0, h0, l0); split_bf(v1, h1, l1);
                split_bf(v2, h2, l2); split_bf(v3, h3, l3);
                bf162 ph0 = {h0, h1}, ph1 = {h2, h3};
                bf162 pl0 = {l0, l1}, pl1 = {l2, l3};
                *(bf162*)&Ch[(rbase + r0) * 128 + c] = ph0;
                *(bf162*)&Cl[(rbase + r0) * 128 + c] = pl0;
                *(bf162*)&Ch[(rbase + r0 + 8) * 128 + c] = ph1;
                *(bf162*)&Cl[(rbase + r0 + 8) * 128 + c] = pl1;
            } else {
                float2 u0 = {v0, v1}, u1 = {v2, v3};
                *(float2*)&Cf[(rbase + r0) * 128 + c] = u0;
                *(float2*)&Cf[(rbase + r0 + 8) * 128 + c] = u1;
            }
        }
    }
}

// ---------------------------------------------------------------------------
// Separable attention step 1 (contract ky):
//   T[b][qy][kx][c] = sum_ky w[h][qy][ky] * V[b][ky*RK+kx][c]
// grid (RK/8, BATCH, NH), block 256.
// ---------------------------------------------------------------------------
template <int RQ, int RK>
__global__ void k_sepY(const float* __restrict__ V, const float* __restrict__ w,
                       float* __restrict__ T) {
    constexpr int QPT = RQ / 8;
    __shared__ float sW[RQ * RK];
    __shared__ float sV[RK * 128];
    int tid = threadIdx.x;
    int kxc = blockIdx.x;
    int b = blockIdx.y, h = blockIdx.z;
    const float* wh = w + h * RQ * RK;
    for (int i = tid; i < RQ * RK; i += 256) sW[i] = wh[i];
    for (int i = tid; i < RK * 128; i += 256) {
        int ky = i >> 7, col = i & 127;
        int kx = kxc * 8 + (col >> 4), vd = col & 15;
        sV[i] = V[(((size_t)b * RK + ky) * RK + kx) * 128 + h * 16 + vd];
    }
    __syncthreads();
    int qy0 = (tid >> 5) * QPT, col0 = (tid & 31) * 4;
    float acc[QPT][4];
#pragma unroll
    for (int i = 0; i < QPT; i++)
#pragma unroll
        for (int j = 0; j < 4; j++) acc[i][j] = 0.f;
#pragma unroll 4
    for (int ky = 0; ky < RK; ky++) {
        float4 v = *reinterpret_cast<const float4*>(&sV[ky * 128 + col0]);
#pragma unroll
        for (int i = 0; i < QPT; i++) {
            float a = sW[(qy0 + i) * RK + ky];
            acc[i][0] = fmaf(a, v.x, acc[i][0]);
            acc[i][1] = fmaf(a, v.y, acc[i][1]);
            acc[i][2] = fmaf(a, v.z, acc[i][2]);
            acc[i][3] = fmaf(a, v.w, acc[i][3]);
        }
    }
    int kx = kxc * 8 + (col0 >> 4), vd0 = col0 & 15;
#pragma unroll
    for (int i = 0; i < QPT; i++) {
        float4 r = make_float4(acc[i][0], acc[i][1], acc[i][2], acc[i][3]);
        *reinterpret_cast<float4*>(
            &T[(((size_t)b * RQ + qy0 + i) * RK + kx) * 128 + h * 16 + vd0]) = r;
    }
}

// ---------------------------------------------------------------------------
// Separable attention step 2 (contract kx), fused gelu, bf16 hi/lo output.
// Round-9 structure (grid (RQ qy, B, NH), 4096/8192 blocks, small smem, high
// occupancy) but with TRANSPOSED weights sWt[kx][qx] staged coalesced from the
// pre-transposed global, removing the 16-way bank conflict: per kx the QPT2
// consecutive-qx weights load as one float2/float4 (broadcast addresses).
// ---------------------------------------------------------------------------
template <int RQ, int RK>
__global__ void k_sepX(const float* __restrict__ T, const float* __restrict__ wT,
                       bf16* __restrict__ Oh, bf16* __restrict__ Ol) {
    constexpr int QPT2 = RQ * 16 / 256;   // 2 (down) or 4 (up)
    __shared__ __align__(16) float sWt[RK * RQ];   // [kx][qx]
    __shared__ float sT[RK * 16];
    int tid = threadIdx.x;
    int qy = blockIdx.x;
    int b = blockIdx.y, h = blockIdx.z;
    const float* wth = wT + h * RQ * RK;
    for (int i = tid; i < RQ * RK; i += 256) sWt[i] = wth[i];
    for (int i = tid; i < RK * 16; i += 256) {
        int kx = i >> 4, vd = i & 15;
        sT[i] = T[(((size_t)b * RQ + qy) * RK + kx) * 128 + h * 16 + vd];
    }
    __syncthreads();
    int c = tid & 15;
    int qx0 = (tid >> 4) * QPT2;
    float acc[QPT2];
#pragma unroll
    for (int i = 0; i < QPT2; i++) acc[i] = 0.f;
#pragma unroll 8
    for (int kx = 0; kx < RK; kx++) {
        float v = sT[kx * 16 + c];
        if (QPT2 == 2) {
            float2 wv = *(const float2*)&sWt[kx * RQ + qx0];
            acc[0] = fmaf(wv.x, v, acc[0]);
            acc[1] = fmaf(wv.y, v, acc[1]);
        } else {
            float4 wv = *(const float4*)&sWt[kx * RQ + qx0];
            acc[0] = fmaf(wv.x, v, acc[0]);
            acc[1] = fmaf(wv.y, v, acc[1]);
            acc[2] = fmaf(wv.z, v, acc[2]);
            acc[3] = fmaf(wv.w, v, acc[3]);
        }
    }
#pragma unroll
    for (int i = 0; i < QPT2; i++) {
        float gv = gelu_f(acc[i]);
        bf16 hi, lo;
        split_bf(gv, hi, lo);
        size_t oi = ((size_t)b * RQ * RQ + qy * RQ + qx0 + i) * 128 + h * 16 + c;
        Oh[oi] = hi;
        Ol[oi] = lo;
    }
}

// ---------------------------------------------------------------------------
// Tiled sparse proc attention -> bf16 plane output
// ---------------------------------------------------------------------------
__global__ void __launch_bounds__(256, 1)
k_procatt(const float* __restrict__ V, const float* __restrict__ rv,
          const int* __restrict__ kidx, const int* __restrict__ kcnt,
          bf16* __restrict__ Oh, bf16* __restrict__ Ol) {
    extern __shared__ float psm[];
    float* sV   = psm;
    float* sp   = sV + 256 * 128;
    int*   skl  = (int*)(sp + 64 * KMAX * 8);
    int*   scnt = skl + 64 * KMAX;
    float* sinv = (float*)(scnt + 64);
    __shared__ float sscale[NH];

    int tile = blockIdx.x;
    int b = blockIdx.y;
    int tx = tile & 3, ty = tile >> 2;
    int x0 = tx * 8 - 4, y0 = ty * 8 - 4;
    int tid = threadIdx.x, lane = tid & 31, w = tid >> 5;

    if (tid < NH) sscale[tid] = head_scale(rv[tid]);

    const float4* V4 = (const float4*)V;
    for (int r = w; r < 256; r += 8) {
        int ix = r & 15, iy = r >> 4;
        int kx = x0 + ix, ky = y0 + iy;
        if ((unsigned)kx < 32u && (unsigned)ky < 32u) {
            int k = ky * 32 + kx;
            *(float4*)&sV[r * 128 + lane * 4] = V4[((size_t)b * NLAT + k) * 32 + lane];
        }
    }
    if (tid < 64) {
        int qx = tx * 8 + (tid & 7), qy = ty * 8 + (tid >> 3);
        scnt[tid] = kcnt[qy * 32 + qx];
    }
    for (int i = tid; i < 64 * KMAX; i += 256) {
        int ql = i / KMAX, j = i - ql * KMAX;
        if (j < 64) {
            int qx = tx * 8 + (ql & 7), qy = ty * 8 + (ql >> 3);
            int gk = kidx[(qy * 32 + qx) * 64 + j];
            int kx = gk & 31, ky = gk >> 5;
            skl[i] = (ky - y0) * 16 + (kx - x0);
        }
    }
    __syncthreads();
    for (int i = tid; i < 64 * KMAX; i += 256) {
        int ql = i / KMAX, j = i - ql * KMAX;
        if (j < scnt[ql]) {
            int kl = skl[i];
            int ix = kl & 15, iy = kl >> 4;
            float dx = (float)(ix - 4 - (ql & 7)) * (1.0f / RLAT);
            float dy = (float)(iy - 4 - (ql >> 3)) * (1.0f / RLAT);
            float dist = 0.5f * (dx * dx + dy * dy);
#pragma unroll
            for (int h = 0; h < NH; h++)
                sp[i * 8 + h] = __expf(-sscale[h] * dist);
        }
    }
    __syncthreads();
    for (int hq = tid; hq < 512; hq += 256) {
        int ql = hq >> 3, h = hq & 7;
        int cnt = scnt[ql];
        float sum = 0.f;
        for (int j = 0; j < cnt; j++) sum += sp[(ql * KMAX + j) * 8 + h];
        sinv[ql * 8 + h] = 1.0f / sum;
    }
    __syncthreads();

    int qy_l = w;
    int cg = lane;
    int h = cg >> 2;
    const float4* sV4 = (const float4*)sV;
#pragma unroll
    for (int qx_l = 0; qx_l < 8; qx_l++) {
        int ql = qy_l * 8 + qx_l;
        int cnt = scnt[ql];
        int base = ql * KMAX;
        float4 acc = make_float4(0.f, 0.f, 0.f, 0.f);
        for (int j = 0; j < cnt; j++) {
            float p = sp[(base + j) * 8 + h];
            float4 v = sV4[skl[base + j] * 32 + cg];
            acc.x = fmaf(p, v.x, acc.x);
            acc.y = fmaf(p, v.y, acc.y);
            acc.z = fmaf(p, v.z, acc.z);
            acc.w = fmaf(p, v.w, acc.w);
        }
        float inv = sinv[ql * 8 + h];
        float r0 = gelu_f(acc.x * inv), r1 = gelu_f(acc.y * inv);
        float r2 = gelu_f(acc.z * inv), r3 = gelu_f(acc.w * inv);
        int qglob = (ty * 8 + qy_l) * 32 + tx * 8 + qx_l;
        size_t oi = ((size_t)b * NLAT + qglob) * 128 + cg * 4;
        bf16 h0, l0, h1, l1, h2, l2, h3, l3;
        split_bf(r0, h0, l0); split_bf(r1, h1, l1);
        split_bf(r2, h2, l2); split_bf(r3, h3, l3);
        bf162 ph0 = {h0, h1}, ph1 = {h2, h3};
        bf162 pl0 = {l0, l1}, pl1 = {l2, l3};
        *(bf162*)&Oh[oi] = ph0;
        *(bf162*)&Oh[oi + 2] = ph1;
        *(bf162*)&Ol[oi] = pl0;
        *(bf162*)&Ol[oi + 2] = pl1;
    }
}

// ---------------------------------------------------------------------------
// Launcher
// ---------------------------------------------------------------------------
extern "C" void kernel_launch(void* const* d_in, const int* in_sizes, int n_in,
                              void* d_out, int out_size) {
    const float* x        = (const float*)d_in[0];
    const float* en_w     = (const float*)d_in[1];
    const float* en_b     = (const float*)d_in[2];
    const float* down_r   = (const float*)d_in[3];
    const float* down_w   = (const float*)d_in[4];
    const float* pa_r     = (const float*)d_in[5];
    const float* pa_w     = (const float*)d_in[6];
    const float* mlp1_w   = (const float*)d_in[7];
    const float* mlp1_b   = (const float*)d_in[8];
    const float* mlp2_w   = (const float*)d_in[9];
    const float* mlp2_b   = (const float*)d_in[10];
    const float* res_w    = (const float*)d_in[11];
    const float* res_b    = (const float*)d_in[12];
    const float* up_r     = (const float*)d_in[13];
    const float* up_w     = (const float*)d_in[14];
    const float* de1_w    = (const float*)d_in[15];
    const float* de1_b    = (const float*)d_in[16];
    const float* de2_w    = (const float*)d_in[17];
    const float* de2_b    = (const float*)d_in[18];
    float* out = (float*)d_out;

    float *val, *T, *wdn, *wdnT, *wup, *wupT;
    int *kidx, *kcnt;
    bf16 *bwh, *bwl;
    bf16 *hAh, *hAl, *hBh, *hBl, *pah, *pal, *t1h, *t1l, *huph, *hupl;
    cudaGetSymbolAddress((void**)&val,  g_val);
    cudaGetSymbolAddress((void**)&T,    g_T);
    cudaGetSymbolAddress((void**)&wdn,  g_wdn);
    cudaGetSymbolAddress((void**)&wdnT, g_wdnT);
    cudaGetSymbolAddress((void**)&wup,  g_wup);
    cudaGetSymbolAddress((void**)&wupT, g_wupT);
    cudaGetSymbolAddress((void**)&kidx, g_kidx);
    cudaGetSymbolAddress((void**)&kcnt, g_kcnt);
    cudaGetSymbolAddress((void**)&bwh,  g_bwh);
    cudaGetSymbolAddress((void**)&bwl,  g_bwl);
    cudaGetSymbolAddress((void**)&hAh,  g_hA_h);
    cudaGetSymbolAddress((void**)&hAl,  g_hA_l);
    cudaGetSymbolAddress((void**)&hBh,  g_hB_h);
    cudaGetSymbolAddress((void**)&hBl,  g_hB_l);
    cudaGetSymbolAddress((void**)&pah,  g_pa_h);
    cudaGetSymbolAddress((void**)&pal,  g_pa_l);
    cudaGetSymbolAddress((void**)&t1h,  g_t1_h);
    cudaGetSymbolAddress((void**)&t1l,  g_t1_l);
    cudaGetSymbolAddress((void**)&huph, g_hup_h);
    cudaGetSymbolAddress((void**)&hupl, g_hup_l);

    cudaFuncSetAttribute(k_gemm<1,0,0,0,0>, cudaFuncAttributeMaxDynamicSharedMemorySize, GEMM_SMEM);
    cudaFuncSetAttribute(k_gemm<0,0,0,0,0>, cudaFuncAttributeMaxDynamicSharedMemorySize, GEMM_SMEM);
    cudaFuncSetAttribute(k_gemm<0,0,1,0,1>, cudaFuncAttributeMaxDynamicSharedMemorySize, GEMM_SMEM);
    cudaFuncSetAttribute(k_gemm<0,1,1,0,1>, cudaFuncAttributeMaxDynamicSharedMemorySize, GEMM_SMEM);
    cudaFuncSetAttribute(k_gemm<0,0,1,1,0>, cudaFuncAttributeMaxDynamicSharedMemorySize, GEMM_SMEM);
    cudaFuncSetAttribute(k_procatt, cudaFuncAttributeMaxDynamicSharedMemorySize, PROC_SMEM);

    const int M_IN  = BATCH * NIN;   // 65536
    const int M_LAT = BATCH * NLAT;  // 16384
    const size_t MS = (size_t)HID * HID;

    BWList L;
    L.w[0] = down_w;
    L.w[1] = pa_w;          L.w[2] = pa_w + 16384;  L.w[3] = pa_w + 32768;
    L.w[4] = up_w;
    L.w[5] = mlp1_w;        L.w[6] = mlp1_w + MS;   L.w[7] = mlp1_w + 2 * MS;
    L.w[8] = mlp2_w;        L.w[9] = mlp2_w + MS;   L.w[10] = mlp2_w + 2 * MS;
    L.w[11] = res_w;        L.w[12] = res_w + MS;   L.w[13] = res_w + 2 * MS;
    L.w[14] = de1_w;
    L.bre_mask = 0x1F;

    // merged precompute: weights + knn + factors (+ transposed factors)
    k_pre<<<2000, 256>>>(L, bwh, bwl, kidx, kcnt, down_r, up_r,
                         wdn, wdnT, wup, wupT);

#define BW(i) (bwh + (size_t)(i) * MS), (bwl + (size_t)(i) * MS)
#define NUL4 nullptr, nullptr, nullptr, nullptr

    // ---- down: fused encoder + value GEMM, then separable attention ----
    k_gemm<1,0,0,0,0><<<M_IN / 128, 256, GEMM_SMEM>>>(
        nullptr, nullptr, BW(0), NUL4,
        nullptr, nullptr, x, en_w, en_b, nullptr, nullptr,
        val, nullptr, nullptr);
    {
        dim3 g1(RIN / 8, BATCH, NH);
        k_sepY<RLAT, RIN><<<g1, 256>>>(val, wdn, T);
        dim3 g2(RLAT, BATCH, NH);
        k_sepX<RLAT, RIN><<<g2, 256>>>(T, wdnT, hAh, hAl);
    }

    // ---- processor blocks ----
    bf16 *hinh = hAh, *hinl = hAl, *houth = hBh, *houtl = hBl;
    for (int i = 0; i < 3; i++) {
        k_gemm<0,0,0,0,0><<<M_LAT / 128, 256, GEMM_SMEM>>>(
            hinh, hinl, BW(1 + i), NUL4,
            nullptr, nullptr, nullptr, nullptr, nullptr, nullptr, nullptr,
            val, nullptr, nullptr);
        {
            dim3 g(16, BATCH);
            k_procatt<<<g, 256, PROC_SMEM>>>(val, pa_r + i * NH, kidx, kcnt, pah, pal);
        }
        k_gemm<0,0,1,0,1><<<M_LAT / 128, 256, GEMM_SMEM>>>(
            pah, pal, BW(5 + i), NUL4,
            mlp1_b + i * HID, nullptr, nullptr, nullptr, nullptr, nullptr, nullptr,
            nullptr, t1h, t1l);
        k_gemm<0,1,1,0,1><<<M_LAT / 128, 256, GEMM_SMEM>>>(
            t1h, t1l, BW(8 + i), hinh, hinl, BW(11 + i),
            mlp2_b + i * HID, res_b + i * HID,
            nullptr, nullptr, nullptr, nullptr, nullptr,
            nullptr, houth, houtl);
        bf16* t;
        t = hinh; hinh = houth; houth = t;
        t = hinl; hinl = houtl; houtl = t;
    }

    // ---- up: value GEMM + separable attention ----
    k_gemm<0,0,0,0,0><<<M_LAT / 128, 256, GEMM_SMEM>>>(
        hinh, hinl, BW(4), NUL4,
        nullptr, nullptr, nullptr, nullptr, nullptr, nullptr, nullptr,
        val, nullptr, nullptr);
    {
        dim3 g1(RLAT / 8, BATCH, NH);
        k_sepY<RIN, RLAT><<<g1, 256>>>(val, wup, T);
        dim3 g2(RIN, BATCH, NH);
        k_sepX<RIN, RLAT><<<g2, 256>>>(T, wupT, huph, hupl);
    }

    // ---- fused decoder ----
    k_gemm<0,0,1,1,0><<<M_IN / 128, 256, GEMM_SMEM>>>(
        huph, hupl, BW(14), NUL4,
        de1_b, nullptr, nullptr, nullptr, nullptr, de2_w, de2_b,
        out, nullptr, nullptr);
#undef BW
#undef NUL4
}

// round 14
// speedup vs baseline: 1.1942x; 1.0270x over previous
#include <cuda_runtime.h>
#include <cuda_bf16.h>
#include <math.h>

// ---------------------------------------------------------------------------
// Problem constants
// ---------------------------------------------------------------------------
#define BATCH   16
#define NH      8
#define HID     128
#define VD      16
#define RIN     64
#define RLAT    32
#define NIN     (RIN*RIN)   // 4096
#define NLAT    (RLAT*RLAT) // 1024
#define PI_F    3.14159265358979323846f

#define NWMAT   15
#define GEMM_SMEM (4*128*136*2)   // BM=128: 139264 bytes

// procatt tiled smem budget
#define KMAX  40
#define PROC_SMEM (256*128*4 + 64*KMAX*8*4 + 64*KMAX*4 + 64*4 + 64*8*4)  // 225536

typedef __nv_bfloat16 bf16;
typedef __nv_bfloat162 bf162;

// ---------------------------------------------------------------------------
// Scratch buffers
// ---------------------------------------------------------------------------
__device__ float g_val[BATCH*NIN*HID];                       // f32 value proj
__device__ float g_T  [BATCH*2048*HID];                      // sep-attention T
__device__ __align__(16) bf16 g_hA_h[BATCH*NLAT*HID];
__device__ __align__(16) bf16 g_hA_l[BATCH*NLAT*HID];
__device__ __align__(16) bf16 g_hB_h[BATCH*NLAT*HID];
__device__ __align__(16) bf16 g_hB_l[BATCH*NLAT*HID];
__device__ __align__(16) bf16 g_pa_h[BATCH*NLAT*HID];
__device__ __align__(16) bf16 g_pa_l[BATCH*NLAT*HID];
__device__ __align__(16) bf16 g_t1_h[BATCH*NLAT*HID];
__device__ __align__(16) bf16 g_t1_l[BATCH*NLAT*HID];
__device__ __align__(16) bf16 g_hup_h[BATCH*NIN*HID];
__device__ __align__(16) bf16 g_hup_l[BATCH*NIN*HID];
__device__ float g_wdn [NH*RLAT*RIN];    // [h][qy][ky]
__device__ float g_wdnT[NH*RIN*RLAT];    // [h][kx][qx]  (transposed)
__device__ float g_wup [NH*RIN*RLAT];
__device__ float g_wupT[NH*RLAT*RIN];
__device__ int   g_kidx[NLAT*64];
__device__ int   g_kcnt[NLAT];
__device__ __align__(16) bf16 g_bwh[NWMAT*HID*HID];
__device__ __align__(16) bf16 g_bwl[NWMAT*HID*HID];

// ---------------------------------------------------------------------------
// Helpers
// ---------------------------------------------------------------------------
__device__ __forceinline__ float gelu_f(float x) {
    const float c = 0.7978845608028654f;
    float y = c * fmaf(0.044715f * x, x * x, x);
    return x / (1.0f + __expf(-2.0f * y));
}

__device__ __forceinline__ float head_scale(float r) {
    return tanf(0.25f * PI_F * (1.0f - 1e-7f) * (1.0f + sinf(r)));
}

__device__ __forceinline__ void split_bf(float v, bf16& h, bf16& l) {
    h = __float2bfloat16(v);
    l = __float2bfloat16(v - __bfloat162float(h));
}

__device__ __forceinline__ void mma_bf16(float* d,
        unsigned a0, unsigned a1, unsigned a2, unsigned a3,
        unsigned b0, unsigned b1) {
    asm volatile(
        "mma.sync.aligned.m16n8k16.row.col.f32.bf16.bf16.f32 "
        "{%0,%1,%2,%3}, {%4,%5,%6,%7}, {%8,%9}, {%0,%1,%2,%3};"
        : "+f"(d[0]), "+f"(d[1]), "+f"(d[2]), "+f"(d[3])
        : "r"(a0), "r"(a1), "r"(a2), "r"(a3), "r"(b0), "r"(b1));
}

__device__ __forceinline__ void ldsm4(unsigned& r0, unsigned& r1, unsigned& r2,
                                      unsigned& r3, unsigned addr) {
    asm volatile("ldmatrix.sync.aligned.m8n8.x4.shared.b16 {%0,%1,%2,%3}, [%4];"
        : "=r"(r0), "=r"(r1), "=r"(r2), "=r"(r3) : "r"(addr));
}

// ---------------------------------------------------------------------------
// Merged precompute kernel:
//   blocks [0,960)    : weight prep (15 mats x 64 blocks)
//   blocks [960,1984) : kNN neighbor lists (1024 queries)
//   blocks [1984,2000): separable factors + transposed copies
// ---------------------------------------------------------------------------
struct BWList { const float* w[NWMAT]; unsigned bre_mask; };

__device__ void factor_body(int h, const float* rv, float* w, float* wt,
                            int RQ, int RK) {
    int tid = threadIdx.x, lane = tid & 31, wp = tid >> 5;
    int KP = RK >> 5;
    float s = head_scale(rv[h]);
    for (int q = wp; q < RQ; q += 8) {
        float qp = (float)q / (float)RQ;
        float d[2];
        float mind = 1e30f;
        for (int i = 0; i < KP; i++) {
            int k = lane + i * 32;
            float dd = qp - (float)k / (float)RK;
            d[i] = 0.5f * dd * dd;
            mind = fminf(mind, d[i]);
        }
        for (int o = 16; o > 0; o >>= 1)
            mind = fminf(mind, __shfl_xor_sync(0xffffffffu, mind, o));
        float p[2], sum = 0.f;
        for (int i = 0; i < KP; i++) { p[i] = __expf(s * (mind - d[i])); sum += p[i]; }
        for (int o = 16; o > 0; o >>= 1)
            sum += __shfl_xor_sync(0xffffffffu, sum, o);
        float inv = 1.0f / sum;
        for (int i = 0; i < KP; i++) {
            int k = lane + i * 32;
            float val = p[i] * inv;
            w [(h * RQ + q) * RK + k] = val;
            wt[(h * RK + k) * RQ + q] = val;
        }
    }
}

__global__ void k_pre(BWList L, bf16* __restrict__ outh, bf16* __restrict__ outl,
                      int* __restrict__ kidx, int* __restrict__ kcnt,
                      const float* __restrict__ down_r, const float* __restrict__ up_r,
                      float* __restrict__ wdn, float* __restrict__ wdnT,
                      float* __restrict__ wup, float* __restrict__ wupT) {
    int bid = blockIdx.x;
    int tid = threadIdx.x;
    if (bid < 960) {
        int mat = bid >> 6;
        const float* w = L.w[mat];
        int bre = (L.bre_mask >> mat) & 1;
        int idx = (bid & 63) * 256 + tid;
        int k = idx >> 7, n = idx & 127;
        float v;
        if (bre) {
            int h = n >> 4, vd = n & 15;
            v = w[((size_t)h * HID + k) * VD + vd];
        } else {
            v = w[k * HID + n];
        }
        bf16 hi, lo;
        split_bf(v, hi, lo);
        size_t o = (size_t)mat * HID * HID + n * HID + k;
        outh[o] = hi;
        outl[o] = lo;
        return;
    }
    if (bid < 1984) {
        int q = bid - 960;
        int lane = tid & 31, w = tid >> 5;
        int qx = q & (RLAT - 1), qy = q >> 5;
        int dv[4];
#pragma unroll
        for (int i = 0; i < 4; i++) {
            int k = tid * 4 + i;
            int kx = k & (RLAT - 1), ky = k >> 5;
            int dx = qx - kx, dy = qy - ky;
            dv[i] = dx * dx + dy * dy;
        }
        __shared__ int scount;
        int lo = 0, hi = 2 * 31 * 31;
        while (lo < hi) {
            int mid = (lo + hi) >> 1;
            if (tid == 0) scount = 0;
            __syncthreads();
            int c = 0;
#pragma unroll
            for (int i = 0; i < 4; i++) c += (dv[i] <= mid);
#pragma unroll
            for (int o = 16; o > 0; o >>= 1) c += __shfl_down_sync(0xffffffffu, c, o);
            if (lane == 0) atomicAdd(&scount, c);
            __syncthreads();
            if (scount >= 21) hi = mid; else lo = mid + 1;
            __syncthreads();
        }
        int sel[4], cnt_t = 0;
#pragma unroll
        for (int i = 0; i < 4; i++) { sel[i] = (dv[i] <= lo); cnt_t += sel[i]; }
        int incl = cnt_t;
#pragma unroll
        for (int o = 1; o < 32; o <<= 1) {
            int v = __shfl_up_sync(0xffffffffu, incl, o);
            if (lane >= o) incl += v;
        }
        __shared__ int wsum[8], wbase[8];
        if (lane == 31) wsum[w] = incl;
        __syncthreads();
        if (tid == 0) {
            int b = 0;
            for (int i = 0; i < 8; i++) { wbase[i] = b; b += wsum[i]; }
            kcnt[q] = b;
        }
        __syncthreads();
        int pos = wbase[w] + incl - cnt_t;
#pragma unroll
        for (int i = 0; i < 4; i++) {
            if (sel[i] && pos < 64) kidx[q * 64 + pos] = tid * 4 + i;
            pos += sel[i];
        }
        return;
    }
    int j = bid - 1984;
    if (j < 8) factor_body(j, down_r, wdn, wdnT, RLAT, RIN);
    else       factor_body(j - 8, up_r, wup, wupT, RIN, RLAT);
}

// ---------------------------------------------------------------------------
// Tensor-core GEMM BM=128 (bf16x3 split), ldmatrix fragment loads.
// ---------------------------------------------------------------------------
template <int AENC, int DUAL, int DOGELU, int DEC, int OBF>
__global__ void __launch_bounds__(256, 1)
k_gemm(const bf16* __restrict__ Ah, const bf16* __restrict__ Al,
       const bf16* __restrict__ Bh, const bf16* __restrict__ Bl,
       const bf16* __restrict__ A2h, const bf16* __restrict__ A2l,
       const bf16* __restrict__ B2h, const bf16* __restrict__ B2l,
       const float* __restrict__ bias, const float* __restrict__ bias2,
       const float* __restrict__ x, const float* __restrict__ enw,
       const float* __restrict__ enb,
       const float* __restrict__ d2w, const float* __restrict__ d2b,
       float* __restrict__ Cf, bf16* __restrict__ Ch, bf16* __restrict__ Cl) {
    extern __shared__ __align__(16) char smem_raw[];
    bf16* sAh = (bf16*)smem_raw;
    bf16* sAl = sAh + 128 * 136;
    bf16* sBh = sAl + 128 * 136;
    bf16* sBl = sBh + 128 * 136;

    int tid = threadIdx.x;
    int wid = tid >> 5, lane = tid & 31;
    int g = lane >> 2, s = lane & 3;
    size_t rbase = (size_t)blockIdx.x * 128;

    unsigned sAh_b = (unsigned)__cvta_generic_to_shared(sAh);
    unsigned sAl_b = (unsigned)__cvta_generic_to_shared(sAl);
    unsigned sBh_b = (unsigned)__cvta_generic_to_shared(sBh);
    unsigned sBl_b = (unsigned)__cvta_generic_to_shared(sBl);
    int arowf = wid * 16 + (lane & 15);
    unsigned aoff = (unsigned)((arowf * 136 + ((lane >> 4) << 3)) * 2);
    int brow = (lane & 7) + ((lane >> 4) << 3);
    unsigned boff = (unsigned)((brow * 136 + (((lane >> 3) & 1) << 3)) * 2);

    float acc[16][4];
#pragma unroll
    for (int j = 0; j < 16; j++)
#pragma unroll
        for (int e = 0; e < 4; e++) acc[j][e] = 0.f;

    const int NPASS = DUAL ? 2 : 1;
#pragma unroll
    for (int pass = 0; pass < NPASS; pass++) {
        const bf16* Aph = (DUAL && pass) ? A2h : Ah;
        const bf16* Apl = (DUAL && pass) ? A2l : Al;
        const bf16* Bph = (DUAL && pass) ? B2h : Bh;
        const bf16* Bpl = (DUAL && pass) ? B2l : Bl;

        if (AENC && pass == 0) {
            int row = tid >> 1, half = tid & 1;
            size_t grow = rbase + row;
            float x0 = x[grow * 3 + 0], x1 = x[grow * 3 + 1], x2 = x[grow * 3 + 2];
#pragma unroll 8
            for (int c = 0; c < 64; c++) {
                int cc = half * 64 + c;
                float a = fmaf(x0, enw[cc],
                          fmaf(x1, enw[HID + cc],
                          fmaf(x2, enw[2 * HID + cc], enb[cc])));
                a = gelu_f(a);
                bf16 h, l;
                split_bf(a, h, l);
                sAh[row * 136 + cc] = h;
                sAl[row * 136 + cc] = l;
            }
        } else {
            const uint4* Ah4 = (const uint4*)(Aph + rbase * 128);
            const uint4* Al4 = (const uint4*)(Apl + rbase * 128);
#pragma unroll
            for (int i = 0; i < 8; i++) {
                int idx8 = tid + i * 256;
                int row = idx8 >> 4, k8 = (idx8 & 15) << 3;
                *(uint4*)&sAh[row * 136 + k8] = Ah4[idx8];
                *(uint4*)&sAl[row * 136 + k8] = Al4[idx8];
            }
        }
        {
            const uint4* Bh4 = (const uint4*)Bph;
            const uint4* Bl4 = (const uint4*)Bpl;
#pragma unroll
            for (int i = 0; i < 8; i++) {
                int idx8 = tid + i * 256;
                int n = idx8 >> 4, k8 = (idx8 & 15) << 3;
                *(uint4*)&sBh[n * 136 + k8] = Bh4[idx8];
                *(uint4*)&sBl[n * 136 + k8] = Bl4[idx8];
            }
        }
        __syncthreads();

#pragma unroll
        for (int ks = 0; ks < 8; ks++) {
            unsigned kb = (unsigned)(ks * 16 * 2);
            unsigned ah0, ah1, ah2, ah3, al0, al1, al2, al3;
            ldsm4(ah0, ah1, ah2, ah3, sAh_b + aoff + kb);
            ldsm4(al0, al1, al2, al3, sAl_b + aoff + kb);
#pragma unroll
            for (int j2 = 0; j2 < 8; j2++) {
                unsigned bofs = boff + (unsigned)(j2 * 16 * 136 * 2) + kb;
                unsigned bh0, bh1, bh2, bh3, bl0, bl1, bl2, bl3;
                ldsm4(bh0, bh1, bh2, bh3, sBh_b + bofs);
                ldsm4(bl0, bl1, bl2, bl3, sBl_b + bofs);
                mma_bf16(acc[2 * j2],     ah0, ah1, ah2, ah3, bh0, bh1);
                mma_bf16(acc[2 * j2],     ah0, ah1, ah2, ah3, bl0, bl1);
                mma_bf16(acc[2 * j2],     al0, al1, al2, al3, bh0, bh1);
                mma_bf16(acc[2 * j2 + 1], ah0, ah1, ah2, ah3, bh2, bh3);
                mma_bf16(acc[2 * j2 + 1], ah0, ah1, ah2, ah3, bl2, bl3);
                mma_bf16(acc[2 * j2 + 1], al0, al1, al2, al3, bh2, bh3);
            }
        }
        __syncthreads();
    }

    int r0 = wid * 16 + g;
    if (DEC) {
        float p0 = 0.f, p1 = 0.f;
#pragma unroll
        for (int j = 0; j < 16; j++) {
            int c = j * 8 + 2 * s;
            float b0 = bias ? bias[c] : 0.f;
            float b1 = bias ? bias[c + 1] : 0.f;
            float w0 = d2w[c], w1 = d2w[c + 1];
            float v0 = gelu_f(acc[j][0] + b0), v1 = gelu_f(acc[j][1] + b1);
            float v2 = gelu_f(acc[j][2] + b0), v3 = gelu_f(acc[j][3] + b1);
            p0 = fmaf(v0, w0, fmaf(v1, w1, p0));
            p1 = fmaf(v2, w0, fmaf(v3, w1, p1));
        }
        p0 += __shfl_xor_sync(0xffffffffu, p0, 1);
        p0 += __shfl_xor_sync(0xffffffffu, p0, 2);
        p1 += __shfl_xor_sync(0xffffffffu, p1, 1);
        p1 += __shfl_xor_sync(0xffffffffu, p1, 2);
        if (s == 0) {
            float db = d2b[0];
            Cf[rbase + r0] = p0 + db;
            Cf[rbase + r0 + 8] = p1 + db;
        }
    } else {
#pragma unroll
        for (int j = 0; j < 16; j++) {
            int c = j * 8 + 2 * s;
            float b0 = 0.f, b1 = 0.f;
            if (bias) {
                float2 bb = *(const float2*)&bias[c];
                b0 += bb.x; b1 += bb.y;
            }
            if (DUAL && bias2) {
                float2 bb = *(const float2*)&bias2[c];
                b0 += bb.x; b1 += bb.y;
            }
            float v0 = acc[j][0] + b0, v1 = acc[j][1] + b1;
            float v2 = acc[j][2] + b0, v3 = acc[j][3] + b1;
            if (DOGELU) {
                v0 = gelu_f(v0); v1 = gelu_f(v1);
                v2 = gelu_f(v2); v3 = gelu_f(v3);
            }
            if (OBF) {
                bf16 h0, l0, h1, l1, h2, l2, h3, l3;
                split_bf(v0, h0, l0); split_bf(v1, h1, l1);
                split_bf(v2, h2, l2); split_bf(v3, h3, l3);
                bf162 ph0 = {h0, h1}, ph1 = {h2, h3};
                bf162 pl0 = {l0, l1}, pl1 = {l2, l3};
                *(bf162*)&Ch[(rbase + r0) * 128 + c] = ph0;
                *(bf162*)&Cl[(rbase + r0) * 128 + c] = pl0;
                *(bf162*)&Ch[(rbase + r0 + 8) * 128 + c] = ph1;
                *(bf162*)&Cl[(rbase + r0 + 8) * 128 + c] = pl1;
            } else {
                float2 u0 = {v0, v1}, u1 = {v2, v3};
                *(float2*)&Cf[(rbase + r0) * 128 + c] = u0;
                *(float2*)&Cf[(rbase + r0 + 8) * 128 + c] = u1;
            }
        }
    }
}

// ---------------------------------------------------------------------------
// Separable attention step 1 (contract ky):
//   T[b][qy][kx][c] = sum_ky w[h][qy][ky] * V[b][ky*RK+kx][c]
// grid (RK/8, BATCH, NH), block 256.
// ---------------------------------------------------------------------------
template <int RQ, int RK>
__global__ void k_sepY(const float* __restrict__ V, const float* __restrict__ w,
                       float* __restrict__ T) {
    constexpr int QPT = RQ / 8;
    __shared__ float sW[RQ * RK];
    __shared__ float sV[RK * 128];
    int tid = threadIdx.x;
    int kxc = blockIdx.x;
    int b = blockIdx.y, h = blockIdx.z;
    const float* wh = w + h * RQ * RK;
    for (int i = tid; i < RQ * RK; i += 256) sW[i] = wh[i];
    for (int i = tid; i < RK * 128; i += 256) {
        int ky = i >> 7, col = i & 127;
        int kx = kxc * 8 + (col >> 4), vd = col & 15;
        sV[i] = V[(((size_t)b * RK + ky) * RK + kx) * 128 + h * 16 + vd];
    }
    __syncthreads();
    int qy0 = (tid >> 5) * QPT, col0 = (tid & 31) * 4;
    float acc[QPT][4];
#pragma unroll
    for (int i = 0; i < QPT; i++)
#pragma unroll
        for (int j = 0; j < 4; j++) acc[i][j] = 0.f;
#pragma unroll 4
    for (int ky = 0; ky < RK; ky++) {
        float4 v = *reinterpret_cast<const float4*>(&sV[ky * 128 + col0]);
#pragma unroll
        for (int i = 0; i < QPT; i++) {
            float a = sW[(qy0 + i) * RK + ky];
            acc[i][0] = fmaf(a, v.x, acc[i][0]);
            acc[i][1] = fmaf(a, v.y, acc[i][1]);
            acc[i][2] = fmaf(a, v.z, acc[i][2]);
            acc[i][3] = fmaf(a, v.w, acc[i][3]);
        }
    }
    int kx = kxc * 8 + (col0 >> 4), vd0 = col0 & 15;
#pragma unroll
    for (int i = 0; i < QPT; i++) {
        float4 r = make_float4(acc[i][0], acc[i][1], acc[i][2], acc[i][3]);
        *reinterpret_cast<float4*>(
            &T[(((size_t)b * RQ + qy0 + i) * RK + kx) * 128 + h * 16 + vd0]) = r;
    }
}

// ---------------------------------------------------------------------------
// Separable attention step 2 (contract kx), fused gelu, bf16 hi/lo output.
// 4x4 register tile: block = (QYT qy rows, b, h), QYT = 256/RQ (down 8, up 4).
// Thread = (qp, qx-group of 4, c-group of 4); per kx: 1 float4 weight LDS +
// 1 float4 sT LDS + 16 FMA. Single stage + single sync; coalesced staging
// from pre-transposed weights. kx-ascending fmaf order => bit-identical.
// ---------------------------------------------------------------------------
template <int RQ, int RK>
__global__ void __launch_bounds__(256, 1)
k_sepX(const float* __restrict__ T, const float* __restrict__ wT,
       bf16* __restrict__ Oh, bf16* __restrict__ Ol) {
    constexpr int QYT = 256 / RQ;            // threads per qy row == RQ
    __shared__ __align__(16) float sWt[RK * RQ];       // [kx][qx]
    __shared__ __align__(16) float sT[QYT * RK * 16];  // [qp][kx][c]
    int tid = threadIdx.x;
    int b = blockIdx.y, h = blockIdx.z;
    int qy0 = blockIdx.x * QYT;
    const float* wth = wT + h * RQ * RK;
    for (int i = tid; i < RQ * RK; i += 256) sWt[i] = wth[i];
    for (int i = tid; i < QYT * RK * 16; i += 256) {
        int qp = i / (RK * 16);
        int rem = i - qp * (RK * 16);
        int kx = rem >> 4, vd = rem & 15;
        sT[i] = T[(((size_t)b * RQ + qy0 + qp) * RK + kx) * 128 + h * 16 + vd];
    }
    __syncthreads();

    int qp = tid / RQ;
    int sub = tid - qp * RQ;
    int qx0 = (sub >> 2) << 2;               // qx group of 4
    int c0 = (sub & 3) << 2;                 // c group of 4
    const float* tr = &sT[qp * RK * 16];

    float acc[4][4];
#pragma unroll
    for (int i = 0; i < 4; i++)
#pragma unroll
        for (int j = 0; j < 4; j++) acc[i][j] = 0.f;

#pragma unroll 4
    for (int kx = 0; kx < RK; kx++) {
        float4 wv = *(const float4*)&sWt[kx * RQ + qx0];
        float4 tv = *(const float4*)&tr[kx * 16 + c0];
        acc[0][0] = fmaf(wv.x, tv.x, acc[0][0]);
        acc[0][1] = fmaf(wv.x, tv.y, acc[0][1]);
        acc[0][2] = fmaf(wv.x, tv.z, acc[0][2]);
        acc[0][3] = fmaf(wv.x, tv.w, acc[0][3]);
        acc[1][0] = fmaf(wv.y, tv.x, acc[1][0]);
        acc[1][1] = fmaf(wv.y, tv.y, acc[1][1]);
        acc[1][2] = fmaf(wv.y, tv.z, acc[1][2]);
        acc[1][3] = fmaf(wv.y, tv.w, acc[1][3]);
        acc[2][0] = fmaf(wv.z, tv.x, acc[2][0]);
        acc[2][1] = fmaf(wv.z, tv.y, acc[2][1]);
        acc[2][2] = fmaf(wv.z, tv.z, acc[2][2]);
        acc[2][3] = fmaf(wv.z, tv.w, acc[2][3]);
        acc[3][0] = fmaf(wv.w, tv.x, acc[3][0]);
        acc[3][1] = fmaf(wv.w, tv.y, acc[3][1]);
        acc[3][2] = fmaf(wv.w, tv.z, acc[3][2]);
        acc[3][3] = fmaf(wv.w, tv.w, acc[3][3]);
    }

    int qy = qy0 + qp;
#pragma unroll
    for (int i = 0; i < 4; i++) {
        float g0 = gelu_f(acc[i][0]), g1 = gelu_f(acc[i][1]);
        float g2 = gelu_f(acc[i][2]), g3 = gelu_f(acc[i][3]);
        bf16 h0, l0, h1, l1, h2, l2, h3, l3;
        split_bf(g0, h0, l0); split_bf(g1, h1, l1);
        split_bf(g2, h2, l2); split_bf(g3, h3, l3);
        bf162 ph0 = {h0, h1}, ph1 = {h2, h3};
        bf162 pl0 = {l0, l1}, pl1 = {l2, l3};
        size_t oi = ((size_t)b * RQ * RQ + qy * RQ + qx0 + i) * 128 + h * 16 + c0;
        *(bf162*)&Oh[oi] = ph0;
        *(bf162*)&Oh[oi + 2] = ph1;
        *(bf162*)&Ol[oi] = pl0;
        *(bf162*)&Ol[oi + 2] = pl1;
    }
}

// ---------------------------------------------------------------------------
// Tiled sparse proc attention -> bf16 plane output
// ---------------------------------------------------------------------------
__global__ void __launch_bounds__(256, 1)
k_procatt(const float* __restrict__ V, const float* __restrict__ rv,
          const int* __restrict__ kidx, const int* __restrict__ kcnt,
          bf16* __restrict__ Oh, bf16* __restrict__ Ol) {
    extern __shared__ float psm[];
    float* sV   = psm;
    float* sp   = sV + 256 * 128;
    int*   skl  = (int*)(sp + 64 * KMAX * 8);
    int*   scnt = skl + 64 * KMAX;
    float* sinv = (float*)(scnt + 64);
    __shared__ float sscale[NH];

    int tile = blockIdx.x;
    int b = blockIdx.y;
    int tx = tile & 3, ty = tile >> 2;
    int x0 = tx * 8 - 4, y0 = ty * 8 - 4;
    int tid = threadIdx.x, lane = tid & 31, w = tid >> 5;

    if (tid < NH) sscale[tid] = head_scale(rv[tid]);

    const float4* V4 = (const float4*)V;
    for (int r = w; r < 256; r += 8) {
        int ix = r & 15, iy = r >> 4;
        int kx = x0 + ix, ky = y0 + iy;
        if ((unsigned)kx < 32u && (unsigned)ky < 32u) {
            int k = ky * 32 + kx;
            *(float4*)&sV[r * 128 + lane * 4] = V4[((size_t)b * NLAT + k) * 32 + lane];
        }
    }
    if (tid < 64) {
        int qx = tx * 8 + (tid & 7), qy = ty * 8 + (tid >> 3);
        scnt[tid] = kcnt[qy * 32 + qx];
    }
    for (int i = tid; i < 64 * KMAX; i += 256) {
        int ql = i / KMAX, j = i - ql * KMAX;
        if (j < 64) {
            int qx = tx * 8 + (ql & 7), qy = ty * 8 + (ql >> 3);
            int gk = kidx[(qy * 32 + qx) * 64 + j];
            int kx = gk & 31, ky = gk >> 5;
            skl[i] = (ky - y0) * 16 + (kx - x0);
        }
    }
    __syncthreads();
    for (int i = tid; i < 64 * KMAX; i += 256) {
        int ql = i / KMAX, j = i - ql * KMAX;
        if (j < scnt[ql]) {
            int kl = skl[i];
            int ix = kl & 15, iy = kl >> 4;
            float dx = (float)(ix - 4 - (ql & 7)) * (1.0f / RLAT);
            float dy = (float)(iy - 4 - (ql >> 3)) * (1.0f / RLAT);
            float dist = 0.5f * (dx * dx + dy * dy);
#pragma unroll
            for (int h = 0; h < NH; h++)
                sp[i * 8 + h] = __expf(-sscale[h] * dist);
        }
    }
    __syncthreads();
    for (int hq = tid; hq < 512; hq += 256) {
        int ql = hq >> 3, h = hq & 7;
        int cnt = scnt[ql];
        float sum = 0.f;
        for (int j = 0; j < cnt; j++) sum += sp[(ql * KMAX + j) * 8 + h];
        sinv[ql * 8 + h] = 1.0f / sum;
    }
    __syncthreads();

    int qy_l = w;
    int cg = lane;
    int h = cg >> 2;
    const float4* sV4 = (const float4*)sV;
#pragma unroll
    for (int qx_l = 0; qx_l < 8; qx_l++) {
        int ql = qy_l * 8 + qx_l;
        int cnt = scnt[ql];
        int base = ql * KMAX;
        float4 acc = make_float4(0.f, 0.f, 0.f, 0.f);
        for (int j = 0; j < cnt; j++) {
            float p = sp[(base + j) * 8 + h];
            float4 v = sV4[skl[base + j] * 32 + cg];
            acc.x = fmaf(p, v.x, acc.x);
            acc.y = fmaf(p, v.y, acc.y);
            acc.z = fmaf(p, v.z, acc.z);
            acc.w = fmaf(p, v.w, acc.w);
        }
        float inv = sinv[ql * 8 + h];
        float r0 = gelu_f(acc.x * inv), r1 = gelu_f(acc.y * inv);
        float r2 = gelu_f(acc.z * inv), r3 = gelu_f(acc.w * inv);
        int qglob = (ty * 8 + qy_l) * 32 + tx * 8 + qx_l;
        size_t oi = ((size_t)b * NLAT + qglob) * 128 + cg * 4;
        bf16 h0, l0, h1, l1, h2, l2, h3, l3;
        split_bf(r0, h0, l0); split_bf(r1, h1, l1);
        split_bf(r2, h2, l2); split_bf(r3, h3, l3);
        bf162 ph0 = {h0, h1}, ph1 = {h2, h3};
        bf162 pl0 = {l0, l1}, pl1 = {l2, l3};
        *(bf162*)&Oh[oi] = ph0;
        *(bf162*)&Oh[oi + 2] = ph1;
        *(bf162*)&Ol[oi] = pl0;
        *(bf162*)&Ol[oi + 2] = pl1;
    }
}

// ---------------------------------------------------------------------------
// Launcher
// ---------------------------------------------------------------------------
extern "C" void kernel_launch(void* const* d_in, const int* in_sizes, int n_in,
                              void* d_out, int out_size) {
    const float* x        = (const float*)d_in[0];
    const float* en_w     = (const float*)d_in[1];
    const float* en_b     = (const float*)d_in[2];
    const float* down_r   = (const float*)d_in[3];
    const float* down_w   = (const float*)d_in[4];
    const float* pa_r     = (const float*)d_in[5];
    const float* pa_w     = (const float*)d_in[6];
    const float* mlp1_w   = (const float*)d_in[7];
    const float* mlp1_b   = (const float*)d_in[8];
    const float* mlp2_w   = (const float*)d_in[9];
    const float* mlp2_b   = (const float*)d_in[10];
    const float* res_w    = (const float*)d_in[11];
    const float* res_b    = (const float*)d_in[12];
    const float* up_r     = (const float*)d_in[13];
    const float* up_w     = (const float*)d_in[14];
    const float* de1_w    = (const float*)d_in[15];
    const float* de1_b    = (const float*)d_in[16];
    const float* de2_w    = (const float*)d_in[17];
    const float* de2_b    = (const float*)d_in[18];
    float* out = (float*)d_out;

    float *val, *T, *wdn, *wdnT, *wup, *wupT;
    int *kidx, *kcnt;
    bf16 *bwh, *bwl;
    bf16 *hAh, *hAl, *hBh, *hBl, *pah, *pal, *t1h, *t1l, *huph, *hupl;
    cudaGetSymbolAddress((void**)&val,  g_val);
    cudaGetSymbolAddress((void**)&T,    g_T);
    cudaGetSymbolAddress((void**)&wdn,  g_wdn);
    cudaGetSymbolAddress((void**)&wdnT, g_wdnT);
    cudaGetSymbolAddress((void**)&wup,  g_wup);
    cudaGetSymbolAddress((void**)&wupT, g_wupT);
    cudaGetSymbolAddress((void**)&kidx, g_kidx);
    cudaGetSymbolAddress((void**)&kcnt, g_kcnt);
    cudaGetSymbolAddress((void**)&bwh,  g_bwh);
    cudaGetSymbolAddress((void**)&bwl,  g_bwl);
    cudaGetSymbolAddress((void**)&hAh,  g_hA_h);
    cudaGetSymbolAddress((void**)&hAl,  g_hA_l);
    cudaGetSymbolAddress((void**)&hBh,  g_hB_h);
    cudaGetSymbolAddress((void**)&hBl,  g_hB_l);
    cudaGetSymbolAddress((void**)&pah,  g_pa_h);
    cudaGetSymbolAddress((void**)&pal,  g_pa_l);
    cudaGetSymbolAddress((void**)&t1h,  g_t1_h);
    cudaGetSymbolAddress((void**)&t1l,  g_t1_l);
    cudaGetSymbolAddress((void**)&huph, g_hup_h);
    cudaGetSymbolAddress((void**)&hupl, g_hup_l);

    cudaFuncSetAttribute(k_gemm<1,0,0,0,0>, cudaFuncAttributeMaxDynamicSharedMemorySize, GEMM_SMEM);
    cudaFuncSetAttribute(k_gemm<0,0,0,0,0>, cudaFuncAttributeMaxDynamicSharedMemorySize, GEMM_SMEM);
    cudaFuncSetAttribute(k_gemm<0,0,1,0,1>, cudaFuncAttributeMaxDynamicSharedMemorySize, GEMM_SMEM);
    cudaFuncSetAttribute(k_gemm<0,1,1,0,1>, cudaFuncAttributeMaxDynamicSharedMemorySize, GEMM_SMEM);
    cudaFuncSetAttribute(k_gemm<0,0,1,1,0>, cudaFuncAttributeMaxDynamicSharedMemorySize, GEMM_SMEM);
    cudaFuncSetAttribute(k_procatt, cudaFuncAttributeMaxDynamicSharedMemorySize, PROC_SMEM);

    const int M_IN  = BATCH * NIN;   // 65536
    const int M_LAT = BATCH * NLAT;  // 16384
    const size_t MS = (size_t)HID * HID;

    BWList L;
    L.w[0] = down_w;
    L.w[1] = pa_w;          L.w[2] = pa_w + 16384;  L.w[3] = pa_w + 32768;
    L.w[4] = up_w;
    L.w[5] = mlp1_w;        L.w[6] = mlp1_w + MS;   L.w[7] = mlp1_w + 2 * MS;
    L.w[8] = mlp2_w;        L.w[9] = mlp2_w + MS;   L.w[10] = mlp2_w + 2 * MS;
    L.w[11] = res_w;        L.w[12] = res_w + MS;   L.w[13] = res_w + 2 * MS;
    L.w[14] = de1_w;
    L.bre_mask = 0x1F;

    // merged precompute: weights + knn + factors (+ transposed factors)
    k_pre<<<2000, 256>>>(L, bwh, bwl, kidx, kcnt, down_r, up_r,
                         wdn, wdnT, wup, wupT);

#define BW(i) (bwh + (size_t)(i) * MS), (bwl + (size_t)(i) * MS)
#define NUL4 nullptr, nullptr, nullptr, nullptr

    // ---- down: fused encoder + value GEMM, then separable attention ----
    k_gemm<1,0,0,0,0><<<M_IN / 128, 256, GEMM_SMEM>>>(
        nullptr, nullptr, BW(0), NUL4,
        nullptr, nullptr, x, en_w, en_b, nullptr, nullptr,
        val, nullptr, nullptr);
    {
        dim3 g1(RIN / 8, BATCH, NH);
        k_sepY<RLAT, RIN><<<g1, 256>>>(val, wdn, T);
        dim3 g2(RLAT / 8, BATCH, NH);      // QYT=8 for RQ=32
        k_sepX<RLAT, RIN><<<g2, 256>>>(T, wdnT, hAh, hAl);
    }

    // ---- processor blocks ----
    bf16 *hinh = hAh, *hinl = hAl, *houth = hBh, *houtl = hBl;
    for (int i = 0; i < 3; i++) {
        k_gemm<0,0,0,0,0><<<M_LAT / 128, 256, GEMM_SMEM>>>(
            hinh, hinl, BW(1 + i), NUL4,
            nullptr, nullptr, nullptr, nullptr, nullptr, nullptr, nullptr,
            val, nullptr, nullptr);
        {
            dim3 g(16, BATCH);
            k_procatt<<<g, 256, PROC_SMEM>>>(val, pa_r + i * NH, kidx, kcnt, pah, pal);
        }
        k_gemm<0,0,1,0,1><<<M_LAT / 128, 256, GEMM_SMEM>>>(
            pah, pal, BW(5 + i), NUL4,
            mlp1_b + i * HID, nullptr, nullptr, nullptr, nullptr, nullptr, nullptr,
            nullptr, t1h, t1l);
        k_gemm<0,1,1,0,1><<<M_LAT / 128, 256, GEMM_SMEM>>>(
            t1h, t1l, BW(8 + i), hinh, hinl, BW(11 + i),
            mlp2_b + i * HID, res_b + i * HID,
            nullptr, nullptr, nullptr, nullptr, nullptr,
            nullptr, houth, houtl);
        bf16* t;
        t = hinh; hinh = houth; houth = t;
        t = hinl; hinl = houtl; houtl = t;
    }

    // ---- up: value GEMM + separable attention ----
    k_gemm<0,0,0,0,0><<<M_LAT / 128, 256, GEMM_SMEM>>>(
        hinh, hinl, BW(4), NUL4,
        nullptr, nullptr, nullptr, nullptr, nullptr, nullptr, nullptr,
        val, nullptr, nullptr);
    {
        dim3 g1(RLAT / 8, BATCH, NH);
        k_sepY<RIN, RLAT><<<g1, 256>>>(val, wup, T);
        dim3 g2(RIN / 4, BATCH, NH);       // QYT=4 for RQ=64
        k_sepX<RIN, RLAT><<<g2, 256>>>(T, wupT, huph, hupl);
    }

    // ---- fused decoder ----
    k_gemm<0,0,1,1,0><<<M_IN / 128, 256, GEMM_SMEM>>>(
        huph, hupl, BW(14), NUL4,
        de1_b, nullptr, nullptr, nullptr, nullptr, de2_w, de2_b,
        out, nullptr, nullptr);
#undef BW
#undef NUL4
}

// round 15
// speedup vs baseline: 1.2431x; 1.0409x over previous
#include <cuda_runtime.h>
#include <cuda_bf16.h>
#include <math.h>

// ---------------------------------------------------------------------------
// Problem constants
// ---------------------------------------------------------------------------
#define BATCH   16
#define NH      8
#define HID     128
#define VD      16
#define RIN     64
#define RLAT    32
#define NIN     (RIN*RIN)   // 4096
#define NLAT    (RLAT*RLAT) // 1024
#define PI_F    3.14159265358979323846f

#define NWMAT   15
#define GEMM_SMEM (4*128*136*2)   // 128x128 tiles: 139264 bytes

// procatt tiled smem budget
#define KMAX  40
#define PROC_SMEM (256*128*4 + 64*KMAX*8*4 + 64*KMAX*4 + 64*4 + 64*8*4)  // 225536

typedef __nv_bfloat16 bf16;
typedef __nv_bfloat162 bf162;

// ---------------------------------------------------------------------------
// Scratch buffers
// ---------------------------------------------------------------------------
__device__ float g_val[BATCH*NIN*HID];                       // f32 value proj
__device__ float g_T  [BATCH*2048*HID];                      // sep-attention T
__device__ __align__(16) bf16 g_hA_h[BATCH*NLAT*HID];
__device__ __align__(16) bf16 g_hA_l[BATCH*NLAT*HID];
__device__ __align__(16) bf16 g_hB_h[BATCH*NLAT*HID];
__device__ __align__(16) bf16 g_hB_l[BATCH*NLAT*HID];
__device__ __align__(16) bf16 g_pa_h[BATCH*NLAT*HID];
__device__ __align__(16) bf16 g_pa_l[BATCH*NLAT*HID];
__device__ __align__(16) bf16 g_t1_h[BATCH*NLAT*HID];
__device__ __align__(16) bf16 g_t1_l[BATCH*NLAT*HID];
__device__ __align__(16) bf16 g_hup_h[BATCH*NIN*HID];
__device__ __align__(16) bf16 g_hup_l[BATCH*NIN*HID];
__device__ float g_wdn [NH*RLAT*RIN];    // [h][qy][ky]
__device__ float g_wdnT[NH*RIN*RLAT];    // [h][kx][qx]  (transposed)
__device__ float g_wup [NH*RIN*RLAT];
__device__ float g_wupT[NH*RLAT*RIN];
__device__ int   g_kidx[NLAT*64];
__device__ int   g_kcnt[NLAT];
__device__ __align__(16) bf16 g_bwh[NWMAT*HID*HID];
__device__ __align__(16) bf16 g_bwl[NWMAT*HID*HID];

// ---------------------------------------------------------------------------
// Helpers
// ---------------------------------------------------------------------------
__device__ __forceinline__ float gelu_f(float x) {
    const float c = 0.7978845608028654f;
    float y = c * fmaf(0.044715f * x, x * x, x);
    return x / (1.0f + __expf(-2.0f * y));
}

__device__ __forceinline__ float head_scale(float r) {
    return tanf(0.25f * PI_F * (1.0f - 1e-7f) * (1.0f + sinf(r)));
}

__device__ __forceinline__ void split_bf(float v, bf16& h, bf16& l) {
    h = __float2bfloat16(v);
    l = __float2bfloat16(v - __bfloat162float(h));
}

__device__ __forceinline__ void mma_bf16(float* d,
        unsigned a0, unsigned a1, unsigned a2, unsigned a3,
        unsigned b0, unsigned b1) {
    asm volatile(
        "mma.sync.aligned.m16n8k16.row.col.f32.bf16.bf16.f32 "
        "{%0,%1,%2,%3}, {%4,%5,%6,%7}, {%8,%9}, {%0,%1,%2,%3};"
        : "+f"(d[0]), "+f"(d[1]), "+f"(d[2]), "+f"(d[3])
        : "r"(a0), "r"(a1), "r"(a2), "r"(a3), "r"(b0), "r"(b1));
}

__device__ __forceinline__ void ldsm4(unsigned& r0, unsigned& r1, unsigned& r2,
                                      unsigned& r3, unsigned addr) {
    asm volatile("ldmatrix.sync.aligned.m8n8.x4.shared.b16 {%0,%1,%2,%3}, [%4];"
        : "=r"(r0), "=r"(r1), "=r"(r2), "=r"(r3) : "r"(addr));
}

// ---------------------------------------------------------------------------
// Merged precompute kernel:
//   blocks [0,960)    : weight prep (15 mats x 64 blocks)
//   blocks [960,1984) : kNN neighbor lists (1024 queries)
//   blocks [1984,2000): separable factors + transposed copies
// ---------------------------------------------------------------------------
struct BWList { const float* w[NWMAT]; unsigned bre_mask; };

__device__ void factor_body(int h, const float* rv, float* w, float* wt,
                            int RQ, int RK) {
    int tid = threadIdx.x, lane = tid & 31, wp = tid >> 5;
    int KP = RK >> 5;
    float s = head_scale(rv[h]);
    for (int q = wp; q < RQ; q += 8) {
        float qp = (float)q / (float)RQ;
        float d[2];
        float mind = 1e30f;
        for (int i = 0; i < KP; i++) {
            int k = lane + i * 32;
            float dd = qp - (float)k / (float)RK;
            d[i] = 0.5f * dd * dd;
            mind = fminf(mind, d[i]);
        }
        for (int o = 16; o > 0; o >>= 1)
            mind = fminf(mind, __shfl_xor_sync(0xffffffffu, mind, o));
        float p[2], sum = 0.f;
        for (int i = 0; i < KP; i++) { p[i] = __expf(s * (mind - d[i])); sum += p[i]; }
        for (int o = 16; o > 0; o >>= 1)
            sum += __shfl_xor_sync(0xffffffffu, sum, o);
        float inv = 1.0f / sum;
        for (int i = 0; i < KP; i++) {
            int k = lane + i * 32;
            float val = p[i] * inv;
            w [(h * RQ + q) * RK + k] = val;
            wt[(h * RK + k) * RQ + q] = val;
        }
    }
}

__global__ void k_pre(BWList L, bf16* __restrict__ outh, bf16* __restrict__ outl,
                      int* __restrict__ kidx, int* __restrict__ kcnt,
                      const float* __restrict__ down_r, const float* __restrict__ up_r,
                      float* __restrict__ wdn, float* __restrict__ wdnT,
                      float* __restrict__ wup, float* __restrict__ wupT) {
    int bid = blockIdx.x;
    int tid = threadIdx.x;
    if (bid < 960) {
        int mat = bid >> 6;
        const float* w = L.w[mat];
        int bre = (L.bre_mask >> mat) & 1;
        int idx = (bid & 63) * 256 + tid;
        int k = idx >> 7, n = idx & 127;
        float v;
        if (bre) {
            int h = n >> 4, vd = n & 15;
            v = w[((size_t)h * HID + k) * VD + vd];
        } else {
            v = w[k * HID + n];
        }
        bf16 hi, lo;
        split_bf(v, hi, lo);
        size_t o = (size_t)mat * HID * HID + n * HID + k;
        outh[o] = hi;
        outl[o] = lo;
        return;
    }
    if (bid < 1984) {
        int q = bid - 960;
        int lane = tid & 31, w = tid >> 5;
        int qx = q & (RLAT - 1), qy = q >> 5;
        int dv[4];
#pragma unroll
        for (int i = 0; i < 4; i++) {
            int k = tid * 4 + i;
            int kx = k & (RLAT - 1), ky = k >> 5;
            int dx = qx - kx, dy = qy - ky;
            dv[i] = dx * dx + dy * dy;
        }
        __shared__ int scount;
        int lo = 0, hi = 2 * 31 * 31;
        while (lo < hi) {
            int mid = (lo + hi) >> 1;
            if (tid == 0) scount = 0;
            __syncthreads();
            int c = 0;
#pragma unroll
            for (int i = 0; i < 4; i++) c += (dv[i] <= mid);
#pragma unroll
            for (int o = 16; o > 0; o >>= 1) c += __shfl_down_sync(0xffffffffu, c, o);
            if (lane == 0) atomicAdd(&scount, c);
            __syncthreads();
            if (scount >= 21) hi = mid; else lo = mid + 1;
            __syncthreads();
        }
        int sel[4], cnt_t = 0;
#pragma unroll
        for (int i = 0; i < 4; i++) { sel[i] = (dv[i] <= lo); cnt_t += sel[i]; }
        int incl = cnt_t;
#pragma unroll
        for (int o = 1; o < 32; o <<= 1) {
            int v = __shfl_up_sync(0xffffffffu, incl, o);
            if (lane >= o) incl += v;
        }
        __shared__ int wsum[8], wbase[8];
        if (lane == 31) wsum[w] = incl;
        __syncthreads();
        if (tid == 0) {
            int b = 0;
            for (int i = 0; i < 8; i++) { wbase[i] = b; b += wsum[i]; }
            kcnt[q] = b;
        }
        __syncthreads();
        int pos = wbase[w] + incl - cnt_t;
#pragma unroll
        for (int i = 0; i < 4; i++) {
            if (sel[i] && pos < 64) kidx[q * 64 + pos] = tid * 4 + i;
            pos += sel[i];
        }
        return;
    }
    int j = bid - 1984;
    if (j < 8) factor_body(j, down_r, wdn, wdnT, RLAT, RIN);
    else       factor_body(j - 8, up_r, wup, wupT, RIN, RLAT);
}

// ---------------------------------------------------------------------------
// Tensor-core GEMM BM=128, 256 threads (bf16x3 split), ldmatrix loads.
// Used for the two M=65536 GEMMs (encoder-fused value GEMM + decoder).
// ---------------------------------------------------------------------------
template <int AENC, int DUAL, int DOGELU, int DEC, int OBF>
__global__ void __launch_bounds__(256, 1)
k_gemm(const bf16* __restrict__ Ah, const bf16* __restrict__ Al,
       const bf16* __restrict__ Bh, const bf16* __restrict__ Bl,
       const bf16* __restrict__ A2h, const bf16* __restrict__ A2l,
       const bf16* __restrict__ B2h, const bf16* __restrict__ B2l,
       const float* __restrict__ bias, const float* __restrict__ bias2,
       const float* __restrict__ x, const float* __restrict__ enw,
       const float* __restrict__ enb,
       const float* __restrict__ d2w, const float* __restrict__ d2b,
       float* __restrict__ Cf, bf16* __restrict__ Ch, bf16* __restrict__ Cl) {
    extern __shared__ __align__(16) char smem_raw[];
    bf16* sAh = (bf16*)smem_raw;
    bf16* sAl = sAh + 128 * 136;
    bf16* sBh = sAl + 128 * 136;
    bf16* sBl = sBh + 128 * 136;

    int tid = threadIdx.x;
    int wid = tid >> 5, lane = tid & 31;
    int g = lane >> 2, s = lane & 3;
    size_t rbase = (size_t)blockIdx.x * 128;

    unsigned sAh_b = (unsigned)__cvta_generic_to_shared(sAh);
    unsigned sAl_b = (unsigned)__cvta_generic_to_shared(sAl);
    unsigned sBh_b = (unsigned)__cvta_generic_to_shared(sBh);
    unsigned sBl_b = (unsigned)__cvta_generic_to_shared(sBl);
    int arowf = wid * 16 + (lane & 15);
    unsigned aoff = (unsigned)((arowf * 136 + ((lane >> 4) << 3)) * 2);
    int brow = (lane & 7) + ((lane >> 4) << 3);
    unsigned boff = (unsigned)((brow * 136 + (((lane >> 3) & 1) << 3)) * 2);

    float acc[16][4];
#pragma unroll
    for (int j = 0; j < 16; j++)
#pragma unroll
        for (int e = 0; e < 4; e++) acc[j][e] = 0.f;

    const int NPASS = DUAL ? 2 : 1;
#pragma unroll
    for (int pass = 0; pass < NPASS; pass++) {
        const bf16* Aph = (DUAL && pass) ? A2h : Ah;
        const bf16* Apl = (DUAL && pass) ? A2l : Al;
        const bf16* Bph = (DUAL && pass) ? B2h : Bh;
        const bf16* Bpl = (DUAL && pass) ? B2l : Bl;

        if (AENC && pass == 0) {
            int row = tid >> 1, half = tid & 1;
            size_t grow = rbase + row;
            float x0 = x[grow * 3 + 0], x1 = x[grow * 3 + 1], x2 = x[grow * 3 + 2];
#pragma unroll 8
            for (int c = 0; c < 64; c++) {
                int cc = half * 64 + c;
                float a = fmaf(x0, enw[cc],
                          fmaf(x1, enw[HID + cc],
                          fmaf(x2, enw[2 * HID + cc], enb[cc])));
                a = gelu_f(a);
                bf16 h, l;
                split_bf(a, h, l);
                sAh[row * 136 + cc] = h;
                sAl[row * 136 + cc] = l;
            }
        } else {
            const uint4* Ah4 = (const uint4*)(Aph + rbase * 128);
            const uint4* Al4 = (const uint4*)(Apl + rbase * 128);
#pragma unroll
            for (int i = 0; i < 8; i++) {
                int idx8 = tid + i * 256;
                int row = idx8 >> 4, k8 = (idx8 & 15) << 3;
                *(uint4*)&sAh[row * 136 + k8] = Ah4[idx8];
                *(uint4*)&sAl[row * 136 + k8] = Al4[idx8];
            }
        }
        {
            const uint4* Bh4 = (const uint4*)Bph;
            const uint4* Bl4 = (const uint4*)Bpl;
#pragma unroll
            for (int i = 0; i < 8; i++) {
                int idx8 = tid + i * 256;
                int n = idx8 >> 4, k8 = (idx8 & 15) << 3;
                *(uint4*)&sBh[n * 136 + k8] = Bh4[idx8];
                *(uint4*)&sBl[n * 136 + k8] = Bl4[idx8];
            }
        }
        __syncthreads();

#pragma unroll
        for (int ks = 0; ks < 8; ks++) {
            unsigned kb = (unsigned)(ks * 16 * 2);
            unsigned ah0, ah1, ah2, ah3, al0, al1, al2, al3;
            ldsm4(ah0, ah1, ah2, ah3, sAh_b + aoff + kb);
            ldsm4(al0, al1, al2, al3, sAl_b + aoff + kb);
#pragma unroll
            for (int j2 = 0; j2 < 8; j2++) {
                unsigned bofs = boff + (unsigned)(j2 * 16 * 136 * 2) + kb;
                unsigned bh0, bh1, bh2, bh3, bl0, bl1, bl2, bl3;
                ldsm4(bh0, bh1, bh2, bh3, sBh_b + bofs);
                ldsm4(bl0, bl1, bl2, bl3, sBl_b + bofs);
                mma_bf16(acc[2 * j2],     ah0, ah1, ah2, ah3, bh0, bh1);
                mma_bf16(acc[2 * j2],     ah0, ah1, ah2, ah3, bl0, bl1);
                mma_bf16(acc[2 * j2],     al0, al1, al2, al3, bh0, bh1);
                mma_bf16(acc[2 * j2 + 1], ah0, ah1, ah2, ah3, bh2, bh3);
                mma_bf16(acc[2 * j2 + 1], ah0, ah1, ah2, ah3, bl2, bl3);
                mma_bf16(acc[2 * j2 + 1], al0, al1, al2, al3, bh2, bh3);
            }
        }
        __syncthreads();
    }

    int r0 = wid * 16 + g;
    if (DEC) {
        float p0 = 0.f, p1 = 0.f;
#pragma unroll
        for (int j = 0; j < 16; j++) {
            int c = j * 8 + 2 * s;
            float b0 = bias ? bias[c] : 0.f;
            float b1 = bias ? bias[c + 1] : 0.f;
            float w0 = d2w[c], w1 = d2w[c + 1];
            float v0 = gelu_f(acc[j][0] + b0), v1 = gelu_f(acc[j][1] + b1);
            float v2 = gelu_f(acc[j][2] + b0), v3 = gelu_f(acc[j][3] + b1);
            p0 = fmaf(v0, w0, fmaf(v1, w1, p0));
            p1 = fmaf(v2, w0, fmaf(v3, w1, p1));
        }
        p0 += __shfl_xor_sync(0xffffffffu, p0, 1);
        p0 += __shfl_xor_sync(0xffffffffu, p0, 2);
        p1 += __shfl_xor_sync(0xffffffffu, p1, 1);
        p1 += __shfl_xor_sync(0xffffffffu, p1, 2);
        if (s == 0) {
            float db = d2b[0];
            Cf[rbase + r0] = p0 + db;
            Cf[rbase + r0 + 8] = p1 + db;
        }
    } else {
#pragma unroll
        for (int j = 0; j < 16; j++) {
            int c = j * 8 + 2 * s;
            float b0 = 0.f, b1 = 0.f;
            if (bias) {
                float2 bb = *(const float2*)&bias[c];
                b0 += bb.x; b1 += bb.y;
            }
            if (DUAL && bias2) {
                float2 bb = *(const float2*)&bias2[c];
                b0 += bb.x; b1 += bb.y;
            }
            float v0 = acc[j][0] + b0, v1 = acc[j][1] + b1;
            float v2 = acc[j][2] + b0, v3 = acc[j][3] + b1;
            if (DOGELU) {
                v0 = gelu_f(v0); v1 = gelu_f(v1);
                v2 = gelu_f(v2); v3 = gelu_f(v3);
            }
            if (OBF) {
                bf16 h0, l0, h1, l1, h2, l2, h3, l3;
                split_bf(v0, h0, l0); split_bf(v1, h1, l1);
                split_bf(v2, h2, l2); split_bf(v3, h3, l3);
                bf162 ph0 = {h0, h1}, ph1 = {h2, h3};
                bf162 pl0 = {l0, l1}, pl1 = {l2, l3};
                *(bf162*)&Ch[(rbase + r0) * 128 + c] = ph0;
                *(bf162*)&Cl[(rbase + r0) * 128 + c] = pl0;
                *(bf162*)&Ch[(rbase + r0 + 8) * 128 + c] = ph1;
                *(bf162*)&Cl[(rbase + r0 + 8) * 128 + c] = pl1;
            } else {
                float2 u0 = {v0, v1}, u1 = {v2, v3};
                *(float2*)&Cf[(rbase + r0) * 128 + c] = u0;
                *(float2*)&Cf[(rbase + r0 + 8) * 128 + c] = u1;
            }
        }
    }
}

// ---------------------------------------------------------------------------
// Tensor-core GEMM BM=128, 512 threads = 16 warps for latent (M=16384) GEMMs.
// Warp = 16 rows x 64 cols (wm in 0..7 row-groups, wn in 0..1 col halves).
// Same 128x128 tiles & bit-identical per-output mma order as k_gemm; doubles
// warps/SM (8 -> 16) to hide ldsm->mma latency (r8 profile: occ 12.5%).
// ---------------------------------------------------------------------------
template <int DUAL, int DOGELU, int OBF>
__global__ void __launch_bounds__(512, 1)
k_gemm512(const bf16* __restrict__ Ah, const bf16* __restrict__ Al,
          const bf16* __restrict__ Bh, const bf16* __restrict__ Bl,
          const bf16* __restrict__ A2h, const bf16* __restrict__ A2l,
          const bf16* __restrict__ B2h, const bf16* __restrict__ B2l,
          const float* __restrict__ bias, const float* __restrict__ bias2,
          float* __restrict__ Cf, bf16* __restrict__ Ch, bf16* __restrict__ Cl) {
    extern __shared__ __align__(16) char smem_raw[];
    bf16* sAh = (bf16*)smem_raw;
    bf16* sAl = sAh + 128 * 136;
    bf16* sBh = sAl + 128 * 136;
    bf16* sBl = sBh + 128 * 136;

    int tid = threadIdx.x;
    int wid = tid >> 5, lane = tid & 31;
    int wm = wid & 7, wn = wid >> 3;
    int g = lane >> 2, s = lane & 3;
    size_t rbase = (size_t)blockIdx.x * 128;

    unsigned sAh_b = (unsigned)__cvta_generic_to_shared(sAh);
    unsigned sAl_b = (unsigned)__cvta_generic_to_shared(sAl);
    unsigned sBh_b = (unsigned)__cvta_generic_to_shared(sBh);
    unsigned sBl_b = (unsigned)__cvta_generic_to_shared(sBl);
    int arowf = wm * 16 + (lane & 15);
    unsigned aoff = (unsigned)((arowf * 136 + ((lane >> 4) << 3)) * 2);
    int brow = wn * 64 + (lane & 7) + ((lane >> 4) << 3);
    unsigned boff = (unsigned)((brow * 136 + (((lane >> 3) & 1) << 3)) * 2);

    float acc[8][4];
#pragma unroll
    for (int j = 0; j < 8; j++)
#pragma unroll
        for (int e = 0; e < 4; e++) acc[j][e] = 0.f;

    const int NPASS = DUAL ? 2 : 1;
#pragma unroll
    for (int pass = 0; pass < NPASS; pass++) {
        const bf16* Aph = (DUAL && pass) ? A2h : Ah;
        const bf16* Apl = (DUAL && pass) ? A2l : Al;
        const bf16* Bph = (DUAL && pass) ? B2h : Bh;
        const bf16* Bpl = (DUAL && pass) ? B2l : Bl;
        {
            const uint4* Ah4 = (const uint4*)(Aph + rbase * 128);
            const uint4* Al4 = (const uint4*)(Apl + rbase * 128);
#pragma unroll
            for (int i = 0; i < 4; i++) {
                int idx8 = tid + i * 512;
                int row = idx8 >> 4, k8 = (idx8 & 15) << 3;
                *(uint4*)&sAh[row * 136 + k8] = Ah4[idx8];
                *(uint4*)&sAl[row * 136 + k8] = Al4[idx8];
            }
            const uint4* Bh4 = (const uint4*)Bph;
            const uint4* Bl4 = (const uint4*)Bpl;
#pragma unroll
            for (int i = 0; i < 4; i++) {
                int idx8 = tid + i * 512;
                int n = idx8 >> 4, k8 = (idx8 & 15) << 3;
                *(uint4*)&sBh[n * 136 + k8] = Bh4[idx8];
                *(uint4*)&sBl[n * 136 + k8] = Bl4[idx8];
            }
        }
        __syncthreads();

#pragma unroll
        for (int ks = 0; ks < 8; ks++) {
            unsigned kb = (unsigned)(ks * 16 * 2);
            unsigned ah0, ah1, ah2, ah3, al0, al1, al2, al3;
            ldsm4(ah0, ah1, ah2, ah3, sAh_b + aoff + kb);
            ldsm4(al0, al1, al2, al3, sAl_b + aoff + kb);
#pragma unroll
            for (int j2 = 0; j2 < 4; j2++) {
                unsigned bofs = boff + (unsigned)(j2 * 16 * 136 * 2) + kb;
                unsigned bh0, bh1, bh2, bh3, bl0, bl1, bl2, bl3;
                ldsm4(bh0, bh1, bh2, bh3, sBh_b + bofs);
                ldsm4(bl0, bl1, bl2, bl3, sBl_b + bofs);
                mma_bf16(acc[2 * j2],     ah0, ah1, ah2, ah3, bh0, bh1);
                mma_bf16(acc[2 * j2],     ah0, ah1, ah2, ah3, bl0, bl1);
                mma_bf16(acc[2 * j2],     al0, al1, al2, al3, bh0, bh1);
                mma_bf16(acc[2 * j2 + 1], ah0, ah1, ah2, ah3, bh2, bh3);
                mma_bf16(acc[2 * j2 + 1], ah0, ah1, ah2, ah3, bl2, bl3);
                mma_bf16(acc[2 * j2 + 1], al0, al1, al2, al3, bh2, bh3);
            }
        }
        __syncthreads();
    }

    int r0 = wm * 16 + g;
#pragma unroll
    for (int j = 0; j < 8; j++) {
        int c = wn * 64 + j * 8 + 2 * s;
        float b0 = 0.f, b1 = 0.f;
        if (bias) {
            float2 bb = *(const float2*)&bias[c];
            b0 += bb.x; b1 += bb.y;
        }
        if (DUAL && bias2) {
            float2 bb = *(const float2*)&bias2[c];
            b0 += bb.x; b1 += bb.y;
        }
        float v0 = acc[j][0] + b0, v1 = acc[j][1] + b1;
        float v2 = acc[j][2] + b0, v3 = acc[j][3] + b1;
        if (DOGELU) {
            v0 = gelu_f(v0); v1 = gelu_f(v1);
            v2 = gelu_f(v2); v3 = gelu_f(v3);
        }
        if (OBF) {
            bf16 h0, l0, h1, l1, h2, l2, h3, l3;
            split_bf(v0, h0, l0); split_bf(v1, h1, l1);
            split_bf(v2, h2, l2); split_bf(v3, h3, l3);
            bf162 ph0 = {h0, h1}, ph1 = {h2, h3};
            bf162 pl0 = {l0, l1}, pl1 = {l2, l3};
            *(bf162*)&Ch[(rbase + r0) * 128 + c] = ph0;
            *(bf162*)&Cl[(rbase + r0) * 128 + c] = pl0;
            *(bf162*)&Ch[(rbase + r0 + 8) * 128 + c] = ph1;
            *(bf162*)&Cl[(rbase + r0 + 8) * 128 + c] = pl1;
        } else {
            float2 u0 = {v0, v1}, u1 = {v2, v3};
            *(float2*)&Cf[(rbase + r0) * 128 + c] = u0;
            *(float2*)&Cf[(rbase + r0 + 8) * 128 + c] = u1;
        }
    }
}

// ---------------------------------------------------------------------------
// Separable attention step 1 (contract ky)
// ---------------------------------------------------------------------------
template <int RQ, int RK>
__global__ void k_sepY(const float* __restrict__ V, const float* __restrict__ w,
                       float* __restrict__ T) {
    constexpr int QPT = RQ / 8;
    __shared__ float sW[RQ * RK];
    __shared__ float sV[RK * 128];
    int tid = threadIdx.x;
    int kxc = blockIdx.x;
    int b = blockIdx.y, h = blockIdx.z;
    const float* wh = w + h * RQ * RK;
    for (int i = tid; i < RQ * RK; i += 256) sW[i] = wh[i];
    for (int i = tid; i < RK * 128; i += 256) {
        int ky = i >> 7, col = i & 127;
        int kx = kxc * 8 + (col >> 4), vd = col & 15;
        sV[i] = V[(((size_t)b * RK + ky) * RK + kx) * 128 + h * 16 + vd];
    }
    __syncthreads();
    int qy0 = (tid >> 5) * QPT, col0 = (tid & 31) * 4;
    float acc[QPT][4];
#pragma unroll
    for (int i = 0; i < QPT; i++)
#pragma unroll
        for (int j = 0; j < 4; j++) acc[i][j] = 0.f;
#pragma unroll 4
    for (int ky = 0; ky < RK; ky++) {
        float4 v = *reinterpret_cast<const float4*>(&sV[ky * 128 + col0]);
#pragma unroll
        for (int i = 0; i < QPT; i++) {
            float a = sW[(qy0 + i) * RK + ky];
            acc[i][0] = fmaf(a, v.x, acc[i][0]);
            acc[i][1] = fmaf(a, v.y, acc[i][1]);
            acc[i][2] = fmaf(a, v.z, acc[i][2]);
            acc[i][3] = fmaf(a, v.w, acc[i][3]);
        }
    }
    int kx = kxc * 8 + (col0 >> 4), vd0 = col0 & 15;
#pragma unroll
    for (int i = 0; i < QPT; i++) {
        float4 r = make_float4(acc[i][0], acc[i][1], acc[i][2], acc[i][3]);
        *reinterpret_cast<float4*>(
            &T[(((size_t)b * RQ + qy0 + i) * RK + kx) * 128 + h * 16 + vd0]) = r;
    }
}

// ---------------------------------------------------------------------------
// Separable attention step 2 (contract kx), 4x4 register tile, bf16 output
// ---------------------------------------------------------------------------
template <int RQ, int RK>
__global__ void __launch_bounds__(256, 1)
k_sepX(const float* __restrict__ T, const float* __restrict__ wT,
       bf16* __restrict__ Oh, bf16* __restrict__ Ol) {
    constexpr int QYT = 256 / RQ;
    __shared__ __align__(16) float sWt[RK * RQ];       // [kx][qx]
    __shared__ __align__(16) float sT[QYT * RK * 16];  // [qp][kx][c]
    int tid = threadIdx.x;
    int b = blockIdx.y, h = blockIdx.z;
    int qy0 = blockIdx.x * QYT;
    const float* wth = wT + h * RQ * RK;
    for (int i = tid; i < RQ * RK; i += 256) sWt[i] = wth[i];
    for (int i = tid; i < QYT * RK * 16; i += 256) {
        int qp = i / (RK * 16);
        int rem = i - qp * (RK * 16);
        int kx = rem >> 4, vd = rem & 15;
        sT[i] = T[(((size_t)b * RQ + qy0 + qp) * RK + kx) * 128 + h * 16 + vd];
    }
    __syncthreads();

    int qp = tid / RQ;
    int sub = tid - qp * RQ;
    int qx0 = (sub >> 2) << 2;
    int c0 = (sub & 3) << 2;
    const float* tr = &sT[qp * RK * 16];

    float acc[4][4];
#pragma unroll
    for (int i = 0; i < 4; i++)
#pragma unroll
        for (int j = 0; j < 4; j++) acc[i][j] = 0.f;

#pragma unroll 4
    for (int kx = 0; kx < RK; kx++) {
        float4 wv = *(const float4*)&sWt[kx * RQ + qx0];
        float4 tv = *(const float4*)&tr[kx * 16 + c0];
        acc[0][0] = fmaf(wv.x, tv.x, acc[0][0]);
        acc[0][1] = fmaf(wv.x, tv.y, acc[0][1]);
        acc[0][2] = fmaf(wv.x, tv.z, acc[0][2]);
        acc[0][3] = fmaf(wv.x, tv.w, acc[0][3]);
        acc[1][0] = fmaf(wv.y, tv.x, acc[1][0]);
        acc[1][1] = fmaf(wv.y, tv.y, acc[1][1]);
        acc[1][2] = fmaf(wv.y, tv.z, acc[1][2]);
        acc[1][3] = fmaf(wv.y, tv.w, acc[1][3]);
        acc[2][0] = fmaf(wv.z, tv.x, acc[2][0]);
        acc[2][1] = fmaf(wv.z, tv.y, acc[2][1]);
        acc[2][2] = fmaf(wv.z, tv.z, acc[2][2]);
        acc[2][3] = fmaf(wv.z, tv.w, acc[2][3]);
        acc[3][0] = fmaf(wv.w, tv.x, acc[3][0]);
        acc[3][1] = fmaf(wv.w, tv.y, acc[3][1]);
        acc[3][2] = fmaf(wv.w, tv.z, acc[3][2]);
        acc[3][3] = fmaf(wv.w, tv.w, acc[3][3]);
    }

    int qy = qy0 + qp;
#pragma unroll
    for (int i = 0; i < 4; i++) {
        float g0 = gelu_f(acc[i][0]), g1 = gelu_f(acc[i][1]);
        float g2 = gelu_f(acc[i][2]), g3 = gelu_f(acc[i][3]);
        bf16 h0, l0, h1, l1, h2, l2, h3, l3;
        split_bf(g0, h0, l0); split_bf(g1, h1, l1);
        split_bf(g2, h2, l2); split_bf(g3, h3, l3);
        bf162 ph0 = {h0, h1}, ph1 = {h2, h3};
        bf162 pl0 = {l0, l1}, pl1 = {l2, l3};
        size_t oi = ((size_t)b * RQ * RQ + qy * RQ + qx0 + i) * 128 + h * 16 + c0;
        *(bf162*)&Oh[oi] = ph0;
        *(bf162*)&Oh[oi + 2] = ph1;
        *(bf162*)&Ol[oi] = pl0;
        *(bf162*)&Ol[oi + 2] = pl1;
    }
}

// ---------------------------------------------------------------------------
// Tiled sparse proc attention -> bf16 plane output
// ---------------------------------------------------------------------------
__global__ void __launch_bounds__(256, 1)
k_procatt(const float* __restrict__ V, const float* __restrict__ rv,
          const int* __restrict__ kidx, const int* __restrict__ kcnt,
          bf16* __restrict__ Oh, bf16* __restrict__ Ol) {
    extern __shared__ float psm[];
    float* sV   = psm;
    float* sp   = sV + 256 * 128;
    int*   skl  = (int*)(sp + 64 * KMAX * 8);
    int*   scnt = skl + 64 * KMAX;
    float* sinv = (float*)(scnt + 64);
    __shared__ float sscale[NH];

    int tile = blockIdx.x;
    int b = blockIdx.y;
    int tx = tile & 3, ty = tile >> 2;
    int x0 = tx * 8 - 4, y0 = ty * 8 - 4;
    int tid = threadIdx.x, lane = tid & 31, w = tid >> 5;

    if (tid < NH) sscale[tid] = head_scale(rv[tid]);

    const float4* V4 = (const float4*)V;
    for (int r = w; r < 256; r += 8) {
        int ix = r & 15, iy = r >> 4;
        int kx = x0 + ix, ky = y0 + iy;
        if ((unsigned)kx < 32u && (unsigned)ky < 32u) {
            int k = ky * 32 + kx;
            *(float4*)&sV[r * 128 + lane * 4] = V4[((size_t)b * NLAT + k) * 32 + lane];
        }
    }
    if (tid < 64) {
        int qx = tx * 8 + (tid & 7), qy = ty * 8 + (tid >> 3);
        scnt[tid] = kcnt[qy * 32 + qx];
    }
    for (int i = tid; i < 64 * KMAX; i += 256) {
        int ql = i / KMAX, j = i - ql * KMAX;
        if (j < 64) {
            int qx = tx * 8 + (ql & 7), qy = ty * 8 + (ql >> 3);
            int gk = kidx[(qy * 32 + qx) * 64 + j];
            int kx = gk & 31, ky = gk >> 5;
            skl[i] = (ky - y0) * 16 + (kx - x0);
        }
    }
    __syncthreads();
    for (int i = tid; i < 64 * KMAX; i += 256) {
        int ql = i / KMAX, j = i - ql * KMAX;
        if (j < scnt[ql]) {
            int kl = skl[i];
            int ix = kl & 15, iy = kl >> 4;
            float dx = (float)(ix - 4 - (ql & 7)) * (1.0f / RLAT);
            float dy = (float)(iy - 4 - (ql >> 3)) * (1.0f / RLAT);
            float dist = 0.5f * (dx * dx + dy * dy);
#pragma unroll
            for (int h = 0; h < NH; h++)
                sp[i * 8 + h] = __expf(-sscale[h] * dist);
        }
    }
    __syncthreads();
    for (int hq = tid; hq < 512; hq += 256) {
        int ql = hq >> 3, h = hq & 7;
        int cnt = scnt[ql];
        float sum = 0.f;
        for (int j = 0; j < cnt; j++) sum += sp[(ql * KMAX + j) * 8 + h];
        sinv[ql * 8 + h] = 1.0f / sum;
    }
    __syncthreads();

    int qy_l = w;
    int cg = lane;
    int h = cg >> 2;
    const float4* sV4 = (const float4*)sV;
#pragma unroll
    for (int qx_l = 0; qx_l < 8; qx_l++) {
        int ql = qy_l * 8 + qx_l;
        int cnt = scnt[ql];
        int base = ql * KMAX;
        float4 acc = make_float4(0.f, 0.f, 0.f, 0.f);
        for (int j = 0; j < cnt; j++) {
            float p = sp[(base + j) * 8 + h];
            float4 v = sV4[skl[base + j] * 32 + cg];
            acc.x = fmaf(p, v.x, acc.x);
            acc.y = fmaf(p, v.y, acc.y);
            acc.z = fmaf(p, v.z, acc.z);
            acc.w = fmaf(p, v.w, acc.w);
        }
        float inv = sinv[ql * 8 + h];
        float r0 = gelu_f(acc.x * inv), r1 = gelu_f(acc.y * inv);
        float r2 = gelu_f(acc.z * inv), r3 = gelu_f(acc.w * inv);
        int qglob = (ty * 8 + qy_l) * 32 + tx * 8 + qx_l;
        size_t oi = ((size_t)b * NLAT + qglob) * 128 + cg * 4;
        bf16 h0, l0, h1, l1, h2, l2, h3, l3;
        split_bf(r0, h0, l0); split_bf(r1, h1, l1);
        split_bf(r2, h2, l2); split_bf(r3, h3, l3);
        bf162 ph0 = {h0, h1}, ph1 = {h2, h3};
        bf162 pl0 = {l0, l1}, pl1 = {l2, l3};
        *(bf162*)&Oh[oi] = ph0;
        *(bf162*)&Oh[oi + 2] = ph1;
        *(bf162*)&Ol[oi] = pl0;
        *(bf162*)&Ol[oi + 2] = pl1;
    }
}

// ---------------------------------------------------------------------------
// Launcher
// ---------------------------------------------------------------------------
extern "C" void kernel_launch(void* const* d_in, const int* in_sizes, int n_in,
                              void* d_out, int out_size) {
    const float* x        = (const float*)d_in[0];
    const float* en_w     = (const float*)d_in[1];
    const float* en_b     = (const float*)d_in[2];
    const float* down_r   = (const float*)d_in[3];
    const float* down_w   = (const float*)d_in[4];
    const float* pa_r     = (const float*)d_in[5];
    const float* pa_w     = (const float*)d_in[6];
    const float* mlp1_w   = (const float*)d_in[7];
    const float* mlp1_b   = (const float*)d_in[8];
    const float* mlp2_w   = (const float*)d_in[9];
    const float* mlp2_b   = (const float*)d_in[10];
    const float* res_w    = (const float*)d_in[11];
    const float* res_b    = (const float*)d_in[12];
    const float* up_r     = (const float*)d_in[13];
    const float* up_w     = (const float*)d_in[14];
    const float* de1_w    = (const float*)d_in[15];
    const float* de1_b    = (const float*)d_in[16];
    const float* de2_w    = (const float*)d_in[17];
    const float* de2_b    = (const float*)d_in[18];
    float* out = (float*)d_out;

    float *val, *T, *wdn, *wdnT, *wup, *wupT;
    int *kidx, *kcnt;
    bf16 *bwh, *bwl;
    bf16 *hAh, *hAl, *hBh, *hBl, *pah, *pal, *t1h, *t1l, *huph, *hupl;
    cudaGetSymbolAddress((void**)&val,  g_val);
    cudaGetSymbolAddress((void**)&T,    g_T);
    cudaGetSymbolAddress((void**)&wdn,  g_wdn);
    cudaGetSymbolAddress((void**)&wdnT, g_wdnT);
    cudaGetSymbolAddress((void**)&wup,  g_wup);
    cudaGetSymbolAddress((void**)&wupT, g_wupT);
    cudaGetSymbolAddress((void**)&kidx, g_kidx);
    cudaGetSymbolAddress((void**)&kcnt, g_kcnt);
    cudaGetSymbolAddress((void**)&bwh,  g_bwh);
    cudaGetSymbolAddress((void**)&bwl,  g_bwl);
    cudaGetSymbolAddress((void**)&hAh,  g_hA_h);
    cudaGetSymbolAddress((void**)&hAl,  g_hA_l);
    cudaGetSymbolAddress((void**)&hBh,  g_hB_h);
    cudaGetSymbolAddress((void**)&hBl,  g_hB_l);
    cudaGetSymbolAddress((void**)&pah,  g_pa_h);
    cudaGetSymbolAddress((void**)&pal,  g_pa_l);
    cudaGetSymbolAddress((void**)&t1h,  g_t1_h);
    cudaGetSymbolAddress((void**)&t1l,  g_t1_l);
    cudaGetSymbolAddress((void**)&huph, g_hup_h);
    cudaGetSymbolAddress((void**)&hupl, g_hup_l);

    cudaFuncSetAttribute(k_gemm<1,0,0,0,0>, cudaFuncAttributeMaxDynamicSharedMemorySize, GEMM_SMEM);
    cudaFuncSetAttribute(k_gemm<0,0,1,1,0>, cudaFuncAttributeMaxDynamicSharedMemorySize, GEMM_SMEM);
    cudaFuncSetAttribute(k_gemm512<0,0,0>, cudaFuncAttributeMaxDynamicSharedMemorySize, GEMM_SMEM);
    cudaFuncSetAttribute(k_gemm512<0,1,1>, cudaFuncAttributeMaxDynamicSharedMemorySize, GEMM_SMEM);
    cudaFuncSetAttribute(k_gemm512<1,1,1>, cudaFuncAttributeMaxDynamicSharedMemorySize, GEMM_SMEM);
    cudaFuncSetAttribute(k_procatt, cudaFuncAttributeMaxDynamicSharedMemorySize, PROC_SMEM);

    const int M_IN  = BATCH * NIN;   // 65536
    const int M_LAT = BATCH * NLAT;  // 16384
    const size_t MS = (size_t)HID * HID;

    BWList L;
    L.w[0] = down_w;
    L.w[1] = pa_w;          L.w[2] = pa_w + 16384;  L.w[3] = pa_w + 32768;
    L.w[4] = up_w;
    L.w[5] = mlp1_w;        L.w[6] = mlp1_w + MS;   L.w[7] = mlp1_w + 2 * MS;
    L.w[8] = mlp2_w;        L.w[9] = mlp2_w + MS;   L.w[10] = mlp2_w + 2 * MS;
    L.w[11] = res_w;        L.w[12] = res_w + MS;   L.w[13] = res_w + 2 * MS;
    L.w[14] = de1_w;
    L.bre_mask = 0x1F;

    // merged precompute: weights + knn + factors (+ transposed factors)
    k_pre<<<2000, 256>>>(L, bwh, bwl, kidx, kcnt, down_r, up_r,
                         wdn, wdnT, wup, wupT);

#define BW(i) (bwh + (size_t)(i) * MS), (bwl + (size_t)(i) * MS)
#define NUL4 nullptr, nullptr, nullptr, nullptr

    // ---- down: fused encoder + value GEMM, then separable attention ----
    k_gemm<1,0,0,0,0><<<M_IN / 128, 256, GEMM_SMEM>>>(
        nullptr, nullptr, BW(0), NUL4,
        nullptr, nullptr, x, en_w, en_b, nullptr, nullptr,
        val, nullptr, nullptr);
    {
        dim3 g1(RIN / 8, BATCH, NH);
        k_sepY<RLAT, RIN><<<g1, 256>>>(val, wdn, T);
        dim3 g2(RLAT / 8, BATCH, NH);      // QYT=8 for RQ=32
        k_sepX<RLAT, RIN><<<g2, 256>>>(T, wdnT, hAh, hAl);
    }

    // ---- processor blocks (latent GEMMs on 512-thread variant) ----
    bf16 *hinh = hAh, *hinl = hAl, *houth = hBh, *houtl = hBl;
    for (int i = 0; i < 3; i++) {
        k_gemm512<0,0,0><<<M_LAT / 128, 512, GEMM_SMEM>>>(
            hinh, hinl, BW(1 + i), NUL4,
            nullptr, nullptr, val, nullptr, nullptr);
        {
            dim3 g(16, BATCH);
            k_procatt<<<g, 256, PROC_SMEM>>>(val, pa_r + i * NH, kidx, kcnt, pah, pal);
        }
        k_gemm512<0,1,1><<<M_LAT / 128, 512, GEMM_SMEM>>>(
            pah, pal, BW(5 + i), NUL4,
            mlp1_b + i * HID, nullptr, nullptr, t1h, t1l);
        k_gemm512<1,1,1><<<M_LAT / 128, 512, GEMM_SMEM>>>(
            t1h, t1l, BW(8 + i), hinh, hinl, BW(11 + i),
            mlp2_b + i * HID, res_b + i * HID,
            nullptr, houth, houtl);
        bf16* t;
        t = hinh; hinh = houth; houth = t;
        t = hinl; hinl = houtl; houtl = t;
    }

    // ---- up: value GEMM + separable attention ----
    k_gemm512<0,0,0><<<M_LAT / 128, 512, GEMM_SMEM>>>(
        hinh, hinl, BW(4), NUL4,
        nullptr, nullptr, val, nullptr, nullptr);
    {
        dim3 g1(RLAT / 8, BATCH, NH);
        k_sepY<RIN, RLAT><<<g1, 256>>>(val, wup, T);
        dim3 g2(RIN / 4, BATCH, NH);       // QYT=4 for RQ=64
        k_sepX<RIN, RLAT><<<g2, 256>>>(T, wupT, huph, hupl);
    }

    // ---- fused decoder ----
    k_gemm<0,0,1,1,0><<<M_IN / 128, 256, GEMM_SMEM>>>(
        huph, hupl, BW(14), NUL4,
        de1_b, nullptr, nullptr, nullptr, nullptr, de2_w, de2_b,
        out, nullptr, nullptr);
#undef BW
#undef NUL4
}

// round 16
// speedup vs baseline: 1.2969x; 1.0433x over previous
#include <cuda_runtime.h>
#include <cuda_bf16.h>
#include <math.h>

// ---------------------------------------------------------------------------
// Problem constants
// ---------------------------------------------------------------------------
#define BATCH   16
#define NH      8
#define HID     128
#define VD      16
#define RIN     64
#define RLAT    32
#define NIN     (RIN*RIN)   // 4096
#define NLAT    (RLAT*RLAT) // 1024
#define PI_F    3.14159265358979323846f

#define NWMAT   15
#define GEMM_SMEM (4*128*136*2)   // 128x128 tiles: 139264 bytes

// procatt tiled smem budget
#define KMAX  40
#define PROC_SMEM (256*128*4 + 64*KMAX*8*4 + 64*KMAX*4 + 64*4 + 64*8*4)  // 225536

typedef __nv_bfloat16 bf16;
typedef __nv_bfloat162 bf162;

// ---------------------------------------------------------------------------
// Scratch buffers
// ---------------------------------------------------------------------------
__device__ float g_val[BATCH*NIN*HID];                       // f32 value proj
__device__ float g_T  [BATCH*2048*HID];                      // sep-attention T
__device__ __align__(16) bf16 g_hA_h[BATCH*NLAT*HID];
__device__ __align__(16) bf16 g_hA_l[BATCH*NLAT*HID];
__device__ __align__(16) bf16 g_hB_h[BATCH*NLAT*HID];
__device__ __align__(16) bf16 g_hB_l[BATCH*NLAT*HID];
__device__ __align__(16) bf16 g_pa_h[BATCH*NLAT*HID];
__device__ __align__(16) bf16 g_pa_l[BATCH*NLAT*HID];
__device__ __align__(16) bf16 g_t1_h[BATCH*NLAT*HID];
__device__ __align__(16) bf16 g_t1_l[BATCH*NLAT*HID];
__device__ __align__(16) bf16 g_hup_h[BATCH*NIN*HID];
__device__ __align__(16) bf16 g_hup_l[BATCH*NIN*HID];
__device__ float g_wdn [NH*RLAT*RIN];    // [h][qy][ky]
__device__ float g_wdnT[NH*RIN*RLAT];    // [h][kx][qx]  (transposed)
__device__ float g_wup [NH*RIN*RLAT];
__device__ float g_wupT[NH*RLAT*RIN];
__device__ int   g_kidx[NLAT*64];
__device__ int   g_kcnt[NLAT];
__device__ __align__(16) bf16 g_bwh[NWMAT*HID*HID];
__device__ __align__(16) bf16 g_bwl[NWMAT*HID*HID];

// ---------------------------------------------------------------------------
// Helpers
// ---------------------------------------------------------------------------
__device__ __forceinline__ float gelu_f(float x) {
    const float c = 0.7978845608028654f;
    float y = c * fmaf(0.044715f * x, x * x, x);
    return x / (1.0f + __expf(-2.0f * y));
}

__device__ __forceinline__ float head_scale(float r) {
    return tanf(0.25f * PI_F * (1.0f - 1e-7f) * (1.0f + sinf(r)));
}

__device__ __forceinline__ void split_bf(float v, bf16& h, bf16& l) {
    h = __float2bfloat16(v);
    l = __float2bfloat16(v - __bfloat162float(h));
}

__device__ __forceinline__ void mma_bf16(float* d,
        unsigned a0, unsigned a1, unsigned a2, unsigned a3,
        unsigned b0, unsigned b1) {
    asm volatile(
        "mma.sync.aligned.m16n8k16.row.col.f32.bf16.bf16.f32 "
        "{%0,%1,%2,%3}, {%4,%5,%6,%7}, {%8,%9}, {%0,%1,%2,%3};"
        : "+f"(d[0]), "+f"(d[1]), "+f"(d[2]), "+f"(d[3])
        : "r"(a0), "r"(a1), "r"(a2), "r"(a3), "r"(b0), "r"(b1));
}

__device__ __forceinline__ void ldsm4(unsigned& r0, unsigned& r1, unsigned& r2,
                                      unsigned& r3, unsigned addr) {
    asm volatile("ldmatrix.sync.aligned.m8n8.x4.shared.b16 {%0,%1,%2,%3}, [%4];"
        : "=r"(r0), "=r"(r1), "=r"(r2), "=r"(r3) : "r"(addr));
}

// ---------------------------------------------------------------------------
// Merged precompute kernel:
//   blocks [0,960)    : weight prep (15 mats x 64 blocks)
//   blocks [960,1984) : kNN neighbor lists (1024 queries)
//   blocks [1984,2000): separable factors + transposed copies
// ---------------------------------------------------------------------------
struct BWList { const float* w[NWMAT]; unsigned bre_mask; };

__device__ void factor_body(int h, const float* rv, float* w, float* wt,
                            int RQ, int RK) {
    int tid = threadIdx.x, lane = tid & 31, wp = tid >> 5;
    int KP = RK >> 5;
    float s = head_scale(rv[h]);
    for (int q = wp; q < RQ; q += 8) {
        float qp = (float)q / (float)RQ;
        float d[2];
        float mind = 1e30f;
        for (int i = 0; i < KP; i++) {
            int k = lane + i * 32;
            float dd = qp - (float)k / (float)RK;
            d[i] = 0.5f * dd * dd;
            mind = fminf(mind, d[i]);
        }
        for (int o = 16; o > 0; o >>= 1)
            mind = fminf(mind, __shfl_xor_sync(0xffffffffu, mind, o));
        float p[2], sum = 0.f;
        for (int i = 0; i < KP; i++) { p[i] = __expf(s * (mind - d[i])); sum += p[i]; }
        for (int o = 16; o > 0; o >>= 1)
            sum += __shfl_xor_sync(0xffffffffu, sum, o);
        float inv = 1.0f / sum;
        for (int i = 0; i < KP; i++) {
            int k = lane + i * 32;
            float val = p[i] * inv;
            w [(h * RQ + q) * RK + k] = val;
            wt[(h * RK + k) * RQ + q] = val;
        }
    }
}

__global__ void k_pre(BWList L, bf16* __restrict__ outh, bf16* __restrict__ outl,
                      int* __restrict__ kidx, int* __restrict__ kcnt,
                      const float* __restrict__ down_r, const float* __restrict__ up_r,
                      float* __restrict__ wdn, float* __restrict__ wdnT,
                      float* __restrict__ wup, float* __restrict__ wupT) {
    int bid = blockIdx.x;
    int tid = threadIdx.x;
    if (bid < 960) {
        int mat = bid >> 6;
        const float* w = L.w[mat];
        int bre = (L.bre_mask >> mat) & 1;
        int idx = (bid & 63) * 256 + tid;
        int k = idx >> 7, n = idx & 127;
        float v;
        if (bre) {
            int h = n >> 4, vd = n & 15;
            v = w[((size_t)h * HID + k) * VD + vd];
        } else {
            v = w[k * HID + n];
        }
        bf16 hi, lo;
        split_bf(v, hi, lo);
        size_t o = (size_t)mat * HID * HID + n * HID + k;
        outh[o] = hi;
        outl[o] = lo;
        return;
    }
    if (bid < 1984) {
        int q = bid - 960;
        int lane = tid & 31, w = tid >> 5;
        int qx = q & (RLAT - 1), qy = q >> 5;
        int dv[4];
#pragma unroll
        for (int i = 0; i < 4; i++) {
            int k = tid * 4 + i;
            int kx = k & (RLAT - 1), ky = k >> 5;
            int dx = qx - kx, dy = qy - ky;
            dv[i] = dx * dx + dy * dy;
        }
        __shared__ int scount;
        int lo = 0, hi = 2 * 31 * 31;
        while (lo < hi) {
            int mid = (lo + hi) >> 1;
            if (tid == 0) scount = 0;
            __syncthreads();
            int c = 0;
#pragma unroll
            for (int i = 0; i < 4; i++) c += (dv[i] <= mid);
#pragma unroll
            for (int o = 16; o > 0; o >>= 1) c += __shfl_down_sync(0xffffffffu, c, o);
            if (lane == 0) atomicAdd(&scount, c);
            __syncthreads();
            if (scount >= 21) hi = mid; else lo = mid + 1;
            __syncthreads();
        }
        int sel[4], cnt_t = 0;
#pragma unroll
        for (int i = 0; i < 4; i++) { sel[i] = (dv[i] <= lo); cnt_t += sel[i]; }
        int incl = cnt_t;
#pragma unroll
        for (int o = 1; o < 32; o <<= 1) {
            int v = __shfl_up_sync(0xffffffffu, incl, o);
            if (lane >= o) incl += v;
        }
        __shared__ int wsum[8], wbase[8];
        if (lane == 31) wsum[w] = incl;
        __syncthreads();
        if (tid == 0) {
            int b = 0;
            for (int i = 0; i < 8; i++) { wbase[i] = b; b += wsum[i]; }
            kcnt[q] = b;
        }
        __syncthreads();
        int pos = wbase[w] + incl - cnt_t;
#pragma unroll
        for (int i = 0; i < 4; i++) {
            if (sel[i] && pos < 64) kidx[q * 64 + pos] = tid * 4 + i;
            pos += sel[i];
        }
        return;
    }
    int j = bid - 1984;
    if (j < 8) factor_body(j, down_r, wdn, wdnT, RLAT, RIN);
    else       factor_body(j - 8, up_r, wup, wupT, RIN, RLAT);
}

// ---------------------------------------------------------------------------
// Unified tensor-core GEMM: BM=128, 512 threads = 16 warps (bf16x3 split).
// Warp = 16 rows x 64 cols (wm in 0..7 row groups, wn in 0..1 col halves).
// Modes: AENC (A-tile = gelu(x@enW+enb) on the fly), DUAL (A@W + A2@W2),
// DOGELU, DEC (dot rows with d2w; two col-halves combined via smem atomicAdd),
// OBF (bf16 hi/lo plane output).
// ---------------------------------------------------------------------------
template <int AENC, int DUAL, int DOGELU, int DEC, int OBF>
__global__ void __launch_bounds__(512, 1)
k_gemm(const bf16* __restrict__ Ah, const bf16* __restrict__ Al,
       const bf16* __restrict__ Bh, const bf16* __restrict__ Bl,
       const bf16* __restrict__ A2h, const bf16* __restrict__ A2l,
       const bf16* __restrict__ B2h, const bf16* __restrict__ B2l,
       const float* __restrict__ bias, const float* __restrict__ bias2,
       const float* __restrict__ x, const float* __restrict__ enw,
       const float* __restrict__ enb,
       const float* __restrict__ d2w, const float* __restrict__ d2b,
       float* __restrict__ Cf, bf16* __restrict__ Ch, bf16* __restrict__ Cl) {
    extern __shared__ __align__(16) char smem_raw[];
    bf16* sAh = (bf16*)smem_raw;
    bf16* sAl = sAh + 128 * 136;
    bf16* sBh = sAl + 128 * 136;
    bf16* sBl = sBh + 128 * 136;

    int tid = threadIdx.x;
    int wid = tid >> 5, lane = tid & 31;
    int wm = wid & 7, wn = wid >> 3;
    int g = lane >> 2, s = lane & 3;
    size_t rbase = (size_t)blockIdx.x * 128;

    unsigned sAh_b = (unsigned)__cvta_generic_to_shared(sAh);
    unsigned sAl_b = (unsigned)__cvta_generic_to_shared(sAl);
    unsigned sBh_b = (unsigned)__cvta_generic_to_shared(sBh);
    unsigned sBl_b = (unsigned)__cvta_generic_to_shared(sBl);
    int arowf = wm * 16 + (lane & 15);
    unsigned aoff = (unsigned)((arowf * 136 + ((lane >> 4) << 3)) * 2);
    int brow = wn * 64 + (lane & 7) + ((lane >> 4) << 3);
    unsigned boff = (unsigned)((brow * 136 + (((lane >> 3) & 1) << 3)) * 2);

    float acc[8][4];
#pragma unroll
    for (int j = 0; j < 8; j++)
#pragma unroll
        for (int e = 0; e < 4; e++) acc[j][e] = 0.f;

    const int NPASS = DUAL ? 2 : 1;
#pragma unroll
    for (int pass = 0; pass < NPASS; pass++) {
        const bf16* Aph = (DUAL && pass) ? A2h : Ah;
        const bf16* Apl = (DUAL && pass) ? A2l : Al;
        const bf16* Bph = (DUAL && pass) ? B2h : Bh;
        const bf16* Bpl = (DUAL && pass) ? B2l : Bl;

        if (AENC && pass == 0) {
            int row = tid >> 2, q4 = tid & 3;
            size_t grow = rbase + row;
            float x0 = x[grow * 3 + 0], x1 = x[grow * 3 + 1], x2 = x[grow * 3 + 2];
#pragma unroll 8
            for (int c = 0; c < 32; c++) {
                int cc = q4 * 32 + c;
                float a = fmaf(x0, enw[cc],
                          fmaf(x1, enw[HID + cc],
                          fmaf(x2, enw[2 * HID + cc], enb[cc])));
                a = gelu_f(a);
                bf16 h, l;
                split_bf(a, h, l);
                sAh[row * 136 + cc] = h;
                sAl[row * 136 + cc] = l;
            }
        } else {
            const uint4* Ah4 = (const uint4*)(Aph + rbase * 128);
            const uint4* Al4 = (const uint4*)(Apl + rbase * 128);
#pragma unroll
            for (int i = 0; i < 4; i++) {
                int idx8 = tid + i * 512;
                int row = idx8 >> 4, k8 = (idx8 & 15) << 3;
                *(uint4*)&sAh[row * 136 + k8] = Ah4[idx8];
                *(uint4*)&sAl[row * 136 + k8] = Al4[idx8];
            }
        }
        {
            const uint4* Bh4 = (const uint4*)Bph;
            const uint4* Bl4 = (const uint4*)Bpl;
#pragma unroll
            for (int i = 0; i < 4; i++) {
                int idx8 = tid + i * 512;
                int n = idx8 >> 4, k8 = (idx8 & 15) << 3;
                *(uint4*)&sBh[n * 136 + k8] = Bh4[idx8];
                *(uint4*)&sBl[n * 136 + k8] = Bl4[idx8];
            }
        }
        __syncthreads();

#pragma unroll
        for (int ks = 0; ks < 8; ks++) {
            unsigned kb = (unsigned)(ks * 16 * 2);
            unsigned ah0, ah1, ah2, ah3, al0, al1, al2, al3;
            ldsm4(ah0, ah1, ah2, ah3, sAh_b + aoff + kb);
            ldsm4(al0, al1, al2, al3, sAl_b + aoff + kb);
#pragma unroll
            for (int j2 = 0; j2 < 4; j2++) {
                unsigned bofs = boff + (unsigned)(j2 * 16 * 136 * 2) + kb;
                unsigned bh0, bh1, bh2, bh3, bl0, bl1, bl2, bl3;
                ldsm4(bh0, bh1, bh2, bh3, sBh_b + bofs);
                ldsm4(bl0, bl1, bl2, bl3, sBl_b + bofs);
                mma_bf16(acc[2 * j2],     ah0, ah1, ah2, ah3, bh0, bh1);
                mma_bf16(acc[2 * j2],     ah0, ah1, ah2, ah3, bl0, bl1);
                mma_bf16(acc[2 * j2],     al0, al1, al2, al3, bh0, bh1);
                mma_bf16(acc[2 * j2 + 1], ah0, ah1, ah2, ah3, bh2, bh3);
                mma_bf16(acc[2 * j2 + 1], ah0, ah1, ah2, ah3, bl2, bl3);
                mma_bf16(acc[2 * j2 + 1], al0, al1, al2, al3, bh2, bh3);
            }
        }
        __syncthreads();
    }

    int r0 = wm * 16 + g;
    if (DEC) {
        float* sred = (float*)smem_raw;     // tiles dead after final sync
        if (tid < 128) sred[tid] = 0.f;
        __syncthreads();
        float p0 = 0.f, p1 = 0.f;
#pragma unroll
        for (int j = 0; j < 8; j++) {
            int c = wn * 64 + j * 8 + 2 * s;
            float b0 = bias ? bias[c] : 0.f;
            float b1 = bias ? bias[c + 1] : 0.f;
            float w0 = d2w[c], w1 = d2w[c + 1];
            float v0 = gelu_f(acc[j][0] + b0), v1 = gelu_f(acc[j][1] + b1);
            float v2 = gelu_f(acc[j][2] + b0), v3 = gelu_f(acc[j][3] + b1);
            p0 = fmaf(v0, w0, fmaf(v1, w1, p0));
            p1 = fmaf(v2, w0, fmaf(v3, w1, p1));
        }
        p0 += __shfl_xor_sync(0xffffffffu, p0, 1);
        p0 += __shfl_xor_sync(0xffffffffu, p0, 2);
        p1 += __shfl_xor_sync(0xffffffffu, p1, 1);
        p1 += __shfl_xor_sync(0xffffffffu, p1, 2);
        if (s == 0) {
            atomicAdd(&sred[r0], p0);
            atomicAdd(&sred[r0 + 8], p1);
        }
        __syncthreads();
        if (tid < 128) Cf[rbase + tid] = sred[tid] + d2b[0];
    } else {
#pragma unroll
        for (int j = 0; j < 8; j++) {
            int c = wn * 64 + j * 8 + 2 * s;
            float b0 = 0.f, b1 = 0.f;
            if (bias) {
                float2 bb = *(const float2*)&bias[c];
                b0 += bb.x; b1 += bb.y;
            }
            if (DUAL && bias2) {
                float2 bb = *(const float2*)&bias2[c];
                b0 += bb.x; b1 += bb.y;
            }
            float v0 = acc[j][0] + b0, v1 = acc[j][1] + b1;
            float v2 = acc[j][2] + b0, v3 = acc[j][3] + b1;
            if (DOGELU) {
                v0 = gelu_f(v0); v1 = gelu_f(v1);
                v2 = gelu_f(v2); v3 = gelu_f(v3);
            }
            if (OBF) {
                bf16 h0, l0, h1, l1, h2, l2, h3, l3;
                split_bf(v0, h0, l0); split_bf(v1, h1, l1);
                split_bf(v2, h2, l2); split_bf(v3, h3, l3);
                bf162 ph0 = {h0, h1}, ph1 = {h2, h3};
                bf162 pl0 = {l0, l1}, pl1 = {l2, l3};
                *(bf162*)&Ch[(rbase + r0) * 128 + c] = ph0;
                *(bf162*)&Cl[(rbase + r0) * 128 + c] = pl0;
                *(bf162*)&Ch[(rbase + r0 + 8) * 128 + c] = ph1;
                *(bf162*)&Cl[(rbase + r0 + 8) * 128 + c] = pl1;
            } else {
                float2 u0 = {v0, v1}, u1 = {v2, v3};
                *(float2*)&Cf[(rbase + r0) * 128 + c] = u0;
                *(float2*)&Cf[(rbase + r0 + 8) * 128 + c] = u1;
            }
        }
    }
}

// ---------------------------------------------------------------------------
// Separable attention step 1 (contract ky)
// ---------------------------------------------------------------------------
template <int RQ, int RK>
__global__ void k_sepY(const float* __restrict__ V, const float* __restrict__ w,
                       float* __restrict__ T) {
    constexpr int QPT = RQ / 8;
    __shared__ float sW[RQ * RK];
    __shared__ float sV[RK * 128];
    int tid = threadIdx.x;
    int kxc = blockIdx.x;
    int b = blockIdx.y, h = blockIdx.z;
    const float* wh = w + h * RQ * RK;
    for (int i = tid; i < RQ * RK; i += 256) sW[i] = wh[i];
    for (int i = tid; i < RK * 128; i += 256) {
        int ky = i >> 7, col = i & 127;
        int kx = kxc * 8 + (col >> 4), vd = col & 15;
        sV[i] = V[(((size_t)b * RK + ky) * RK + kx) * 128 + h * 16 + vd];
    }
    __syncthreads();
    int qy0 = (tid >> 5) * QPT, col0 = (tid & 31) * 4;
    float acc[QPT][4];
#pragma unroll
    for (int i = 0; i < QPT; i++)
#pragma unroll
        for (int j = 0; j < 4; j++) acc[i][j] = 0.f;
#pragma unroll 4
    for (int ky = 0; ky < RK; ky++) {
        float4 v = *reinterpret_cast<const float4*>(&sV[ky * 128 + col0]);
#pragma unroll
        for (int i = 0; i < QPT; i++) {
            float a = sW[(qy0 + i) * RK + ky];
            acc[i][0] = fmaf(a, v.x, acc[i][0]);
            acc[i][1] = fmaf(a, v.y, acc[i][1]);
            acc[i][2] = fmaf(a, v.z, acc[i][2]);
            acc[i][3] = fmaf(a, v.w, acc[i][3]);
        }
    }
    int kx = kxc * 8 + (col0 >> 4), vd0 = col0 & 15;
#pragma unroll
    for (int i = 0; i < QPT; i++) {
        float4 r = make_float4(acc[i][0], acc[i][1], acc[i][2], acc[i][3]);
        *reinterpret_cast<float4*>(
            &T[(((size_t)b * RQ + qy0 + i) * RK + kx) * 128 + h * 16 + vd0]) = r;
    }
}

// ---------------------------------------------------------------------------
// Separable attention step 2 (contract kx), 4x4 register tile, bf16 output
// ---------------------------------------------------------------------------
template <int RQ, int RK>
__global__ void __launch_bounds__(256, 1)
k_sepX(const float* __restrict__ T, const float* __restrict__ wT,
       bf16* __restrict__ Oh, bf16* __restrict__ Ol) {
    constexpr int QYT = 256 / RQ;
    __shared__ __align__(16) float sWt[RK * RQ];       // [kx][qx]
    __shared__ __align__(16) float sT[QYT * RK * 16];  // [qp][kx][c]
    int tid = threadIdx.x;
    int b = blockIdx.y, h = blockIdx.z;
    int qy0 = blockIdx.x * QYT;
    const float* wth = wT + h * RQ * RK;
    for (int i = tid; i < RQ * RK; i += 256) sWt[i] = wth[i];
    for (int i = tid; i < QYT * RK * 16; i += 256) {
        int qp = i / (RK * 16);
        int rem = i - qp * (RK * 16);
        int kx = rem >> 4, vd = rem & 15;
        sT[i] = T[(((size_t)b * RQ + qy0 + qp) * RK + kx) * 128 + h * 16 + vd];
    }
    __syncthreads();

    int qp = tid / RQ;
    int sub = tid - qp * RQ;
    int qx0 = (sub >> 2) << 2;
    int c0 = (sub & 3) << 2;
    const float* tr = &sT[qp * RK * 16];

    float acc[4][4];
#pragma unroll
    for (int i = 0; i < 4; i++)
#pragma unroll
        for (int j = 0; j < 4; j++) acc[i][j] = 0.f;

#pragma unroll 4
    for (int kx = 0; kx < RK; kx++) {
        float4 wv = *(const float4*)&sWt[kx * RQ + qx0];
        float4 tv = *(const float4*)&tr[kx * 16 + c0];
        acc[0][0] = fmaf(wv.x, tv.x, acc[0][0]);
        acc[0][1] = fmaf(wv.x, tv.y, acc[0][1]);
        acc[0][2] = fmaf(wv.x, tv.z, acc[0][2]);
        acc[0][3] = fmaf(wv.x, tv.w, acc[0][3]);
        acc[1][0] = fmaf(wv.y, tv.x, acc[1][0]);
        acc[1][1] = fmaf(wv.y, tv.y, acc[1][1]);
        acc[1][2] = fmaf(wv.y, tv.z, acc[1][2]);
        acc[1][3] = fmaf(wv.y, tv.w, acc[1][3]);
        acc[2][0] = fmaf(wv.z, tv.x, acc[2][0]);
        acc[2][1] = fmaf(wv.z, tv.y, acc[2][1]);
        acc[2][2] = fmaf(wv.z, tv.z, acc[2][2]);
        acc[2][3] = fmaf(wv.z, tv.w, acc[2][3]);
        acc[3][0] = fmaf(wv.w, tv.x, acc[3][0]);
        acc[3][1] = fmaf(wv.w, tv.y, acc[3][1]);
        acc[3][2] = fmaf(wv.w, tv.z, acc[3][2]);
        acc[3][3] = fmaf(wv.w, tv.w, acc[3][3]);
    }

    int qy = qy0 + qp;
#pragma unroll
    for (int i = 0; i < 4; i++) {
        float g0 = gelu_f(acc[i][0]), g1 = gelu_f(acc[i][1]);
        float g2 = gelu_f(acc[i][2]), g3 = gelu_f(acc[i][3]);
        bf16 h0, l0, h1, l1, h2, l2, h3, l3;
        split_bf(g0, h0, l0); split_bf(g1, h1, l1);
        split_bf(g2, h2, l2); split_bf(g3, h3, l3);
        bf162 ph0 = {h0, h1}, ph1 = {h2, h3};
        bf162 pl0 = {l0, l1}, pl1 = {l2, l3};
        size_t oi = ((size_t)b * RQ * RQ + qy * RQ + qx0 + i) * 128 + h * 16 + c0;
        *(bf162*)&Oh[oi] = ph0;
        *(bf162*)&Oh[oi + 2] = ph1;
        *(bf162*)&Ol[oi] = pl0;
        *(bf162*)&Ol[oi + 2] = pl1;
    }
}

// ---------------------------------------------------------------------------
// Tiled sparse proc attention -> bf16 plane output
// ---------------------------------------------------------------------------
__global__ void __launch_bounds__(256, 1)
k_procatt(const float* __restrict__ V, const float* __restrict__ rv,
          const int* __restrict__ kidx, const int* __restrict__ kcnt,
          bf16* __restrict__ Oh, bf16* __restrict__ Ol) {
    extern __shared__ float psm[];
    float* sV   = psm;
    float* sp   = sV + 256 * 128;
    int*   skl  = (int*)(sp + 64 * KMAX * 8);
    int*   scnt = skl + 64 * KMAX;
    float* sinv = (float*)(scnt + 64);
    __shared__ float sscale[NH];

    int tile = blockIdx.x;
    int b = blockIdx.y;
    int tx = tile & 3, ty = tile >> 2;
    int x0 = tx * 8 - 4, y0 = ty * 8 - 4;
    int tid = threadIdx.x, lane = tid & 31, w = tid >> 5;

    if (tid < NH) sscale[tid] = head_scale(rv[tid]);

    const float4* V4 = (const float4*)V;
    for (int r = w; r < 256; r += 8) {
        int ix = r & 15, iy = r >> 4;
        int kx = x0 + ix, ky = y0 + iy;
        if ((unsigned)kx < 32u && (unsigned)ky < 32u) {
            int k = ky * 32 + kx;
            *(float4*)&sV[r * 128 + lane * 4] = V4[((size_t)b * NLAT + k) * 32 + lane];
        }
    }
    if (tid < 64) {
        int qx = tx * 8 + (tid & 7), qy = ty * 8 + (tid >> 3);
        scnt[tid] = kcnt[qy * 32 + qx];
    }
    for (int i = tid; i < 64 * KMAX; i += 256) {
        int ql = i / KMAX, j = i - ql * KMAX;
        if (j < 64) {
            int qx = tx * 8 + (ql & 7), qy = ty * 8 + (ql >> 3);
            int gk = kidx[(qy * 32 + qx) * 64 + j];
            int kx = gk & 31, ky = gk >> 5;
            skl[i] = (ky - y0) * 16 + (kx - x0);
        }
    }
    __syncthreads();
    for (int i = tid; i < 64 * KMAX; i += 256) {
        int ql = i / KMAX, j = i - ql * KMAX;
        if (j < scnt[ql]) {
            int kl = skl[i];
            int ix = kl & 15, iy = kl >> 4;
            float dx = (float)(ix - 4 - (ql & 7)) * (1.0f / RLAT);
            float dy = (float)(iy - 4 - (ql >> 3)) * (1.0f / RLAT);
            float dist = 0.5f * (dx * dx + dy * dy);
#pragma unroll
            for (int h = 0; h < NH; h++)
                sp[i * 8 + h] = __expf(-sscale[h] * dist);
        }
    }
    __syncthreads();
    for (int hq = tid; hq < 512; hq += 256) {
        int ql = hq >> 3, h = hq & 7;
        int cnt = scnt[ql];
        float sum = 0.f;
        for (int j = 0; j < cnt; j++) sum += sp[(ql * KMAX + j) * 8 + h];
        sinv[ql * 8 + h] = 1.0f / sum;
    }
    __syncthreads();

    int qy_l = w;
    int cg = lane;
    int h = cg >> 2;
    const float4* sV4 = (const float4*)sV;
#pragma unroll
    for (int qx_l = 0; qx_l < 8; qx_l++) {
        int ql = qy_l * 8 + qx_l;
        int cnt = scnt[ql];
        int base = ql * KMAX;
        float4 acc = make_float4(0.f, 0.f, 0.f, 0.f);
        for (int j = 0; j < cnt; j++) {
            float p = sp[(base + j) * 8 + h];
            float4 v = sV4[skl[base + j] * 32 + cg];
            acc.x = fmaf(p, v.x, acc.x);
            acc.y = fmaf(p, v.y, acc.y);
            acc.z = fmaf(p, v.z, acc.z);
            acc.w = fmaf(p, v.w, acc.w);
        }
        float inv = sinv[ql * 8 + h];
        float r0 = gelu_f(acc.x * inv), r1 = gelu_f(acc.y * inv);
        float r2 = gelu_f(acc.z * inv), r3 = gelu_f(acc.w * inv);
        int qglob = (ty * 8 + qy_l) * 32 + tx * 8 + qx_l;
        size_t oi = ((size_t)b * NLAT + qglob) * 128 + cg * 4;
        bf16 h0, l0, h1, l1, h2, l2, h3, l3;
        split_bf(r0, h0, l0); split_bf(r1, h1, l1);
        split_bf(r2, h2, l2); split_bf(r3, h3, l3);
        bf162 ph0 = {h0, h1}, ph1 = {h2, h3};
        bf162 pl0 = {l0, l1}, pl1 = {l2, l3};
        *(bf162*)&Oh[oi] = ph0;
        *(bf162*)&Oh[oi + 2] = ph1;
        *(bf162*)&Ol[oi] = pl0;
        *(bf162*)&Ol[oi + 2] = pl1;
    }
}

// ---------------------------------------------------------------------------
// Launcher
// ---------------------------------------------------------------------------
extern "C" void kernel_launch(void* const* d_in, const int* in_sizes, int n_in,
                              void* d_out, int out_size) {
    const float* x        = (const float*)d_in[0];
    const float* en_w     = (const float*)d_in[1];
    const float* en_b     = (const float*)d_in[2];
    const float* down_r   = (const float*)d_in[3];
    const float* down_w   = (const float*)d_in[4];
    const float* pa_r     = (const float*)d_in[5];
    const float* pa_w     = (const float*)d_in[6];
    const float* mlp1_w   = (const float*)d_in[7];
    const float* mlp1_b   = (const float*)d_in[8];
    const float* mlp2_w   = (const float*)d_in[9];
    const float* mlp2_b   = (const float*)d_in[10];
    const float* res_w    = (const float*)d_in[11];
    const float* res_b    = (const float*)d_in[12];
    const float* up_r     = (const float*)d_in[13];
    const float* up_w     = (const float*)d_in[14];
    const float* de1_w    = (const float*)d_in[15];
    const float* de1_b    = (const float*)d_in[16];
    const float* de2_w    = (const float*)d_in[17];
    const float* de2_b    = (const float*)d_in[18];
    float* out = (float*)d_out;

    float *val, *T, *wdn, *wdnT, *wup, *wupT;
    int *kidx, *kcnt;
    bf16 *bwh, *bwl;
    bf16 *hAh, *hAl, *hBh, *hBl, *pah, *pal, *t1h, *t1l, *huph, *hupl;
    cudaGetSymbolAddress((void**)&val,  g_val);
    cudaGetSymbolAddress((void**)&T,    g_T);
    cudaGetSymbolAddress((void**)&wdn,  g_wdn);
    cudaGetSymbolAddress((void**)&wdnT, g_wdnT);
    cudaGetSymbolAddress((void**)&wup,  g_wup);
    cudaGetSymbolAddress((void**)&wupT, g_wupT);
    cudaGetSymbolAddress((void**)&kidx, g_kidx);
    cudaGetSymbolAddress((void**)&kcnt, g_kcnt);
    cudaGetSymbolAddress((void**)&bwh,  g_bwh);
    cudaGetSymbolAddress((void**)&bwl,  g_bwl);
    cudaGetSymbolAddress((void**)&hAh,  g_hA_h);
    cudaGetSymbolAddress((void**)&hAl,  g_hA_l);
    cudaGetSymbolAddress((void**)&hBh,  g_hB_h);
    cudaGetSymbolAddress((void**)&hBl,  g_hB_l);
    cudaGetSymbolAddress((void**)&pah,  g_pa_h);
    cudaGetSymbolAddress((void**)&pal,  g_pa_l);
    cudaGetSymbolAddress((void**)&t1h,  g_t1_h);
    cudaGetSymbolAddress((void**)&t1l,  g_t1_l);
    cudaGetSymbolAddress((void**)&huph, g_hup_h);
    cudaGetSymbolAddress((void**)&hupl, g_hup_l);

    cudaFuncSetAttribute(k_gemm<1,0,0,0,0>, cudaFuncAttributeMaxDynamicSharedMemorySize, GEMM_SMEM);
    cudaFuncSetAttribute(k_gemm<0,0,0,0,0>, cudaFuncAttributeMaxDynamicSharedMemorySize, GEMM_SMEM);
    cudaFuncSetAttribute(k_gemm<0,0,1,0,1>, cudaFuncAttributeMaxDynamicSharedMemorySize, GEMM_SMEM);
    cudaFuncSetAttribute(k_gemm<0,1,1,0,1>, cudaFuncAttributeMaxDynamicSharedMemorySize, GEMM_SMEM);
    cudaFuncSetAttribute(k_gemm<0,0,1,1,0>, cudaFuncAttributeMaxDynamicSharedMemorySize, GEMM_SMEM);
    cudaFuncSetAttribute(k_procatt, cudaFuncAttributeMaxDynamicSharedMemorySize, PROC_SMEM);

    const int M_IN  = BATCH * NIN;   // 65536
    const int M_LAT = BATCH * NLAT;  // 16384
    const size_t MS = (size_t)HID * HID;

    BWList L;
    L.w[0] = down_w;
    L.w[1] = pa_w;          L.w[2] = pa_w + 16384;  L.w[3] = pa_w + 32768;
    L.w[4] = up_w;
    L.w[5] = mlp1_w;        L.w[6] = mlp1_w + MS;   L.w[7] = mlp1_w + 2 * MS;
    L.w[8] = mlp2_w;        L.w[9] = mlp2_w + MS;   L.w[10] = mlp2_w + 2 * MS;
    L.w[11] = res_w;        L.w[12] = res_w + MS;   L.w[13] = res_w + 2 * MS;
    L.w[14] = de1_w;
    L.bre_mask = 0x1F;

    // merged precompute: weights + knn + factors (+ transposed factors)
    k_pre<<<2000, 256>>>(L, bwh, bwl, kidx, kcnt, down_r, up_r,
                         wdn, wdnT, wup, wupT);

#define BW(i) (bwh + (size_t)(i) * MS), (bwl + (size_t)(i) * MS)
#define NUL4 nullptr, nullptr, nullptr, nullptr

    // ---- down: fused encoder + value GEMM (512 thr), then separable attn ----
    k_gemm<1,0,0,0,0><<<M_IN / 128, 512, GEMM_SMEM>>>(
        nullptr, nullptr, BW(0), NUL4,
        nullptr, nullptr, x, en_w, en_b, nullptr, nullptr,
        val, nullptr, nullptr);
    {
        dim3 g1(RIN / 8, BATCH, NH);
        k_sepY<RLAT, RIN><<<g1, 256>>>(val, wdn, T);
        dim3 g2(RLAT / 8, BATCH, NH);      // QYT=8 for RQ=32
        k_sepX<RLAT, RIN><<<g2, 256>>>(T, wdnT, hAh, hAl);
    }

    // ---- processor blocks ----
    bf16 *hinh = hAh, *hinl = hAl, *houth = hBh, *houtl = hBl;
    for (int i = 0; i < 3; i++) {
        k_gemm<0,0,0,0,0><<<M_LAT / 128, 512, GEMM_SMEM>>>(
            hinh, hinl, BW(1 + i), NUL4,
            nullptr, nullptr, nullptr, nullptr, nullptr, nullptr, nullptr,
            val, nullptr, nullptr);
        {
            dim3 g(16, BATCH);
            k_procatt<<<g, 256, PROC_SMEM>>>(val, pa_r + i * NH, kidx, kcnt, pah, pal);
        }
        k_gemm<0,0,1,0,1><<<M_LAT / 128, 512, GEMM_SMEM>>>(
            pah, pal, BW(5 + i), NUL4,
            mlp1_b + i * HID, nullptr, nullptr, nullptr, nullptr, nullptr, nullptr,
            nullptr, t1h, t1l);
        k_gemm<0,1,1,0,1><<<M_LAT / 128, 512, GEMM_SMEM>>>(
            t1h, t1l, BW(8 + i), hinh, hinl, BW(11 + i),
            mlp2_b + i * HID, res_b + i * HID,
            nullptr, nullptr, nullptr, nullptr, nullptr,
            nullptr, houth, houtl);
        bf16* t;
        t = hinh; hinh = houth; houth = t;
        t = hinl; hinl = houtl; houtl = t;
    }

    // ---- up: value GEMM + separable attention ----
    k_gemm<0,0,0,0,0><<<M_LAT / 128, 512, GEMM_SMEM>>>(
        hinh, hinl, BW(4), NUL4,
        nullptr, nullptr, nullptr, nullptr, nullptr, nullptr, nullptr,
        val, nullptr, nullptr);
    {
        dim3 g1(RLAT / 8, BATCH, NH);
        k_sepY<RIN, RLAT><<<g1, 256>>>(val, wup, T);
        dim3 g2(RIN / 4, BATCH, NH);       // QYT=4 for RQ=64
        k_sepX<RIN, RLAT><<<g2, 256>>>(T, wupT, huph, hupl);
    }

    // ---- fused decoder (512 thr, smem-reduced DEC epilogue) ----
    k_gemm<0,0,1,1,0><<<M_IN / 128, 512, GEMM_SMEM>>>(
        huph, hupl, BW(14), NUL4,
        de1_b, nullptr, nullptr, nullptr, nullptr, de2_w, de2_b,
        out, nullptr, nullptr);
#undef BW
#undef NUL4
}

// round 17
// speedup vs baseline: 1.3350x; 1.0293x over previous
#include <cuda_runtime.h>
#include <cuda_bf16.h>
#include <math.h>

// ---------------------------------------------------------------------------
// Problem constants
// ---------------------------------------------------------------------------
#define BATCH   16
#define NH      8
#define HID     128
#define VD      16
#define RIN     64
#define RLAT    32
#define NIN     (RIN*RIN)   // 4096
#define NLAT    (RLAT*RLAT) // 1024
#define PI_F    3.14159265358979323846f

#define NWMAT   15
#define GEMM_SMEM (4*128*136*2)   // 128x128 tiles: 139264 bytes

// procatt tiled smem budget
#define KMAX  40
#define PROC_SMEM (256*128*4 + 64*KMAX*8*4 + 64*KMAX*4 + 64*4 + 64*8*4)  // 225536

typedef __nv_bfloat16 bf16;
typedef __nv_bfloat162 bf162;

// ---------------------------------------------------------------------------
// Scratch buffers
// ---------------------------------------------------------------------------
__device__ float g_val[BATCH*NIN*HID];                       // f32 value proj
__device__ float g_T  [BATCH*2048*HID];                      // sep-attention T
__device__ __align__(16) bf16 g_hA_h[BATCH*NLAT*HID];
__device__ __align__(16) bf16 g_hA_l[BATCH*NLAT*HID];
__device__ __align__(16) bf16 g_hB_h[BATCH*NLAT*HID];
__device__ __align__(16) bf16 g_hB_l[BATCH*NLAT*HID];
__device__ __align__(16) bf16 g_pa_h[BATCH*NLAT*HID];
__device__ __align__(16) bf16 g_pa_l[BATCH*NLAT*HID];
__device__ __align__(16) bf16 g_hup_h[BATCH*NIN*HID];
__device__ __align__(16) bf16 g_hup_l[BATCH*NIN*HID];
__device__ float g_wdn [NH*RLAT*RIN];    // [h][qy][ky]
__device__ float g_wdnT[NH*RIN*RLAT];    // [h][kx][qx]  (transposed)
__device__ float g_wup [NH*RIN*RLAT];
__device__ float g_wupT[NH*RLAT*RIN];
__device__ int   g_kidx[NLAT*64];
__device__ int   g_kcnt[NLAT];
__device__ __align__(16) bf16 g_bwh[NWMAT*HID*HID];
__device__ __align__(16) bf16 g_bwl[NWMAT*HID*HID];

// ---------------------------------------------------------------------------
// Helpers
// ---------------------------------------------------------------------------
__device__ __forceinline__ float gelu_f(float x) {
    const float c = 0.7978845608028654f;
    float y = c * fmaf(0.044715f * x, x * x, x);
    return x / (1.0f + __expf(-2.0f * y));
}

__device__ __forceinline__ float head_scale(float r) {
    return tanf(0.25f * PI_F * (1.0f - 1e-7f) * (1.0f + sinf(r)));
}

__device__ __forceinline__ void split_bf(float v, bf16& h, bf16& l) {
    h = __float2bfloat16(v);
    l = __float2bfloat16(v - __bfloat162float(h));
}

__device__ __forceinline__ void mma_bf16(float* d,
        unsigned a0, unsigned a1, unsigned a2, unsigned a3,
        unsigned b0, unsigned b1) {
    asm volatile(
        "mma.sync.aligned.m16n8k16.row.col.f32.bf16.bf16.f32 "
        "{%0,%1,%2,%3}, {%4,%5,%6,%7}, {%8,%9}, {%0,%1,%2,%3};"
        : "+f"(d[0]), "+f"(d[1]), "+f"(d[2]), "+f"(d[3])
        : "r"(a0), "r"(a1), "r"(a2), "r"(a3), "r"(b0), "r"(b1));
}

__device__ __forceinline__ void ldsm4(unsigned& r0, unsigned& r1, unsigned& r2,
                                      unsigned& r3, unsigned addr) {
    asm volatile("ldmatrix.sync.aligned.m8n8.x4.shared.b16 {%0,%1,%2,%3}, [%4];"
        : "=r"(r0), "=r"(r1), "=r"(r2), "=r"(r3) : "r"(addr));
}

// ---------------------------------------------------------------------------
// Merged precompute kernel
// ---------------------------------------------------------------------------
struct BWList { const float* w[NWMAT]; unsigned bre_mask; };

__device__ void factor_body(int h, const float* rv, float* w, float* wt,
                            int RQ, int RK) {
    int tid = threadIdx.x, lane = tid & 31, wp = tid >> 5;
    int KP = RK >> 5;
    float s = head_scale(rv[h]);
    for (int q = wp; q < RQ; q += 8) {
        float qp = (float)q / (float)RQ;
        float d[2];
        float mind = 1e30f;
        for (int i = 0; i < KP; i++) {
            int k = lane + i * 32;
            float dd = qp - (float)k / (float)RK;
            d[i] = 0.5f * dd * dd;
            mind = fminf(mind, d[i]);
        }
        for (int o = 16; o > 0; o >>= 1)
            mind = fminf(mind, __shfl_xor_sync(0xffffffffu, mind, o));
        float p[2], sum = 0.f;
        for (int i = 0; i < KP; i++) { p[i] = __expf(s * (mind - d[i])); sum += p[i]; }
        for (int o = 16; o > 0; o >>= 1)
            sum += __shfl_xor_sync(0xffffffffu, sum, o);
        float inv = 1.0f / sum;
        for (int i = 0; i < KP; i++) {
            int k = lane + i * 32;
            float val = p[i] * inv;
            w [(h * RQ + q) * RK + k] = val;
            wt[(h * RK + k) * RQ + q] = val;
        }
    }
}

__global__ void k_pre(BWList L, bf16* __restrict__ outh, bf16* __restrict__ outl,
                      int* __restrict__ kidx, int* __restrict__ kcnt,
                      const float* __restrict__ down_r, const float* __restrict__ up_r,
                      float* __restrict__ wdn, float* __restrict__ wdnT,
                      float* __restrict__ wup, float* __restrict__ wupT) {
    int bid = blockIdx.x;
    int tid = threadIdx.x;
    if (bid < 960) {
        int mat = bid >> 6;
        const float* w = L.w[mat];
        int bre = (L.bre_mask >> mat) & 1;
        int idx = (bid & 63) * 256 + tid;
        int k = idx >> 7, n = idx & 127;
        float v;
        if (bre) {
            int h = n >> 4, vd = n & 15;
            v = w[((size_t)h * HID + k) * VD + vd];
        } else {
            v = w[k * HID + n];
        }
        bf16 hi, lo;
        split_bf(v, hi, lo);
        size_t o = (size_t)mat * HID * HID + n * HID + k;
        outh[o] = hi;
        outl[o] = lo;
        return;
    }
    if (bid < 1984) {
        int q = bid - 960;
        int lane = tid & 31, w = tid >> 5;
        int qx = q & (RLAT - 1), qy = q >> 5;
        int dv[4];
#pragma unroll
        for (int i = 0; i < 4; i++) {
            int k = tid * 4 + i;
            int kx = k & (RLAT - 1), ky = k >> 5;
            int dx = qx - kx, dy = qy - ky;
            dv[i] = dx * dx + dy * dy;
        }
        __shared__ int scount;
        int lo = 0, hi = 2 * 31 * 31;
        while (lo < hi) {
            int mid = (lo + hi) >> 1;
            if (tid == 0) scount = 0;
            __syncthreads();
            int c = 0;
#pragma unroll
            for (int i = 0; i < 4; i++) c += (dv[i] <= mid);
#pragma unroll
            for (int o = 16; o > 0; o >>= 1) c += __shfl_down_sync(0xffffffffu, c, o);
            if (lane == 0) atomicAdd(&scount, c);
            __syncthreads();
            if (scount >= 21) hi = mid; else lo = mid + 1;
            __syncthreads();
        }
        int sel[4], cnt_t = 0;
#pragma unroll
        for (int i = 0; i < 4; i++) { sel[i] = (dv[i] <= lo); cnt_t += sel[i]; }
        int incl = cnt_t;
#pragma unroll
        for (int o = 1; o < 32; o <<= 1) {
            int v = __shfl_up_sync(0xffffffffu, incl, o);
            if (lane >= o) incl += v;
        }
        __shared__ int wsum[8], wbase[8];
        if (lane == 31) wsum[w] = incl;
        __syncthreads();
        if (tid == 0) {
            int b = 0;
            for (int i = 0; i < 8; i++) { wbase[i] = b; b += wsum[i]; }
            kcnt[q] = b;
        }
        __syncthreads();
        int pos = wbase[w] + incl - cnt_t;
#pragma unroll
        for (int i = 0; i < 4; i++) {
            if (sel[i] && pos < 64) kidx[q * 64 + pos] = tid * 4 + i;
            pos += sel[i];
        }
        return;
    }
    int j = bid - 1984;
    if (j < 8) factor_body(j, down_r, wdn, wdnT, RLAT, RIN);
    else       factor_body(j - 8, up_r, wup, wupT, RIN, RLAT);
}

// ---------------------------------------------------------------------------
// Unified tensor-core GEMM: BM=128, 512 threads = 16 warps (bf16x3 split).
// ---------------------------------------------------------------------------
template <int AENC, int DUAL, int DOGELU, int DEC, int OBF>
__global__ void __launch_bounds__(512, 1)
k_gemm(const bf16* __restrict__ Ah, const bf16* __restrict__ Al,
       const bf16* __restrict__ Bh, const bf16* __restrict__ Bl,
       const bf16* __restrict__ A2h, const bf16* __restrict__ A2l,
       const bf16* __restrict__ B2h, const bf16* __restrict__ B2l,
       const float* __restrict__ bias, const float* __restrict__ bias2,
       const float* __restrict__ x, const float* __restrict__ enw,
       const float* __restrict__ enb,
       const float* __restrict__ d2w, const float* __restrict__ d2b,
       float* __restrict__ Cf, bf16* __restrict__ Ch, bf16* __restrict__ Cl) {
    extern __shared__ __align__(16) char smem_raw[];
    bf16* sAh = (bf16*)smem_raw;
    bf16* sAl = sAh + 128 * 136;
    bf16* sBh = sAl + 128 * 136;
    bf16* sBl = sBh + 128 * 136;

    int tid = threadIdx.x;
    int wid = tid >> 5, lane = tid & 31;
    int wm = wid & 7, wn = wid >> 3;
    int g = lane >> 2, s = lane & 3;
    size_t rbase = (size_t)blockIdx.x * 128;

    unsigned sAh_b = (unsigned)__cvta_generic_to_shared(sAh);
    unsigned sAl_b = (unsigned)__cvta_generic_to_shared(sAl);
    unsigned sBh_b = (unsigned)__cvta_generic_to_shared(sBh);
    unsigned sBl_b = (unsigned)__cvta_generic_to_shared(sBl);
    int arowf = wm * 16 + (lane & 15);
    unsigned aoff = (unsigned)((arowf * 136 + ((lane >> 4) << 3)) * 2);
    int brow = wn * 64 + (lane & 7) + ((lane >> 4) << 3);
    unsigned boff = (unsigned)((brow * 136 + (((lane >> 3) & 1) << 3)) * 2);

    float acc[8][4];
#pragma unroll
    for (int j = 0; j < 8; j++)
#pragma unroll
        for (int e = 0; e < 4; e++) acc[j][e] = 0.f;

    const int NPASS = DUAL ? 2 : 1;
#pragma unroll
    for (int pass = 0; pass < NPASS; pass++) {
        const bf16* Aph = (DUAL && pass) ? A2h : Ah;
        const bf16* Apl = (DUAL && pass) ? A2l : Al;
        const bf16* Bph = (DUAL && pass) ? B2h : Bh;
        const bf16* Bpl = (DUAL && pass) ? B2l : Bl;

        if (AENC && pass == 0) {
            int row = tid >> 2, q4 = tid & 3;
            size_t grow = rbase + row;
            float x0 = x[grow * 3 + 0], x1 = x[grow * 3 + 1], x2 = x[grow * 3 + 2];
#pragma unroll 8
            for (int c = 0; c < 32; c++) {
                int cc = q4 * 32 + c;
                float a = fmaf(x0, enw[cc],
                          fmaf(x1, enw[HID + cc],
                          fmaf(x2, enw[2 * HID + cc], enb[cc])));
                a = gelu_f(a);
                bf16 h, l;
                split_bf(a, h, l);
                sAh[row * 136 + cc] = h;
                sAl[row * 136 + cc] = l;
            }
        } else {
            const uint4* Ah4 = (const uint4*)(Aph + rbase * 128);
            const uint4* Al4 = (const uint4*)(Apl + rbase * 128);
#pragma unroll
            for (int i = 0; i < 4; i++) {
                int idx8 = tid + i * 512;
                int row = idx8 >> 4, k8 = (idx8 & 15) << 3;
                *(uint4*)&sAh[row * 136 + k8] = Ah4[idx8];
                *(uint4*)&sAl[row * 136 + k8] = Al4[idx8];
            }
        }
        {
            const uint4* Bh4 = (const uint4*)Bph;
            const uint4* Bl4 = (const uint4*)Bpl;
#pragma unroll
            for (int i = 0; i < 4; i++) {
                int idx8 = tid + i * 512;
                int n = idx8 >> 4, k8 = (idx8 & 15) << 3;
                *(uint4*)&sBh[n * 136 + k8] = Bh4[idx8];
                *(uint4*)&sBl[n * 136 + k8] = Bl4[idx8];
            }
        }
        __syncthreads();

#pragma unroll
        for (int ks = 0; ks < 8; ks++) {
            unsigned kb = (unsigned)(ks * 16 * 2);
            unsigned ah0, ah1, ah2, ah3, al0, al1, al2, al3;
            ldsm4(ah0, ah1, ah2, ah3, sAh_b + aoff + kb);
            ldsm4(al0, al1, al2, al3, sAl_b + aoff + kb);
#pragma unroll
            for (int j2 = 0; j2 < 4; j2++) {
                unsigned bofs = boff + (unsigned)(j2 * 16 * 136 * 2) + kb;
                unsigned bh0, bh1, bh2, bh3, bl0, bl1, bl2, bl3;
                ldsm4(bh0, bh1, bh2, bh3, sBh_b + bofs);
                ldsm4(bl0, bl1, bl2, bl3, sBl_b + bofs);
                mma_bf16(acc[2 * j2],     ah0, ah1, ah2, ah3, bh0, bh1);
                mma_bf16(acc[2 * j2],     ah0, ah1, ah2, ah3, bl0, bl1);
                mma_bf16(acc[2 * j2],     al0, al1, al2, al3, bh0, bh1);
                mma_bf16(acc[2 * j2 + 1], ah0, ah1, ah2, ah3, bh2, bh3);
                mma_bf16(acc[2 * j2 + 1], ah0, ah1, ah2, ah3, bl2, bl3);
                mma_bf16(acc[2 * j2 + 1], al0, al1, al2, al3, bh2, bh3);
            }
        }
        __syncthreads();
    }

    int r0 = wm * 16 + g;
    if (DEC) {
        float* sred = (float*)smem_raw;     // tiles dead after final sync
        if (tid < 128) sred[tid] = 0.f;
        __syncthreads();
        float p0 = 0.f, p1 = 0.f;
#pragma unroll
        for (int j = 0; j < 8; j++) {
            int c = wn * 64 + j * 8 + 2 * s;
            float b0 = bias ? bias[c] : 0.f;
            float b1 = bias ? bias[c + 1] : 0.f;
            float w0 = d2w[c], w1 = d2w[c + 1];
            float v0 = gelu_f(acc[j][0] + b0), v1 = gelu_f(acc[j][1] + b1);
            float v2 = gelu_f(acc[j][2] + b0), v3 = gelu_f(acc[j][3] + b1);
            p0 = fmaf(v0, w0, fmaf(v1, w1, p0));
            p1 = fmaf(v2, w0, fmaf(v3, w1, p1));
        }
        p0 += __shfl_xor_sync(0xffffffffu, p0, 1);
        p0 += __shfl_xor_sync(0xffffffffu, p0, 2);
        p1 += __shfl_xor_sync(0xffffffffu, p1, 1);
        p1 += __shfl_xor_sync(0xffffffffu, p1, 2);
        if (s == 0) {
            atomicAdd(&sred[r0], p0);
            atomicAdd(&sred[r0 + 8], p1);
        }
        __syncthreads();
        if (tid < 128) Cf[rbase + tid] = sred[tid] + d2b[0];
    } else {
#pragma unroll
        for (int j = 0; j < 8; j++) {
            int c = wn * 64 + j * 8 + 2 * s;
            float b0 = 0.f, b1 = 0.f;
            if (bias) {
                float2 bb = *(const float2*)&bias[c];
                b0 += bb.x; b1 += bb.y;
            }
            if (DUAL && bias2) {
                float2 bb = *(const float2*)&bias2[c];
                b0 += bb.x; b1 += bb.y;
            }
            float v0 = acc[j][0] + b0, v1 = acc[j][1] + b1;
            float v2 = acc[j][2] + b0, v3 = acc[j][3] + b1;
            if (DOGELU) {
                v0 = gelu_f(v0); v1 = gelu_f(v1);
                v2 = gelu_f(v2); v3 = gelu_f(v3);
            }
            if (OBF) {
                bf16 h0, l0, h1, l1, h2, l2, h3, l3;
                split_bf(v0, h0, l0); split_bf(v1, h1, l1);
                split_bf(v2, h2, l2); split_bf(v3, h3, l3);
                bf162 ph0 = {h0, h1}, ph1 = {h2, h3};
                bf162 pl0 = {l0, l1}, pl1 = {l2, l3};
                *(bf162*)&Ch[(rbase + r0) * 128 + c] = ph0;
                *(bf162*)&Cl[(rbase + r0) * 128 + c] = pl0;
                *(bf162*)&Ch[(rbase + r0 + 8) * 128 + c] = ph1;
                *(bf162*)&Cl[(rbase + r0 + 8) * 128 + c] = pl1;
            } else {
                float2 u0 = {v0, v1}, u1 = {v2, v3};
                *(float2*)&Cf[(rbase + r0) * 128 + c] = u0;
                *(float2*)&Cf[(rbase + r0 + 8) * 128 + c] = u1;
            }
        }
    }
}

// ---------------------------------------------------------------------------
// Fused MLP kernel: hout = gelu(t1@W2 + hin@Wres + b2 + bres),
//                   t1   = gelu(pa@W1 + b1)   (t1 lives in smem only).
// Same 512-thread / 16-warp layout & per-output mma order as the split
// kernels; t1 goes through the identical bf16 hi/lo split => bit-identical.
// ---------------------------------------------------------------------------
__global__ void __launch_bounds__(512, 1)
k_mlp(const bf16* __restrict__ pah, const bf16* __restrict__ pal,
      const bf16* __restrict__ W1h, const bf16* __restrict__ W1l,
      const bf16* __restrict__ W2h, const bf16* __restrict__ W2l,
      const bf16* __restrict__ hinh, const bf16* __restrict__ hinl,
      const bf16* __restrict__ W3h, const bf16* __restrict__ W3l,
      const float* __restrict__ b1, const float* __restrict__ b2,
      const float* __restrict__ b3,
      bf16* __restrict__ Ch, bf16* __restrict__ Cl) {
    extern __shared__ __align__(16) char smem_raw[];
    bf16* sAh = (bf16*)smem_raw;
    bf16* sAl = sAh + 128 * 136;
    bf16* sBh = sAl + 128 * 136;
    bf16* sBl = sBh + 128 * 136;

    int tid = threadIdx.x;
    int wid = tid >> 5, lane = tid & 31;
    int wm = wid & 7, wn = wid >> 3;
    int g = lane >> 2, s = lane & 3;
    size_t rbase = (size_t)blockIdx.x * 128;

    unsigned sAh_b = (unsigned)__cvta_generic_to_shared(sAh);
    unsigned sAl_b = (unsigned)__cvta_generic_to_shared(sAl);
    unsigned sBh_b = (unsigned)__cvta_generic_to_shared(sBh);
    unsigned sBl_b = (unsigned)__cvta_generic_to_shared(sBl);
    int arowf = wm * 16 + (lane & 15);
    unsigned aoff = (unsigned)((arowf * 136 + ((lane >> 4) << 3)) * 2);
    int brow = wn * 64 + (lane & 7) + ((lane >> 4) << 3);
    unsigned boff = (unsigned)((brow * 136 + (((lane >> 3) & 1) << 3)) * 2);

    int r0 = wm * 16 + g;
    float acc[8][4];
#pragma unroll
    for (int j = 0; j < 8; j++)
#pragma unroll
        for (int e = 0; e < 4; e++) acc[j][e] = 0.f;

    // ---- pass 1: acc = pa @ W1 ----
    {
        const uint4* Ah4 = (const uint4*)(pah + rbase * 128);
        const uint4* Al4 = (const uint4*)(pal + rbase * 128);
#pragma unroll
        for (int i = 0; i < 4; i++) {
            int idx8 = tid + i * 512;
            int row = idx8 >> 4, k8 = (idx8 & 15) << 3;
            *(uint4*)&sAh[row * 136 + k8] = Ah4[idx8];
            *(uint4*)&sAl[row * 136 + k8] = Al4[idx8];
        }
        const uint4* Bh4 = (const uint4*)W1h;
        const uint4* Bl4 = (const uint4*)W1l;
#pragma unroll
        for (int i = 0; i < 4; i++) {
            int idx8 = tid + i * 512;
            int n = idx8 >> 4, k8 = (idx8 & 15) << 3;
            *(uint4*)&sBh[n * 136 + k8] = Bh4[idx8];
            *(uint4*)&sBl[n * 136 + k8] = Bl4[idx8];
        }
    }
    __syncthreads();
#pragma unroll
    for (int ks = 0; ks < 8; ks++) {
        unsigned kb = (unsigned)(ks * 16 * 2);
        unsigned ah0, ah1, ah2, ah3, al0, al1, al2, al3;
        ldsm4(ah0, ah1, ah2, ah3, sAh_b + aoff + kb);
        ldsm4(al0, al1, al2, al3, sAl_b + aoff + kb);
#pragma unroll
        for (int j2 = 0; j2 < 4; j2++) {
            unsigned bofs = boff + (unsigned)(j2 * 16 * 136 * 2) + kb;
            unsigned bh0, bh1, bh2, bh3, bl0, bl1, bl2, bl3;
            ldsm4(bh0, bh1, bh2, bh3, sBh_b + bofs);
            ldsm4(bl0, bl1, bl2, bl3, sBl_b + bofs);
            mma_bf16(acc[2 * j2],     ah0, ah1, ah2, ah3, bh0, bh1);
            mma_bf16(acc[2 * j2],     ah0, ah1, ah2, ah3, bl0, bl1);
            mma_bf16(acc[2 * j2],     al0, al1, al2, al3, bh0, bh1);
            mma_bf16(acc[2 * j2 + 1], ah0, ah1, ah2, ah3, bh2, bh3);
            mma_bf16(acc[2 * j2 + 1], ah0, ah1, ah2, ah3, bl2, bl3);
            mma_bf16(acc[2 * j2 + 1], al0, al1, al2, al3, bh2, bh3);
        }
    }
    __syncthreads();

    // ---- write t1 = split(gelu(acc + b1)) into sA; stage W2 into sB ----
#pragma unroll
    for (int j = 0; j < 8; j++) {
        int c = wn * 64 + j * 8 + 2 * s;
        float2 bb = *(const float2*)&b1[c];
        float v0 = gelu_f(acc[j][0] + bb.x), v1 = gelu_f(acc[j][1] + bb.y);
        float v2 = gelu_f(acc[j][2] + bb.x), v3 = gelu_f(acc[j][3] + bb.y);
        bf16 h0, l0, h1, l1, h2, l2, h3, l3;
        split_bf(v0, h0, l0); split_bf(v1, h1, l1);
        split_bf(v2, h2, l2); split_bf(v3, h3, l3);
        bf162 ph0 = {h0, h1}, ph1 = {h2, h3};
        bf162 pl0 = {l0, l1}, pl1 = {l2, l3};
        *(bf162*)&sAh[r0 * 136 + c] = ph0;
        *(bf162*)&sAl[r0 * 136 + c] = pl0;
        *(bf162*)&sAh[(r0 + 8) * 136 + c] = ph1;
        *(bf162*)&sAl[(r0 + 8) * 136 + c] = pl1;
    }
    {
        const uint4* Bh4 = (const uint4*)W2h;
        const uint4* Bl4 = (const uint4*)W2l;
#pragma unroll
        for (int i = 0; i < 4; i++) {
            int idx8 = tid + i * 512;
            int n = idx8 >> 4, k8 = (idx8 & 15) << 3;
            *(uint4*)&sBh[n * 136 + k8] = Bh4[idx8];
            *(uint4*)&sBl[n * 136 + k8] = Bl4[idx8];
        }
    }
#pragma unroll
    for (int j = 0; j < 8; j++)
#pragma unroll
        for (int e = 0; e < 4; e++) acc[j][e] = 0.f;
    __syncthreads();

    // ---- pass 2: acc = t1 @ W2 ----
#pragma unroll
    for (int ks = 0; ks < 8; ks++) {
        unsigned kb = (unsigned)(ks * 16 * 2);
        unsigned ah0, ah1, ah2, ah3, al0, al1, al2, al3;
        ldsm4(ah0, ah1, ah2, ah3, sAh_b + aoff + kb);
        ldsm4(al0, al1, al2, al3, sAl_b + aoff + kb);
#pragma unroll
        for (int j2 = 0; j2 < 4; j2++) {
            unsigned bofs = boff + (unsigned)(j2 * 16 * 136 * 2) + kb;
            unsigned bh0, bh1, bh2, bh3, bl0, bl1, bl2, bl3;
            ldsm4(bh0, bh1, bh2, bh3, sBh_b + bofs);
            ldsm4(bl0, bl1, bl2, bl3, sBl_b + bofs);
            mma_bf16(acc[2 * j2],     ah0, ah1, ah2, ah3, bh0, bh1);
            mma_bf16(acc[2 * j2],     ah0, ah1, ah2, ah3, bl0, bl1);
            mma_bf16(acc[2 * j2],     al0, al1, al2, al3, bh0, bh1);
            mma_bf16(acc[2 * j2 + 1], ah0, ah1, ah2, ah3, bh2, bh3);
            mma_bf16(acc[2 * j2 + 1], ah0, ah1, ah2, ah3, bl2, bl3);
            mma_bf16(acc[2 * j2 + 1], al0, al1, al2, al3, bh2, bh3);
        }
    }
    __syncthreads();

    // ---- pass 3: acc += hin @ Wres ----
    {
        const uint4* Ah4 = (const uint4*)(hinh + rbase * 128);
        const uint4* Al4 = (const uint4*)(hinl + rbase * 128);
#pragma unroll
        for (int i = 0; i < 4; i++) {
            int idx8 = tid + i * 512;
            int row = idx8 >> 4, k8 = (idx8 & 15) << 3;
            *(uint4*)&sAh[row * 136 + k8] = Ah4[idx8];
            *(uint4*)&sAl[row * 136 + k8] = Al4[idx8];
        }
        const uint4* Bh4 = (const uint4*)W3h;
        const uint4* Bl4 = (const uint4*)W3l;
#pragma unroll
        for (int i = 0; i < 4; i++) {
            int idx8 = tid + i * 512;
            int n = idx8 >> 4, k8 = (idx8 & 15) << 3;
            *(uint4*)&sBh[n * 136 + k8] = Bh4[idx8];
            *(uint4*)&sBl[n * 136 + k8] = Bl4[idx8];
        }
    }
    __syncthreads();
#pragma unroll
    for (int ks = 0; ks < 8; ks++) {
        unsigned kb = (unsigned)(ks * 16 * 2);
        unsigned ah0, ah1, ah2, ah3, al0, al1, al2, al3;
        ldsm4(ah0, ah1, ah2, ah3, sAh_b + aoff + kb);
        ldsm4(al0, al1, al2, al3, sAl_b + aoff + kb);
#pragma unroll
        for (int j2 = 0; j2 < 4; j2++) {
            unsigned bofs = boff + (unsigned)(j2 * 16 * 136 * 2) + kb;
            unsigned bh0, bh1, bh2, bh3, bl0, bl1, bl2, bl3;
            ldsm4(bh0, bh1, bh2, bh3, sBh_b + bofs);
            ldsm4(bl0, bl1, bl2, bl3, sBl_b + bofs);
            mma_bf16(acc[2 * j2],     ah0, ah1, ah2, ah3, bh0, bh1);
            mma_bf16(acc[2 * j2],     ah0, ah1, ah2, ah3, bl0, bl1);
            mma_bf16(acc[2 * j2],     al0, al1, al2, al3, bh0, bh1);
            mma_bf16(acc[2 * j2 + 1], ah0, ah1, ah2, ah3, bh2, bh3);
            mma_bf16(acc[2 * j2 + 1], ah0, ah1, ah2, ah3, bl2, bl3);
            mma_bf16(acc[2 * j2 + 1], al0, al1, al2, al3, bh2, bh3);
        }
    }

    // ---- epilogue: hout = split(gelu(acc + b2 + b3)) ----
#pragma unroll
    for (int j = 0; j < 8; j++) {
        int c = wn * 64 + j * 8 + 2 * s;
        float2 bb2 = *(const float2*)&b2[c];
        float2 bb3 = *(const float2*)&b3[c];
        float b0 = bb2.x + bb3.x, bb = bb2.y + bb3.y;
        float v0 = gelu_f(acc[j][0] + b0), v1 = gelu_f(acc[j][1] + bb);
        float v2 = gelu_f(acc[j][2] + b0), v3 = gelu_f(acc[j][3] + bb);
        bf16 h0, l0, h1, l1, h2, l2, h3, l3;
        split_bf(v0, h0, l0); split_bf(v1, h1, l1);
        split_bf(v2, h2, l2); split_bf(v3, h3, l3);
        bf162 ph0 = {h0, h1}, ph1 = {h2, h3};
        bf162 pl0 = {l0, l1}, pl1 = {l2, l3};
        *(bf162*)&Ch[(rbase + r0) * 128 + c] = ph0;
        *(bf162*)&Cl[(rbase + r0) * 128 + c] = pl0;
        *(bf162*)&Ch[(rbase + r0 + 8) * 128 + c] = ph1;
        *(bf162*)&Cl[(rbase + r0 + 8) * 128 + c] = pl1;
    }
}

// ---------------------------------------------------------------------------
// Separable attention step 1 (contract ky)
// ---------------------------------------------------------------------------
template <int RQ, int RK>
__global__ void k_sepY(const float* __restrict__ V, const float* __restrict__ w,
                       float* __restrict__ T) {
    constexpr int QPT = RQ / 8;
    __shared__ float sW[RQ * RK];
    __shared__ float sV[RK * 128];
    int tid = threadIdx.x;
    int kxc = blockIdx.x;
    int b = blockIdx.y, h = blockIdx.z;
    const float* wh = w + h * RQ * RK;
    for (int i = tid; i < RQ * RK; i += 256) sW[i] = wh[i];
    for (int i = tid; i < RK * 128; i += 256) {
        int ky = i >> 7, col = i & 127;
        int kx = kxc * 8 + (col >> 4), vd = col & 15;
        sV[i] = V[(((size_t)b * RK + ky) * RK + kx) * 128 + h * 16 + vd];
    }
    __syncthreads();
    int qy0 = (tid >> 5) * QPT, col0 = (tid & 31) * 4;
    float acc[QPT][4];
#pragma unroll
    for (int i = 0; i < QPT; i++)
#pragma unroll
        for (int j = 0; j < 4; j++) acc[i][j] = 0.f;
#pragma unroll 4
    for (int ky = 0; ky < RK; ky++) {
        float4 v = *reinterpret_cast<const float4*>(&sV[ky * 128 + col0]);
#pragma unroll
        for (int i = 0; i < QPT; i++) {
            float a = sW[(qy0 + i) * RK + ky];
            acc[i][0] = fmaf(a, v.x, acc[i][0]);
            acc[i][1] = fmaf(a, v.y, acc[i][1]);
            acc[i][2] = fmaf(a, v.z, acc[i][2]);
            acc[i][3] = fmaf(a, v.w, acc[i][3]);
        }
    }
    int kx = kxc * 8 + (col0 >> 4), vd0 = col0 & 15;
#pragma unroll
    for (int i = 0; i < QPT; i++) {
        float4 r = make_float4(acc[i][0], acc[i][1], acc[i][2], acc[i][3]);
        *reinterpret_cast<float4*>(
            &T[(((size_t)b * RQ + qy0 + i) * RK + kx) * 128 + h * 16 + vd0]) = r;
    }
}

// ---------------------------------------------------------------------------
// Separable attention step 2 (contract kx), 4x4 register tile, bf16 output
// ---------------------------------------------------------------------------
template <int RQ, int RK>
__global__ void __launch_bounds__(256, 1)
k_sepX(const float* __restrict__ T, const float* __restrict__ wT,
       bf16* __restrict__ Oh, bf16* __restrict__ Ol) {
    constexpr int QYT = 256 / RQ;
    __shared__ __align__(16) float sWt[RK * RQ];       // [kx][qx]
    __shared__ __align__(16) float sT[QYT * RK * 16];  // [qp][kx][c]
    int tid = threadIdx.x;
    int b = blockIdx.y, h = blockIdx.z;
    int qy0 = blockIdx.x * QYT;
    const float* wth = wT + h * RQ * RK;
    for (int i = tid; i < RQ * RK; i += 256) sWt[i] = wth[i];
    for (int i = tid; i < QYT * RK * 16; i += 256) {
        int qp = i / (RK * 16);
        int rem = i - qp * (RK * 16);
        int kx = rem >> 4, vd = rem & 15;
        sT[i] = T[(((size_t)b * RQ + qy0 + qp) * RK + kx) * 128 + h * 16 + vd];
    }
    __syncthreads();

    int qp = tid / RQ;
    int sub = tid - qp * RQ;
    int qx0 = (sub >> 2) << 2;
    int c0 = (sub & 3) << 2;
    const float* tr = &sT[qp * RK * 16];

    float acc[4][4];
#pragma unroll
    for (int i = 0; i < 4; i++)
#pragma unroll
        for (int j = 0; j < 4; j++) acc[i][j] = 0.f;

#pragma unroll 4
    for (int kx = 0; kx < RK; kx++) {
        float4 wv = *(const float4*)&sWt[kx * RQ + qx0];
        float4 tv = *(const float4*)&tr[kx * 16 + c0];
        acc[0][0] = fmaf(wv.x, tv.x, acc[0][0]);
        acc[0][1] = fmaf(wv.x, tv.y, acc[0][1]);
        acc[0][2] = fmaf(wv.x, tv.z, acc[0][2]);
        acc[0][3] = fmaf(wv.x, tv.w, acc[0][3]);
        acc[1][0] = fmaf(wv.y, tv.x, acc[1][0]);
        acc[1][1] = fmaf(wv.y, tv.y, acc[1][1]);
        acc[1][2] = fmaf(wv.y, tv.z, acc[1][2]);
        acc[1][3] = fmaf(wv.y, tv.w, acc[1][3]);
        acc[2][0] = fmaf(wv.z, tv.x, acc[2][0]);
        acc[2][1] = fmaf(wv.z, tv.y, acc[2][1]);
        acc[2][2] = fmaf(wv.z, tv.z, acc[2][2]);
        acc[2][3] = fmaf(wv.z, tv.w, acc[2][3]);
        acc[3][0] = fmaf(wv.w, tv.x, acc[3][0]);
        acc[3][1] = fmaf(wv.w, tv.y, acc[3][1]);
        acc[3][2] = fmaf(wv.w, tv.z, acc[3][2]);
        acc[3][3] = fmaf(wv.w, tv.w, acc[3][3]);
    }

    int qy = qy0 + qp;
#pragma unroll
    for (int i = 0; i < 4; i++) {
        float g0 = gelu_f(acc[i][0]), g1 = gelu_f(acc[i][1]);
        float g2 = gelu_f(acc[i][2]), g3 = gelu_f(acc[i][3]);
        bf16 h0, l0, h1, l1, h2, l2, h3, l3;
        split_bf(g0, h0, l0); split_bf(g1, h1, l1);
        split_bf(g2, h2, l2); split_bf(g3, h3, l3);
        bf162 ph0 = {h0, h1}, ph1 = {h2, h3};
        bf162 pl0 = {l0, l1}, pl1 = {l2, l3};
        size_t oi = ((size_t)b * RQ * RQ + qy * RQ + qx0 + i) * 128 + h * 16 + c0;
        *(bf162*)&Oh[oi] = ph0;
        *(bf162*)&Oh[oi + 2] = ph1;
        *(bf162*)&Ol[oi] = pl0;
        *(bf162*)&Ol[oi + 2] = pl1;
    }
}

// ---------------------------------------------------------------------------
// Tiled sparse proc attention -> bf16 plane output
// ---------------------------------------------------------------------------
__global__ void __launch_bounds__(256, 1)
k_procatt(const float* __restrict__ V, const float* __restrict__ rv,
          const int* __restrict__ kidx, const int* __restrict__ kcnt,
          bf16* __restrict__ Oh, bf16* __restrict__ Ol) {
    extern __shared__ float psm[];
    float* sV   = psm;
    float* sp   = sV + 256 * 128;
    int*   skl  = (int*)(sp + 64 * KMAX * 8);
    int*   scnt = skl + 64 * KMAX;
    float* sinv = (float*)(scnt + 64);
    __shared__ float sscale[NH];

    int tile = blockIdx.x;
    int b = blockIdx.y;
    int tx = tile & 3, ty = tile >> 2;
    int x0 = tx * 8 - 4, y0 = ty * 8 - 4;
    int tid = threadIdx.x, lane = tid & 31, w = tid >> 5;

    if (tid < NH) sscale[tid] = head_scale(rv[tid]);

    const float4* V4 = (const float4*)V;
    for (int r = w; r < 256; r += 8) {
        int ix = r & 15, iy = r >> 4;
        int kx = x0 + ix, ky = y0 + iy;
        if ((unsigned)kx < 32u && (unsigned)ky < 32u) {
            int k = ky * 32 + kx;
            *(float4*)&sV[r * 128 + lane * 4] = V4[((size_t)b * NLAT + k) * 32 + lane];
        }
    }
    if (tid < 64) {
        int qx = tx * 8 + (tid & 7), qy = ty * 8 + (tid >> 3);
        scnt[tid] = kcnt[qy * 32 + qx];
    }
    for (int i = tid; i < 64 * KMAX; i += 256) {
        int ql = i / KMAX, j = i - ql * KMAX;
        if (j < 64) {
            int qx = tx * 8 + (ql & 7), qy = ty * 8 + (ql >> 3);
            int gk = kidx[(qy * 32 + qx) * 64 + j];
            int kx = gk & 31, ky = gk >> 5;
            skl[i] = (ky - y0) * 16 + (kx - x0);
        }
    }
    __syncthreads();
    for (int i = tid; i < 64 * KMAX; i += 256) {
        int ql = i / KMAX, j = i - ql * KMAX;
        if (j < scnt[ql]) {
            int kl = skl[i];
            int ix = kl & 15, iy = kl >> 4;
            float dx = (float)(ix - 4 - (ql & 7)) * (1.0f / RLAT);
            float dy = (float)(iy - 4 - (ql >> 3)) * (1.0f / RLAT);
            float dist = 0.5f * (dx * dx + dy * dy);
#pragma unroll
            for (int h = 0; h < NH; h++)
                sp[i * 8 + h] = __expf(-sscale[h] * dist);
        }
    }
    __syncthreads();
    for (int hq = tid; hq < 512; hq += 256) {
        int ql = hq >> 3, h = hq & 7;
        int cnt = scnt[ql];
        float sum = 0.f;
        for (int j = 0; j < cnt; j++) sum += sp[(ql * KMAX + j) * 8 + h];
        sinv[ql * 8 + h] = 1.0f / sum;
    }
    __syncthreads();

    int qy_l = w;
    int cg = lane;
    int h = cg >> 2;
    const float4* sV4 = (const float4*)sV;
#pragma unroll
    for (int qx_l = 0; qx_l < 8; qx_l++) {
        int ql = qy_l * 8 + qx_l;
        int cnt = scnt[ql];
        int base = ql * KMAX;
        float4 acc = make_float4(0.f, 0.f, 0.f, 0.f);
        for (int j = 0; j < cnt; j++) {
            float p = sp[(base + j) * 8 + h];
            float4 v = sV4[skl[base + j] * 32 + cg];
            acc.x = fmaf(p, v.x, acc.x);
            acc.y = fmaf(p, v.y, acc.y);
            acc.z = fmaf(p, v.z, acc.z);
            acc.w = fmaf(p, v.w, acc.w);
        }
        float inv = sinv[ql * 8 + h];
        float r0 = gelu_f(acc.x * inv), r1 = gelu_f(acc.y * inv);
        float r2 = gelu_f(acc.z * inv), r3 = gelu_f(acc.w * inv);
        int qglob = (ty * 8 + qy_l) * 32 + tx * 8 + qx_l;
        size_t oi = ((size_t)b * NLAT + qglob) * 128 + cg * 4;
        bf16 h0, l0, h1, l1, h2, l2, h3, l3;
        split_bf(r0, h0, l0); split_bf(r1, h1, l1);
        split_bf(r2, h2, l2); split_bf(r3, h3, l3);
        bf162 ph0 = {h0, h1}, ph1 = {h2, h3};
        bf162 pl0 = {l0, l1}, pl1 = {l2, l3};
        *(bf162*)&Oh[oi] = ph0;
        *(bf162*)&Oh[oi + 2] = ph1;
        *(bf162*)&Ol[oi] = pl0;
        *(bf162*)&Ol[oi + 2] = pl1;
    }
}

// ---------------------------------------------------------------------------
// Launcher
// ---------------------------------------------------------------------------
extern "C" void kernel_launch(void* const* d_in, const int* in_sizes, int n_in,
                              void* d_out, int out_size) {
    const float* x        = (const float*)d_in[0];
    const float* en_w     = (const float*)d_in[1];
    const float* en_b     = (const float*)d_in[2];
    const float* down_r   = (const float*)d_in[3];
    const float* down_w   = (const float*)d_in[4];
    const float* pa_r     = (const float*)d_in[5];
    const float* pa_w     = (const float*)d_in[6];
    const float* mlp1_w   = (const float*)d_in[7];
    const float* mlp1_b   = (const float*)d_in[8];
    const float* mlp2_w   = (const float*)d_in[9];
    const float* mlp2_b   = (const float*)d_in[10];
    const float* res_w    = (const float*)d_in[11];
    const float* res_b    = (const float*)d_in[12];
    const float* up_r     = (const float*)d_in[13];
    const float* up_w     = (const float*)d_in[14];
    const float* de1_w    = (const float*)d_in[15];
    const float* de1_b    = (const float*)d_in[16];
    const float* de2_w    = (const float*)d_in[17];
    const float* de2_b    = (const float*)d_in[18];
    float* out = (float*)d_out;

    float *val, *T, *wdn, *wdnT, *wup, *wupT;
    int *kidx, *kcnt;
    bf16 *bwh, *bwl;
    bf16 *hAh, *hAl, *hBh, *hBl, *pah, *pal, *huph, *hupl;
    cudaGetSymbolAddress((void**)&val,  g_val);
    cudaGetSymbolAddress((void**)&T,    g_T);
    cudaGetSymbolAddress((void**)&wdn,  g_wdn);
    cudaGetSymbolAddress((void**)&wdnT, g_wdnT);
    cudaGetSymbolAddress((void**)&wup,  g_wup);
    cudaGetSymbolAddress((void**)&wupT, g_wupT);
    cudaGetSymbolAddress((void**)&kidx, g_kidx);
    cudaGetSymbolAddress((void**)&kcnt, g_kcnt);
    cudaGetSymbolAddress((void**)&bwh,  g_bwh);
    cudaGetSymbolAddress((void**)&bwl,  g_bwl);
    cudaGetSymbolAddress((void**)&hAh,  g_hA_h);
    cudaGetSymbolAddress((void**)&hAl,  g_hA_l);
    cudaGetSymbolAddress((void**)&hBh,  g_hB_h);
    cudaGetSymbolAddress((void**)&hBl,  g_hB_l);
    cudaGetSymbolAddress((void**)&pah,  g_pa_h);
    cudaGetSymbolAddress((void**)&pal,  g_pa_l);
    cudaGetSymbolAddress((void**)&huph, g_hup_h);
    cudaGetSymbolAddress((void**)&hupl, g_hup_l);

    cudaFuncSetAttribute(k_gemm<1,0,0,0,0>, cudaFuncAttributeMaxDynamicSharedMemorySize, GEMM_SMEM);
    cudaFuncSetAttribute(k_gemm<0,0,0,0,0>, cudaFuncAttributeMaxDynamicSharedMemorySize, GEMM_SMEM);
    cudaFuncSetAttribute(k_gemm<0,0,1,1,0>, cudaFuncAttributeMaxDynamicSharedMemorySize, GEMM_SMEM);
    cudaFuncSetAttribute(k_mlp, cudaFuncAttributeMaxDynamicSharedMemorySize, GEMM_SMEM);
    cudaFuncSetAttribute(k_procatt, cudaFuncAttributeMaxDynamicSharedMemorySize, PROC_SMEM);

    const int M_IN  = BATCH * NIN;   // 65536
    const int M_LAT = BATCH * NLAT;  // 16384
    const size_t MS = (size_t)HID * HID;

    BWList L;
    L.w[0] = down_w;
    L.w[1] = pa_w;          L.w[2] = pa_w + 16384;  L.w[3] = pa_w + 32768;
    L.w[4] = up_w;
    L.w[5] = mlp1_w;        L.w[6] = mlp1_w + MS;   L.w[7] = mlp1_w + 2 * MS;
    L.w[8] = mlp2_w;        L.w[9] = mlp2_w + MS;   L.w[10] = mlp2_w + 2 * MS;
    L.w[11] = res_w;        L.w[12] = res_w + MS;   L.w[13] = res_w + 2 * MS;
    L.w[14] = de1_w;
    L.bre_mask = 0x1F;

    // merged precompute: weights + knn + factors (+ transposed factors)
    k_pre<<<2000, 256>>>(L, bwh, bwl, kidx, kcnt, down_r, up_r,
                         wdn, wdnT, wup, wupT);

#define BW(i) (bwh + (size_t)(i) * MS), (bwl + (size_t)(i) * MS)
#define NUL4 nullptr, nullptr, nullptr, nullptr

    // ---- down: fused encoder + value GEMM (512 thr), then separable attn ----
    k_gemm<1,0,0,0,0><<<M_IN / 128, 512, GEMM_SMEM>>>(
        nullptr, nullptr, BW(0), NUL4,
        nullptr, nullptr, x, en_w, en_b, nullptr, nullptr,
        val, nullptr, nullptr);
    {
        dim3 g1(RIN / 8, BATCH, NH);
        k_sepY<RLAT, RIN><<<g1, 256>>>(val, wdn, T);
        dim3 g2(RLAT / 8, BATCH, NH);      // QYT=8 for RQ=32
        k_sepX<RLAT, RIN><<<g2, 256>>>(T, wdnT, hAh, hAl);
    }

    // ---- processor blocks ----
    bf16 *hinh = hAh, *hinl = hAl, *houth = hBh, *houtl = hBl;
    for (int i = 0; i < 3; i++) {
        k_gemm<0,0,0,0,0><<<M_LAT / 128, 512, GEMM_SMEM>>>(
            hinh, hinl, BW(1 + i), NUL4,
            nullptr, nullptr, nullptr, nullptr, nullptr, nullptr, nullptr,
            val, nullptr, nullptr);
        {
            dim3 g(16, BATCH);
            k_procatt<<<g, 256, PROC_SMEM>>>(val, pa_r + i * NH, kidx, kcnt, pah, pal);
        }
        // fused: t1 = gelu(pa@W1+b1) in smem; hout = gelu(t1@W2 + hin@Wres + b)
        k_mlp<<<M_LAT / 128, 512, GEMM_SMEM>>>(
            pah, pal, BW(5 + i), BW(8 + i),
            hinh, hinl, BW(11 + i),
            mlp1_b + i * HID, mlp2_b + i * HID, res_b + i * HID,
            houth, houtl);
        bf16* t;
        t = hinh; hinh = houth; houth = t;
        t = hinl; hinl = houtl; houtl = t;
    }

    // ---- up: value GEMM + separable attention ----
    k_gemm<0,0,0,0,0><<<M_LAT / 128, 512, GEMM_SMEM>>>(
        hinh, hinl, BW(4), NUL4,
        nullptr, nullptr, nullptr, nullptr, nullptr, nullptr, nullptr,
        val, nullptr, nullptr);
    {
        dim3 g1(RLAT / 8, BATCH, NH);
        k_sepY<RIN, RLAT><<<g1, 256>>>(val, wup, T);
        dim3 g2(RIN / 4, BATCH, NH);       // QYT=4 for RQ=64
        k_sepX<RIN, RLAT><<<g2, 256>>>(T, wupT, huph, hupl);
    }

    // ---- fused decoder (512 thr, smem-reduced DEC epilogue) ----
    k_gemm<0,0,1,1,0><<<M_IN / 128, 512, GEMM_SMEM>>>(
        huph, hupl, BW(14), NUL4,
        de1_b, nullptr, nullptr, nullptr, nullptr, de2_w, de2_b,
        out, nullptr, nullptr);
#undef BW
#undef NUL4
}